// round 3
// baseline (speedup 1.0000x reference)
#include <cuda_runtime.h>
#include <cuda_fp16.h>
#include <math.h>

#define BB 4
#define CC 64
#define MH 18
#define HH 128
#define WW 128
#define NN 9

typedef unsigned long long ull;

// ---------------- scratch (static __device__, no allocations) ----------------
__device__ float  g_update[BB*MH*HH*WW];          // sigmoid(upd conv)
__device__ float  g_rgoff [BB*MH*HH*WW];          // pre_offset * sigmoid(rst conv)
__device__ float  g_m     [BB*NN*HH*WW];          // sigmoid(wg conv)
__device__ __half g_xTh   [BB*130*130*CC];        // padded NHWC x_t (fp16)

__device__ __forceinline__ float sigf(float x) { return 1.f/(1.f + __expf(-x)); }

// ---- f32x2 helpers (Blackwell packed fp32) ----
__device__ __forceinline__ ull ffma2(ull a, ull b, ull c) {
    ull d; asm("fma.rn.f32x2 %0,%1,%2,%3;" : "=l"(d) : "l"(a), "l"(b), "l"(c)); return d;
}
__device__ __forceinline__ ull fmul2(ull a, ull b) {
    ull d; asm("mul.rn.f32x2 %0,%1,%2;" : "=l"(d) : "l"(a), "l"(b)); return d;
}
__device__ __forceinline__ ull dup2(float v) {
    ull d; asm("mov.b64 %0,{%1,%1};" : "=l"(d) : "f"(v)); return d;
}
__device__ __forceinline__ ull pack2(float lo, float hi) {
    ull d; asm("mov.b64 %0,{%1,%2};" : "=l"(d) : "f"(lo), "f"(hi)); return d;
}
__device__ __forceinline__ void unpack2(ull p, float& lo, float& hi) {
    asm("mov.b64 {%0,%1},%2;" : "=f"(lo), "=f"(hi) : "l"(p));
}

// ---------------- kernel: zero padded NHWC fp16 buffer ----------------
__global__ void k_zero() {
    int i = blockIdx.x * blockDim.x + threadIdx.x;
    const int n = (int)(BB*130*130*CC*sizeof(__half)/16);
    if (i < n) reinterpret_cast<uint4*>(g_xTh)[i] = make_uint4(0,0,0,0);
}

// ---------------- kernel: NCHW fp32 -> padded NHWC fp16 ----------------
__global__ void k_pad(const float* __restrict__ x) {
    __shared__ float sm[64][33];
    int jb = blockIdx.x, i0 = blockIdx.y, b = blockIdx.z;
    int tx = threadIdx.x, ty = threadIdx.y;
    int jcol = jb*32 + tx;
    for (int c = ty; c < 64; c += 8)
        sm[c][tx] = x[((b*CC + c)*HH + i0)*WW + jcol];
    __syncthreads();
    for (int jj = ty; jj < 32; jj += 8) {
        int base = ((b*130 + (i0+1))*130 + (jb*32 + jj + 1))*64;
        g_xTh[base + tx]      = __float2half_rn(sm[tx][jj]);
        g_xTh[base + 32 + tx] = __float2half_rn(sm[32 + tx][jj]);
    }
}

// ================= K1: upd + rst convs (36 oc) — f32x2, 2 blocks/SM =================
// tile 8h x 32w, 256 threads, 1 px/thread. weights [738][36], input dbl-buf [2][2*10*34]
#define K1OC 36
#define K1_WF (738*K1OC)              /* 26568 */
#define IN2   (2*10*34)               /* 680   */
#define K1_SMEMF (K1_WF + 2*IN2)

__global__ void __launch_bounds__(256, 2) k_gates(
    const float* __restrict__ x, const float* __restrict__ pre,
    const float* __restrict__ uw, const float* __restrict__ ub,
    const float* __restrict__ rw, const float* __restrict__ rb)
{
    extern __shared__ float sh[];
    float* s_w  = sh;                 // [738][36]
    float* s_in = sh + K1_WF;
    int t  = threadIdx.x;
    int b  = blockIdx.z;
    int h0 = blockIdx.y * 8, w0 = blockIdx.x * 32;

    for (int i = t; i < 18*738; i += 256) {
        int oc = i / 738, k = i % 738;
        s_w[k*K1OC + oc]      = uw[i];
        s_w[k*K1OC + 18 + oc] = rw[i];
    }

    ull acc[18];
    #pragma unroll
    for (int q = 0; q < 18; ++q) acc[q] = 0ULL;

    int ty = t >> 5, tx = t & 31;

    for (int e = t; e < IN2; e += 256) {
        int ch = e / 340; int rr = (e % 340) / 34; int cc2 = e % 34;
        int gh = h0 - 1 + rr, gw = w0 - 1 + cc2;
        float v = 0.f;
        if (gh >= 0 && gh < HH && gw >= 0 && gw < WW)
            v = x[((b*CC + ch)*HH + gh)*WW + gw];
        s_in[e] = v;
    }
    __syncthreads();

    #pragma unroll 1
    for (int it = 0; it < 41; ++it) {
        int c0 = it*2;
        const float* buf = s_in + (it & 1) * IN2;

        float pf[3];
        if (it < 40) {
            int nc0 = c0 + 2;
            #pragma unroll
            for (int s = 0; s < 3; ++s) {
                int e = t + s*256;
                float v = 0.f;
                if (e < IN2) {
                    int ch = e / 340; int rr = (e % 340) / 34; int cc2 = e % 34;
                    int gh = h0 - 1 + rr, gw = w0 - 1 + cc2;
                    if (gh >= 0 && gh < HH && gw >= 0 && gw < WW) {
                        int ic = nc0 + ch;
                        v = (ic < 64) ? x[((b*CC + ic)*HH + gh)*WW + gw]
                                      : pre[((b*MH + (ic - 64))*HH + gh)*WW + gw];
                    }
                }
                pf[s] = v;
            }
        }

        #pragma unroll
        for (int ch = 0; ch < 2; ++ch) {
            #pragma unroll
            for (int ki = 0; ki < 3; ++ki) {
                int ib = ch*340 + (ty + ki)*34 + tx;
                ull d0 = dup2(buf[ib]), d1 = dup2(buf[ib+1]), d2 = dup2(buf[ib+2]);
                #pragma unroll
                for (int kj = 0; kj < 3; ++kj) {
                    ull dv = (kj == 0) ? d0 : (kj == 1) ? d1 : d2;
                    const float* wrow = s_w + ((c0 + ch)*9 + ki*3 + kj)*K1OC;
                    #pragma unroll
                    for (int q = 0; q < 9; ++q) {
                        ulonglong2 wv = *reinterpret_cast<const ulonglong2*>(wrow + q*4);
                        acc[2*q]   = ffma2(wv.x, dv, acc[2*q]);
                        acc[2*q+1] = ffma2(wv.y, dv, acc[2*q+1]);
                    }
                }
            }
        }

        if (it < 40) {
            float* nbuf = s_in + ((it + 1) & 1) * IN2;
            #pragma unroll
            for (int s = 0; s < 3; ++s) {
                int e = t + s*256;
                if (e < IN2) nbuf[e] = pf[s];
            }
        }
        __syncthreads();
    }

    int h = h0 + ty;
    int w1 = w0 + tx;
    #pragma unroll
    for (int j = 0; j < 9; ++j) {
        float a0, a1;
        unpack2(acc[j], a0, a1);
        int oc0 = 2*j, oc1 = 2*j + 1;
        g_update[((b*MH + oc0)*HH + h)*WW + w1] = sigf(a0 + ub[oc0]);
        g_update[((b*MH + oc1)*HH + h)*WW + w1] = sigf(a1 + ub[oc1]);
    }
    #pragma unroll
    for (int j = 9; j < 18; ++j) {
        float a0, a1;
        unpack2(acc[j], a0, a1);
        int oc0 = 2*j - 18, oc1 = oc0 + 1;
        int i0 = ((b*MH + oc0)*HH + h)*WW + w1;
        int i1 = ((b*MH + oc1)*HH + h)*WW + w1;
        g_rgoff[i0] = pre[i0] * sigf(a0 + rb[oc0]);
        g_rgoff[i1] = pre[i1] * sigf(a1 + rb[oc1]);
    }
}

// ================= K2: cand conv + wg conv + GRU combine =================
#define K2OC 28
#define K2_WF (738*K2OC)              /* 20664 */
#define K2_SMEMF (K2_WF + 2*IN2)

__global__ void __launch_bounds__(256, 2) k_cand(
    const float* __restrict__ x, const float* __restrict__ pre,
    const float* __restrict__ mean,
    const float* __restrict__ ow, const float* __restrict__ ob,
    const float* __restrict__ ww, const float* __restrict__ wb,
    float* __restrict__ out_off, float* __restrict__ out_mean)
{
    extern __shared__ float sh[];
    float* s_w  = sh;                 // [738][28] : 0..17 cand, 18..26 wg, 27 pad
    float* s_in = sh + K2_WF;
    int t  = threadIdx.x;
    int b  = blockIdx.z;
    int h0 = blockIdx.y * 8, w0 = blockIdx.x * 32;

    for (int i = t; i < K2_WF/4; i += 256)
        reinterpret_cast<float4*>(s_w)[i] = make_float4(0.f,0.f,0.f,0.f);
    __syncthreads();
    for (int i = t; i < 18*738; i += 256) {
        int oc = i / 738, k = i % 738;
        s_w[k*K2OC + oc] = ow[i];
    }
    for (int i = t; i < 9*576; i += 256) {
        int oc = i / 576, k = i % 576;
        s_w[k*K2OC + 18 + oc] = ww[i];
    }

    ull acc[14];
    #pragma unroll
    for (int q = 0; q < 14; ++q) acc[q] = 0ULL;

    int ty = t >> 5, tx = t & 31;

    for (int e = t; e < IN2; e += 256) {
        int ch = e / 340; int rr = (e % 340) / 34; int cc2 = e % 34;
        int gh = h0 - 1 + rr, gw = w0 - 1 + cc2;
        float v = 0.f;
        if (gh >= 0 && gh < HH && gw >= 0 && gw < WW)
            v = x[((b*CC + ch)*HH + gh)*WW + gw];
        s_in[e] = v;
    }
    __syncthreads();

    #pragma unroll 1
    for (int it = 0; it < 41; ++it) {
        int c0 = it*2;
        const float* buf = s_in + (it & 1) * IN2;

        float pf[3];
        if (it < 40) {
            int nc0 = c0 + 2;
            #pragma unroll
            for (int s = 0; s < 3; ++s) {
                int e = t + s*256;
                float v = 0.f;
                if (e < IN2) {
                    int ch = e / 340; int rr = (e % 340) / 34; int cc2 = e % 34;
                    int gh = h0 - 1 + rr, gw = w0 - 1 + cc2;
                    if (gh >= 0 && gh < HH && gw >= 0 && gw < WW) {
                        int ic = nc0 + ch;
                        v = (ic < 64) ? x[((b*CC + ic)*HH + gh)*WW + gw]
                                      : g_rgoff[((b*MH + (ic - 64))*HH + gh)*WW + gw];
                    }
                }
                pf[s] = v;
            }
        }

        #pragma unroll
        for (int ch = 0; ch < 2; ++ch) {
            #pragma unroll
            for (int ki = 0; ki < 3; ++ki) {
                int ib = ch*340 + (ty + ki)*34 + tx;
                ull d0 = dup2(buf[ib]), d1 = dup2(buf[ib+1]), d2 = dup2(buf[ib+2]);
                #pragma unroll
                for (int kj = 0; kj < 3; ++kj) {
                    ull dv = (kj == 0) ? d0 : (kj == 1) ? d1 : d2;
                    const float* wrow = s_w + ((c0 + ch)*9 + ki*3 + kj)*K2OC;
                    #pragma unroll
                    for (int q = 0; q < 7; ++q) {
                        ulonglong2 wv = *reinterpret_cast<const ulonglong2*>(wrow + q*4);
                        acc[2*q]   = ffma2(wv.x, dv, acc[2*q]);
                        acc[2*q+1] = ffma2(wv.y, dv, acc[2*q+1]);
                    }
                }
            }
        }

        if (it < 40) {
            float* nbuf = s_in + ((it + 1) & 1) * IN2;
            #pragma unroll
            for (int s = 0; s < 3; ++s) {
                int e = t + s*256;
                if (e < IN2) nbuf[e] = pf[s];
            }
        }
        __syncthreads();
    }

    int h = h0 + ty;
    int w1 = w0 + tx;
    #pragma unroll
    for (int j = 0; j < 9; ++j) {
        float a0, a1;
        unpack2(acc[j], a0, a1);
        int oc0 = 2*j, oc1 = 2*j + 1;
        #pragma unroll
        for (int s = 0; s < 2; ++s) {
            int oc = s ? oc1 : oc0;
            float cv = tanhf((s ? a1 : a0) + ob[oc]);
            int i1 = ((b*MH + oc)*HH + h)*WW + w1;
            float u = g_update[i1];
            float p = pre[i1];
            float mn = 0.5f*(mean[i1] + p);
            out_off[i1]  = p*(1.f - u) + cv*u + mn;
            out_mean[i1] = mn;
        }
    }
    #pragma unroll
    for (int j = 9; j < 14; ++j) {
        float a0, a1;
        unpack2(acc[j], a0, a1);
        int oc0 = 2*(j - 9), oc1 = oc0 + 1;
        g_m[((b*NN + oc0)*HH + h)*WW + w1] = sigf(a0 + wb[oc0]);
        if (oc1 < 9)
            g_m[((b*NN + oc1)*HH + h)*WW + w1] = sigf(a1 + wb[oc1]);
    }
}

// ================= deformable warp + regroup conv — fp16 gather, dbl-buf =================
#define WARP_WTF (576*64)
#define SVP 68
#define SVB (64*SVP)
#define WARP_SMEMF (WARP_WTF + 2*SVB)

__global__ void __launch_bounds__(256, 1) k_warp(
    const float* __restrict__ off, const float* __restrict__ Wc,
    float* __restrict__ out)
{
    extern __shared__ float sh[];
    float* sWT = sh;                  // [k=576][co=64]
    float* sv0 = sh + WARP_WTF;       // two [px=64][68] buffers
    int t = threadIdx.x;
    int lane = t & 31, warp = t >> 5;
    int ch4 = (lane & 15) * 4;        // 4-channel group
    int psel = lane >> 4;             // 0/1: which pixel of the pair

    for (int i = t; i < 64*576; i += 256) {
        int co = i / 576, k = i % 576;
        sWT[k*64 + co] = Wc[i];
    }
    __syncthreads();

    int cob = (t & 7) * 8;            // 8 consecutive co
    int pxb = (t >> 3) * 2;           // 2 consecutive px

    for (int g = blockIdx.x; g < BB*HH*2; g += gridDim.x) {
        int b = g >> 8;
        int rem = g & 255;
        int h  = rem >> 1;
        int w0 = (rem & 1) << 6;
        const __half* xh = g_xTh + b*130*130*64;

        ull acc[4][2];
        #pragma unroll
        for (int i = 0; i < 4; ++i) { acc[i][0] = 0ULL; acc[i][1] = 0ULL; }

        // ---- gather for one n into buffer ----
        auto gather = [&](int n, float* svb) {
            float pnx = (float)(n/3 - 1), pny = (float)(n%3 - 1);
            #pragma unroll
            for (int st = 0; st < 4; ++st) {
                int pix = warp*8 + st*2 + psel;
                int wc  = w0 + pix;
                float ox = off[((b*MH + n     )*HH + h)*WW + wc];
                float oy = off[((b*MH + 9 + n )*HH + h)*WW + wc];
                float mm = g_m[((b*NN + n)*HH + h)*WW + wc];
                float px = (float)(h + 1) + pnx + ox;
                float py = (float)(wc + 1) + pny + oy;
                float fx = floorf(px), fy = floorf(py);
                float qxl = fminf(fmaxf(fx,       0.f), 129.f);
                float qxr = fminf(fmaxf(fx + 1.f, 0.f), 129.f);
                float qyl = fminf(fmaxf(fy,       0.f), 129.f);
                float qyr = fminf(fmaxf(fy + 1.f, 0.f), 129.f);
                float pxc = fminf(fmaxf(px, 0.f), 129.f);
                float pyc = fminf(fmaxf(py, 0.f), 129.f);
                float gx_l = 1.f + (qxl - pxc);
                float gx_r = 1.f - (qxr - pxc);
                float gy_l = 1.f + (qyl - pyc);
                float gy_r = 1.f - (qyr - pyc);
                ull glt = dup2(gx_l*gy_l*mm), grb = dup2(gx_r*gy_r*mm);
                ull glb = dup2(gx_l*gy_r*mm), grt = dup2(gx_r*gy_l*mm);
                int ixl = (int)qxl, ixr = (int)qxr, iyl = (int)qyl, iyr = (int)qyr;
                ull rlt = *reinterpret_cast<const ull*>(xh + (ixl*130 + iyl)*64 + ch4);
                ull rrb = *reinterpret_cast<const ull*>(xh + (ixr*130 + iyr)*64 + ch4);
                ull rlb = *reinterpret_cast<const ull*>(xh + (ixl*130 + iyr)*64 + ch4);
                ull rrt = *reinterpret_cast<const ull*>(xh + (ixr*130 + iyl)*64 + ch4);
                const __half2* plt = reinterpret_cast<const __half2*>(&rlt);
                const __half2* prb = reinterpret_cast<const __half2*>(&rrb);
                const __half2* plb = reinterpret_cast<const __half2*>(&rlb);
                const __half2* prt = reinterpret_cast<const __half2*>(&rrt);
                float2 flt0 = __half22float2(plt[0]), flt1 = __half22float2(plt[1]);
                float2 frb0 = __half22float2(prb[0]), frb1 = __half22float2(prb[1]);
                float2 flb0 = __half22float2(plb[0]), flb1 = __half22float2(plb[1]);
                float2 frt0 = __half22float2(prt[0]), frt1 = __half22float2(prt[1]);
                ull v0 = fmul2(glt, pack2(flt0.x, flt0.y));
                ull v1 = fmul2(glt, pack2(flt1.x, flt1.y));
                v0 = ffma2(grb, pack2(frb0.x, frb0.y), v0);
                v1 = ffma2(grb, pack2(frb1.x, frb1.y), v1);
                v0 = ffma2(glb, pack2(flb0.x, flb0.y), v0);
                v1 = ffma2(glb, pack2(flb1.x, flb1.y), v1);
                v0 = ffma2(grt, pack2(frt0.x, frt0.y), v0);
                v1 = ffma2(grt, pack2(frt1.x, frt1.y), v1);
                *reinterpret_cast<ull*>(svb + pix*SVP + ch4)     = v0;
                *reinterpret_cast<ull*>(svb + pix*SVP + ch4 + 2) = v1;
            }
        };

        gather(0, sv0);
        __syncthreads();

        #pragma unroll 1
        for (int n = 0; n < 9; ++n) {
            if (n < 8) gather(n + 1, sv0 + ((n + 1) & 1) * SVB);
            const float* svb = sv0 + (n & 1) * SVB;
            #pragma unroll 2
            for (int ci = 0; ci < 64; ++ci) {
                int k = ci*9 + n;
                ulonglong2 wA = *reinterpret_cast<const ulonglong2*>(sWT + k*64 + cob);
                ulonglong2 wB = *reinterpret_cast<const ulonglong2*>(sWT + k*64 + cob + 4);
                ull dv0 = dup2(svb[pxb*SVP + ci]);
                ull dv1 = dup2(svb[(pxb+1)*SVP + ci]);
                acc[0][0] = ffma2(wA.x, dv0, acc[0][0]);
                acc[0][1] = ffma2(wA.x, dv1, acc[0][1]);
                acc[1][0] = ffma2(wA.y, dv0, acc[1][0]);
                acc[1][1] = ffma2(wA.y, dv1, acc[1][1]);
                acc[2][0] = ffma2(wB.x, dv0, acc[2][0]);
                acc[2][1] = ffma2(wB.x, dv1, acc[2][1]);
                acc[3][0] = ffma2(wB.y, dv0, acc[3][0]);
                acc[3][1] = ffma2(wB.y, dv1, acc[3][1]);
            }
            __syncthreads();
        }

        // stage outputs to smem (reuse buffer 0) then coalesced global write
        #pragma unroll
        for (int i = 0; i < 4; ++i) {
            #pragma unroll
            for (int j = 0; j < 2; ++j) {
                float lo, hi;
                unpack2(acc[i][j], lo, hi);
                sv0[(pxb + j)*SVP + cob + 2*i]     = lo;
                sv0[(pxb + j)*SVP + cob + 2*i + 1] = hi;
            }
        }
        __syncthreads();
        for (int i = t; i < 4096; i += 256) {
            int co = i >> 6, pix = i & 63;
            out[((b*CC + co)*HH + h)*WW + w0 + pix] = sv0[pix*SVP + co];
        }
        __syncthreads();
    }
}

// ---------------- launch ----------------
extern "C" void kernel_launch(void* const* d_in, const int* in_sizes, int n_in,
                              void* d_out, int out_size)
{
    const float* x    = (const float*)d_in[0];
    const float* pre  = (const float*)d_in[1];
    const float* mean = (const float*)d_in[2];
    const float* uw   = (const float*)d_in[3];
    const float* ub   = (const float*)d_in[4];
    const float* rw   = (const float*)d_in[5];
    const float* rb   = (const float*)d_in[6];
    const float* ow   = (const float*)d_in[7];
    const float* ob   = (const float*)d_in[8];
    const float* ww   = (const float*)d_in[9];
    const float* wb   = (const float*)d_in[10];
    const float* wc   = (const float*)d_in[11];

    float* out_x    = (float*)d_out;
    float* out_off  = out_x + BB*CC*HH*WW;
    float* out_mean = out_off + BB*MH*HH*WW;

    cudaFuncSetAttribute(k_gates, cudaFuncAttributeMaxDynamicSharedMemorySize,
                         K1_SMEMF * (int)sizeof(float));
    cudaFuncSetAttribute(k_cand, cudaFuncAttributeMaxDynamicSharedMemorySize,
                         K2_SMEMF * (int)sizeof(float));
    cudaFuncSetAttribute(k_warp, cudaFuncAttributeMaxDynamicSharedMemorySize,
                         WARP_SMEMF * (int)sizeof(float));

    k_zero<<<((int)(BB*130*130*CC*sizeof(__half)/16) + 255)/256, 256>>>();
    k_pad<<<dim3(4, 128, 4), dim3(32, 8)>>>(x);

    dim3 gg(WW/32, HH/8, BB);
    k_gates<<<gg, 256, K1_SMEMF * sizeof(float)>>>(x, pre, uw, ub, rw, rb);
    k_cand<<<gg, 256, K2_SMEMF * sizeof(float)>>>(x, pre, mean, ow, ob, ww, wb,
                                                  out_off, out_mean);
    k_warp<<<148, 256, WARP_SMEMF * sizeof(float)>>>(out_off, wc, out_x);
}

// round 4
// speedup vs baseline: 1.0464x; 1.0464x over previous
#include <cuda_runtime.h>
#include <cuda_fp16.h>
#include <math.h>

#define BB 4
#define CC 64
#define MH 18
#define HH 128
#define WW 128
#define NN 9

typedef unsigned long long ull;

// ---------------- scratch (static __device__, no allocations) ----------------
__device__ float  g_update[BB*MH*HH*WW];          // sigmoid(upd conv)
__device__ float  g_rgoff [BB*MH*HH*WW];          // pre_offset * sigmoid(rst conv)
__device__ float  g_m     [BB*NN*HH*WW];          // sigmoid(wg conv)
__device__ __half g_xTh   [BB*130*130*CC];        // padded NHWC x_t (fp16)

__device__ __forceinline__ float sigf(float x) { return 1.f/(1.f + __expf(-x)); }

// ---- f32x2 helpers (Blackwell packed fp32) ----
__device__ __forceinline__ ull ffma2(ull a, ull b, ull c) {
    ull d; asm("fma.rn.f32x2 %0,%1,%2,%3;" : "=l"(d) : "l"(a), "l"(b), "l"(c)); return d;
}
__device__ __forceinline__ ull fmul2(ull a, ull b) {
    ull d; asm("mul.rn.f32x2 %0,%1,%2;" : "=l"(d) : "l"(a), "l"(b)); return d;
}
__device__ __forceinline__ ull dup2(float v) {
    ull d; asm("mov.b64 %0,{%1,%1};" : "=l"(d) : "f"(v)); return d;
}
__device__ __forceinline__ ull pack2(float lo, float hi) {
    ull d; asm("mov.b64 %0,{%1,%2};" : "=l"(d) : "f"(lo), "f"(hi)); return d;
}
__device__ __forceinline__ void unpack2(ull p, float& lo, float& hi) {
    asm("mov.b64 {%0,%1},%2;" : "=f"(lo), "=f"(hi) : "l"(p));
}

// ---------------- kernel: zero padded NHWC fp16 buffer ----------------
__global__ void k_zero() {
    int i = blockIdx.x * blockDim.x + threadIdx.x;
    const int n = (int)(BB*130*130*CC*sizeof(__half)/16);
    if (i < n) reinterpret_cast<uint4*>(g_xTh)[i] = make_uint4(0,0,0,0);
}

// ---------------- kernel: NCHW fp32 -> padded NHWC fp16 ----------------
__global__ void k_pad(const float* __restrict__ x) {
    __shared__ float sm[64][33];
    int jb = blockIdx.x, i0 = blockIdx.y, b = blockIdx.z;
    int tx = threadIdx.x, ty = threadIdx.y;
    int jcol = jb*32 + tx;
    for (int c = ty; c < 64; c += 8)
        sm[c][tx] = x[((b*CC + c)*HH + i0)*WW + jcol];
    __syncthreads();
    for (int jj = ty; jj < 32; jj += 8) {
        int base = ((b*130 + (i0+1))*130 + (jb*32 + jj + 1))*64;
        g_xTh[base + tx]      = __float2half_rn(sm[tx][jj]);
        g_xTh[base + 32 + tx] = __float2half_rn(sm[32 + tx][jj]);
    }
}

// ====== shared conv geometry: 16x16 tile, 128 threads, 2 px/thread ======
#define INW 18
#define INS (2*INW*INW)               /* 648 */

// ================= K_updwg: upd (18 oc) + wg (9 oc) =================
#define UOC 28
#define U_WF (738*UOC)                /* 20664 */
#define U_SMEMF (U_WF + 2*INS)

__global__ void __launch_bounds__(128, 2) k_updwg(
    const float* __restrict__ x, const float* __restrict__ pre,
    const float* __restrict__ uw, const float* __restrict__ ub,
    const float* __restrict__ ww, const float* __restrict__ wb)
{
    extern __shared__ float sh[];
    float* s_w  = sh;                 // [738][28]: 0..17 upd, 18..26 wg, 27 pad
    float* s_in = sh + U_WF;
    int t  = threadIdx.x;
    int b  = blockIdx.z;
    int h0 = blockIdx.y * 16, w0 = blockIdx.x * 16;

    for (int i = t; i < U_WF/4; i += 128)
        reinterpret_cast<float4*>(s_w)[i] = make_float4(0.f,0.f,0.f,0.f);
    __syncthreads();
    for (int i = t; i < 18*738; i += 128) {
        int oc = i / 738, k = i % 738;
        s_w[k*UOC + oc] = uw[i];
    }
    for (int i = t; i < 9*576; i += 128) {
        int oc = i / 576, k = i % 576;
        s_w[k*UOC + 18 + oc] = ww[i];
    }

    ull acc[14][2];
    #pragma unroll
    for (int q = 0; q < 14; ++q) { acc[q][0] = 0ULL; acc[q][1] = 0ULL; }

    int ty  = t >> 3;
    int txp = (t & 7) * 2;

    for (int e = t; e < INS; e += 128) {
        int ch = e / 324; int rr = (e % 324) / INW; int cc2 = e % INW;
        int gh = h0 - 1 + rr, gw = w0 - 1 + cc2;
        float v = 0.f;
        if (gh >= 0 && gh < HH && gw >= 0 && gw < WW)
            v = x[((b*CC + ch)*HH + gh)*WW + gw];
        s_in[e] = v;
    }
    __syncthreads();

    #pragma unroll 1
    for (int it = 0; it < 41; ++it) {
        int c0 = it*2;
        const float* buf = s_in + (it & 1) * INS;

        float pf[6];
        if (it < 40) {
            int nc0 = c0 + 2;
            #pragma unroll
            for (int s = 0; s < 6; ++s) {
                int e = t + s*128;
                float v = 0.f;
                if (e < INS) {
                    int ch = e / 324; int rr = (e % 324) / INW; int cc2 = e % INW;
                    int gh = h0 - 1 + rr, gw = w0 - 1 + cc2;
                    if (gh >= 0 && gh < HH && gw >= 0 && gw < WW) {
                        int ic = nc0 + ch;
                        v = (ic < 64) ? x[((b*CC + ic)*HH + gh)*WW + gw]
                                      : pre[((b*MH + (ic - 64))*HH + gh)*WW + gw];
                    }
                }
                pf[s] = v;
            }
        }

        #pragma unroll
        for (int ch = 0; ch < 2; ++ch) {
            #pragma unroll
            for (int ki = 0; ki < 3; ++ki) {
                int ib = ch*324 + (ty + ki)*INW + txp;
                float2 a01 = *reinterpret_cast<const float2*>(buf + ib);
                float2 a23 = *reinterpret_cast<const float2*>(buf + ib + 2);
                ull d0 = dup2(a01.x), d1 = dup2(a01.y), d2 = dup2(a23.x), d3 = dup2(a23.y);
                #pragma unroll
                for (int kj = 0; kj < 3; ++kj) {
                    ull dA = (kj == 0) ? d0 : (kj == 1) ? d1 : d2;
                    ull dB = (kj == 0) ? d1 : (kj == 1) ? d2 : d3;
                    const float* wrow = s_w + ((c0 + ch)*9 + ki*3 + kj)*UOC;
                    #pragma unroll
                    for (int q = 0; q < 7; ++q) {
                        ulonglong2 wv = *reinterpret_cast<const ulonglong2*>(wrow + q*4);
                        acc[2*q  ][0] = ffma2(wv.x, dA, acc[2*q  ][0]);
                        acc[2*q  ][1] = ffma2(wv.x, dB, acc[2*q  ][1]);
                        acc[2*q+1][0] = ffma2(wv.y, dA, acc[2*q+1][0]);
                        acc[2*q+1][1] = ffma2(wv.y, dB, acc[2*q+1][1]);
                    }
                }
            }
        }

        if (it < 40) {
            float* nbuf = s_in + ((it + 1) & 1) * INS;
            #pragma unroll
            for (int s = 0; s < 6; ++s) {
                int e = t + s*128;
                if (e < INS) nbuf[e] = pf[s];
            }
        }
        __syncthreads();
    }

    int h = h0 + ty;
    int w1 = w0 + txp;
    #pragma unroll
    for (int j = 0; j < 9; ++j) {
        float l0, h0v, l1, h1v;
        unpack2(acc[j][0], l0, h0v);   // px0: (oc0, oc1)
        unpack2(acc[j][1], l1, h1v);   // px1
        int oc0 = 2*j, oc1 = 2*j + 1;
        int i0 = ((b*MH + oc0)*HH + h)*WW + w1;
        int i1 = ((b*MH + oc1)*HH + h)*WW + w1;
        *reinterpret_cast<float2*>(g_update + i0) =
            make_float2(sigf(l0 + ub[oc0]), sigf(l1 + ub[oc0]));
        *reinterpret_cast<float2*>(g_update + i1) =
            make_float2(sigf(h0v + ub[oc1]), sigf(h1v + ub[oc1]));
    }
    #pragma unroll
    for (int j = 9; j < 14; ++j) {
        float l0, h0v, l1, h1v;
        unpack2(acc[j][0], l0, h0v);
        unpack2(acc[j][1], l1, h1v);
        int oc0 = 2*(j - 9), oc1 = oc0 + 1;
        int i0 = ((b*NN + oc0)*HH + h)*WW + w1;
        *reinterpret_cast<float2*>(g_m + i0) =
            make_float2(sigf(l0 + wb[oc0]), sigf(l1 + wb[oc0]));
        if (oc1 < 9) {
            int i1 = ((b*NN + oc1)*HH + h)*WW + w1;
            *reinterpret_cast<float2*>(g_m + i1) =
                make_float2(sigf(h0v + wb[oc1]), sigf(h1v + wb[oc1]));
        }
    }
}

// ================= K_rst: rst conv (18 oc) -> g_rgoff =================
#define ROC 20
#define R_WF (738*ROC)                /* 14760 */
#define R_SMEMF (R_WF + 2*INS)

__global__ void __launch_bounds__(128, 2) k_rst(
    const float* __restrict__ x, const float* __restrict__ pre,
    const float* __restrict__ rw, const float* __restrict__ rb)
{
    extern __shared__ float sh[];
    float* s_w  = sh;
    float* s_in = sh + R_WF;
    int t  = threadIdx.x;
    int b  = blockIdx.z;
    int h0 = blockIdx.y * 16, w0 = blockIdx.x * 16;

    for (int i = t; i < R_WF/4; i += 128)
        reinterpret_cast<float4*>(s_w)[i] = make_float4(0.f,0.f,0.f,0.f);
    __syncthreads();
    for (int i = t; i < 18*738; i += 128) {
        int oc = i / 738, k = i % 738;
        s_w[k*ROC + oc] = rw[i];
    }

    ull acc[10][2];
    #pragma unroll
    for (int q = 0; q < 10; ++q) { acc[q][0] = 0ULL; acc[q][1] = 0ULL; }

    int ty  = t >> 3;
    int txp = (t & 7) * 2;

    for (int e = t; e < INS; e += 128) {
        int ch = e / 324; int rr = (e % 324) / INW; int cc2 = e % INW;
        int gh = h0 - 1 + rr, gw = w0 - 1 + cc2;
        float v = 0.f;
        if (gh >= 0 && gh < HH && gw >= 0 && gw < WW)
            v = x[((b*CC + ch)*HH + gh)*WW + gw];
        s_in[e] = v;
    }
    __syncthreads();

    #pragma unroll 1
    for (int it = 0; it < 41; ++it) {
        int c0 = it*2;
        const float* buf = s_in + (it & 1) * INS;

        float pf[6];
        if (it < 40) {
            int nc0 = c0 + 2;
            #pragma unroll
            for (int s = 0; s < 6; ++s) {
                int e = t + s*128;
                float v = 0.f;
                if (e < INS) {
                    int ch = e / 324; int rr = (e % 324) / INW; int cc2 = e % INW;
                    int gh = h0 - 1 + rr, gw = w0 - 1 + cc2;
                    if (gh >= 0 && gh < HH && gw >= 0 && gw < WW) {
                        int ic = nc0 + ch;
                        v = (ic < 64) ? x[((b*CC + ic)*HH + gh)*WW + gw]
                                      : pre[((b*MH + (ic - 64))*HH + gh)*WW + gw];
                    }
                }
                pf[s] = v;
            }
        }

        #pragma unroll
        for (int ch = 0; ch < 2; ++ch) {
            #pragma unroll
            for (int ki = 0; ki < 3; ++ki) {
                int ib = ch*324 + (ty + ki)*INW + txp;
                float2 a01 = *reinterpret_cast<const float2*>(buf + ib);
                float2 a23 = *reinterpret_cast<const float2*>(buf + ib + 2);
                ull d0 = dup2(a01.x), d1 = dup2(a01.y), d2 = dup2(a23.x), d3 = dup2(a23.y);
                #pragma unroll
                for (int kj = 0; kj < 3; ++kj) {
                    ull dA = (kj == 0) ? d0 : (kj == 1) ? d1 : d2;
                    ull dB = (kj == 0) ? d1 : (kj == 1) ? d2 : d3;
                    const float* wrow = s_w + ((c0 + ch)*9 + ki*3 + kj)*ROC;
                    #pragma unroll
                    for (int q = 0; q < 5; ++q) {
                        ulonglong2 wv = *reinterpret_cast<const ulonglong2*>(wrow + q*4);
                        acc[2*q  ][0] = ffma2(wv.x, dA, acc[2*q  ][0]);
                        acc[2*q  ][1] = ffma2(wv.x, dB, acc[2*q  ][1]);
                        acc[2*q+1][0] = ffma2(wv.y, dA, acc[2*q+1][0]);
                        acc[2*q+1][1] = ffma2(wv.y, dB, acc[2*q+1][1]);
                    }
                }
            }
        }

        if (it < 40) {
            float* nbuf = s_in + ((it + 1) & 1) * INS;
            #pragma unroll
            for (int s = 0; s < 6; ++s) {
                int e = t + s*128;
                if (e < INS) nbuf[e] = pf[s];
            }
        }
        __syncthreads();
    }

    int h = h0 + ty;
    int w1 = w0 + txp;
    #pragma unroll
    for (int j = 0; j < 9; ++j) {
        float l0, h0v, l1, h1v;
        unpack2(acc[j][0], l0, h0v);
        unpack2(acc[j][1], l1, h1v);
        int oc0 = 2*j, oc1 = 2*j + 1;
        int i0 = ((b*MH + oc0)*HH + h)*WW + w1;
        int i1 = ((b*MH + oc1)*HH + h)*WW + w1;
        float2 p0 = *reinterpret_cast<const float2*>(pre + i0);
        float2 p1 = *reinterpret_cast<const float2*>(pre + i1);
        *reinterpret_cast<float2*>(g_rgoff + i0) =
            make_float2(p0.x * sigf(l0 + rb[oc0]), p0.y * sigf(l1 + rb[oc0]));
        *reinterpret_cast<float2*>(g_rgoff + i1) =
            make_float2(p1.x * sigf(h0v + rb[oc1]), p1.y * sigf(h1v + rb[oc1]));
    }
}

// ================= K_cand: cand conv (18 oc) + GRU combine =================
__global__ void __launch_bounds__(128, 2) k_cand(
    const float* __restrict__ x, const float* __restrict__ pre,
    const float* __restrict__ mean,
    const float* __restrict__ ow, const float* __restrict__ ob,
    float* __restrict__ out_off, float* __restrict__ out_mean)
{
    extern __shared__ float sh[];
    float* s_w  = sh;
    float* s_in = sh + R_WF;
    int t  = threadIdx.x;
    int b  = blockIdx.z;
    int h0 = blockIdx.y * 16, w0 = blockIdx.x * 16;

    for (int i = t; i < R_WF/4; i += 128)
        reinterpret_cast<float4*>(s_w)[i] = make_float4(0.f,0.f,0.f,0.f);
    __syncthreads();
    for (int i = t; i < 18*738; i += 128) {
        int oc = i / 738, k = i % 738;
        s_w[k*ROC + oc] = ow[i];
    }

    ull acc[10][2];
    #pragma unroll
    for (int q = 0; q < 10; ++q) { acc[q][0] = 0ULL; acc[q][1] = 0ULL; }

    int ty  = t >> 3;
    int txp = (t & 7) * 2;

    for (int e = t; e < INS; e += 128) {
        int ch = e / 324; int rr = (e % 324) / INW; int cc2 = e % INW;
        int gh = h0 - 1 + rr, gw = w0 - 1 + cc2;
        float v = 0.f;
        if (gh >= 0 && gh < HH && gw >= 0 && gw < WW)
            v = x[((b*CC + ch)*HH + gh)*WW + gw];
        s_in[e] = v;
    }
    __syncthreads();

    #pragma unroll 1
    for (int it = 0; it < 41; ++it) {
        int c0 = it*2;
        const float* buf = s_in + (it & 1) * INS;

        float pf[6];
        if (it < 40) {
            int nc0 = c0 + 2;
            #pragma unroll
            for (int s = 0; s < 6; ++s) {
                int e = t + s*128;
                float v = 0.f;
                if (e < INS) {
                    int ch = e / 324; int rr = (e % 324) / INW; int cc2 = e % INW;
                    int gh = h0 - 1 + rr, gw = w0 - 1 + cc2;
                    if (gh >= 0 && gh < HH && gw >= 0 && gw < WW) {
                        int ic = nc0 + ch;
                        v = (ic < 64) ? x[((b*CC + ic)*HH + gh)*WW + gw]
                                      : g_rgoff[((b*MH + (ic - 64))*HH + gh)*WW + gw];
                    }
                }
                pf[s] = v;
            }
        }

        #pragma unroll
        for (int ch = 0; ch < 2; ++ch) {
            #pragma unroll
            for (int ki = 0; ki < 3; ++ki) {
                int ib = ch*324 + (ty + ki)*INW + txp;
                float2 a01 = *reinterpret_cast<const float2*>(buf + ib);
                float2 a23 = *reinterpret_cast<const float2*>(buf + ib + 2);
                ull d0 = dup2(a01.x), d1 = dup2(a01.y), d2 = dup2(a23.x), d3 = dup2(a23.y);
                #pragma unroll
                for (int kj = 0; kj < 3; ++kj) {
                    ull dA = (kj == 0) ? d0 : (kj == 1) ? d1 : d2;
                    ull dB = (kj == 0) ? d1 : (kj == 1) ? d2 : d3;
                    const float* wrow = s_w + ((c0 + ch)*9 + ki*3 + kj)*ROC;
                    #pragma unroll
                    for (int q = 0; q < 5; ++q) {
                        ulonglong2 wv = *reinterpret_cast<const ulonglong2*>(wrow + q*4);
                        acc[2*q  ][0] = ffma2(wv.x, dA, acc[2*q  ][0]);
                        acc[2*q  ][1] = ffma2(wv.x, dB, acc[2*q  ][1]);
                        acc[2*q+1][0] = ffma2(wv.y, dA, acc[2*q+1][0]);
                        acc[2*q+1][1] = ffma2(wv.y, dB, acc[2*q+1][1]);
                    }
                }
            }
        }

        if (it < 40) {
            float* nbuf = s_in + ((it + 1) & 1) * INS;
            #pragma unroll
            for (int s = 0; s < 6; ++s) {
                int e = t + s*128;
                if (e < INS) nbuf[e] = pf[s];
            }
        }
        __syncthreads();
    }

    int h = h0 + ty;
    int w1 = w0 + txp;
    #pragma unroll
    for (int j = 0; j < 9; ++j) {
        float l0, h0v, l1, h1v;
        unpack2(acc[j][0], l0, h0v);
        unpack2(acc[j][1], l1, h1v);
        int oc0 = 2*j, oc1 = 2*j + 1;
        #pragma unroll
        for (int s = 0; s < 2; ++s) {
            int oc = s ? oc1 : oc0;
            float cv0 = tanhf((s ? h0v : l0) + ob[oc]);
            float cv1 = tanhf((s ? h1v : l1) + ob[oc]);
            int i1 = ((b*MH + oc)*HH + h)*WW + w1;
            float2 u = *reinterpret_cast<const float2*>(g_update + i1);
            float2 p = *reinterpret_cast<const float2*>(pre + i1);
            float2 mn = *reinterpret_cast<const float2*>(mean + i1);
            float mn0 = 0.5f*(mn.x + p.x);
            float mn1 = 0.5f*(mn.y + p.y);
            *reinterpret_cast<float2*>(out_off + i1) =
                make_float2(p.x*(1.f - u.x) + cv0*u.x + mn0,
                            p.y*(1.f - u.y) + cv1*u.y + mn1);
            *reinterpret_cast<float2*>(out_mean + i1) = make_float2(mn0, mn1);
        }
    }
}

// ================= deformable warp + regroup conv — pipelined =================
#define WARP_WTF (576*64)
#define SVP 68
#define SVB (64*SVP)
#define WARP_SMEMF (WARP_WTF + 2*SVB)

__global__ void __launch_bounds__(256, 1) k_warp(
    const float* __restrict__ off, const float* __restrict__ Wc,
    float* __restrict__ out)
{
    extern __shared__ float sh[];
    float* sWT = sh;                  // [k=576][co=64]
    float* sv0 = sh + WARP_WTF;       // two [px=64][68] buffers
    int t = threadIdx.x;
    int lane = t & 31, warp = t >> 5;
    int ch4 = (lane & 15) * 4;        // 4-channel group
    int psel = lane >> 4;             // 0/1: pixel select within step

    for (int i = t; i < 64*576; i += 256) {
        int co = i / 576, k = i % 576;
        sWT[k*64 + co] = Wc[i];
    }
    __syncthreads();

    int cob = (t & 7) * 8;            // 8 consecutive co
    int pxb = (t >> 3) * 2;           // 2 consecutive px

    for (int g = blockIdx.x; g < BB*HH*2; g += gridDim.x) {
        int b = g >> 8;
        int rem = g & 255;
        int h  = rem >> 1;
        int w0 = (rem & 1) << 6;
        const __half* xh = g_xTh + b*130*130*64;

        ull acc[4][2];
        #pragma unroll
        for (int i = 0; i < 4; ++i) { acc[i][0] = 0ULL; acc[i][1] = 0ULL; }

        // pipeline registers: corners + dup-packed gate weights, 4 steps
        ull cLT[4], cRB[4], cLB[4], cRT[4];
        ull wLT[4], wRB[4], wLB[4], wRT[4];

        // ---- phase A: issue all LDGs for neighbour n ----
        auto loadph = [&](int n) {
            float pnx = (float)(n/3 - 1), pny = (float)(n%3 - 1);
            #pragma unroll
            for (int st = 0; st < 4; ++st) {
                int pix = warp*8 + st*2 + psel;
                int wc  = w0 + pix;
                float ox = off[((b*MH + n     )*HH + h)*WW + wc];
                float oy = off[((b*MH + 9 + n )*HH + h)*WW + wc];
                float mm = g_m[((b*NN + n)*HH + h)*WW + wc];
                float px = (float)(h + 1) + pnx + ox;
                float py = (float)(wc + 1) + pny + oy;
                float fx = floorf(px), fy = floorf(py);
                float qxl = fminf(fmaxf(fx,       0.f), 129.f);
                float qxr = fminf(fmaxf(fx + 1.f, 0.f), 129.f);
                float qyl = fminf(fmaxf(fy,       0.f), 129.f);
                float qyr = fminf(fmaxf(fy + 1.f, 0.f), 129.f);
                float pxc = fminf(fmaxf(px, 0.f), 129.f);
                float pyc = fminf(fmaxf(py, 0.f), 129.f);
                float gx_l = 1.f + (qxl - pxc);
                float gx_r = 1.f - (qxr - pxc);
                float gy_l = 1.f + (qyl - pyc);
                float gy_r = 1.f - (qyr - pyc);
                wLT[st] = dup2(gx_l*gy_l*mm);
                wRB[st] = dup2(gx_r*gy_r*mm);
                wLB[st] = dup2(gx_l*gy_r*mm);
                wRT[st] = dup2(gx_r*gy_l*mm);
                int ixl = (int)qxl, ixr = (int)qxr, iyl = (int)qyl, iyr = (int)qyr;
                cLT[st] = *reinterpret_cast<const ull*>(xh + (ixl*130 + iyl)*64 + ch4);
                cRB[st] = *reinterpret_cast<const ull*>(xh + (ixr*130 + iyr)*64 + ch4);
                cLB[st] = *reinterpret_cast<const ull*>(xh + (ixl*130 + iyr)*64 + ch4);
                cRT[st] = *reinterpret_cast<const ull*>(xh + (ixr*130 + iyl)*64 + ch4);
            }
        };

        // ---- phase B: blend corners, store to sv buffer ----
        auto blendst = [&](float* svb) {
            #pragma unroll
            for (int st = 0; st < 4; ++st) {
                int pix = warp*8 + st*2 + psel;
                const __half2* plt = reinterpret_cast<const __half2*>(&cLT[st]);
                const __half2* prb = reinterpret_cast<const __half2*>(&cRB[st]);
                const __half2* plb = reinterpret_cast<const __half2*>(&cLB[st]);
                const __half2* prt = reinterpret_cast<const __half2*>(&cRT[st]);
                float2 flt0 = __half22float2(plt[0]), flt1 = __half22float2(plt[1]);
                float2 frb0 = __half22float2(prb[0]), frb1 = __half22float2(prb[1]);
                float2 flb0 = __half22float2(plb[0]), flb1 = __half22float2(plb[1]);
                float2 frt0 = __half22float2(prt[0]), frt1 = __half22float2(prt[1]);
                ull v0 = fmul2(wLT[st], pack2(flt0.x, flt0.y));
                ull v1 = fmul2(wLT[st], pack2(flt1.x, flt1.y));
                v0 = ffma2(wRB[st], pack2(frb0.x, frb0.y), v0);
                v1 = ffma2(wRB[st], pack2(frb1.x, frb1.y), v1);
                v0 = ffma2(wLB[st], pack2(flb0.x, flb0.y), v0);
                v1 = ffma2(wLB[st], pack2(flb1.x, flb1.y), v1);
                v0 = ffma2(wRT[st], pack2(frt0.x, frt0.y), v0);
                v1 = ffma2(wRT[st], pack2(frt1.x, frt1.y), v1);
                *reinterpret_cast<ull*>(svb + pix*SVP + ch4)     = v0;
                *reinterpret_cast<ull*>(svb + pix*SVP + ch4 + 2) = v1;
            }
        };

        loadph(0);
        blendst(sv0);
        __syncthreads();

        #pragma unroll 1
        for (int n = 0; n < 9; ++n) {
            if (n < 8) loadph(n + 1);        // LDGs in flight during matmul
            const float* svb = sv0 + (n & 1) * SVB;
            #pragma unroll 2
            for (int ci = 0; ci < 64; ++ci) {
                int k = ci*9 + n;
                ulonglong2 wA = *reinterpret_cast<const ulonglong2*>(sWT + k*64 + cob);
                ulonglong2 wB = *reinterpret_cast<const ulonglong2*>(sWT + k*64 + cob + 4);
                ull dv0 = dup2(svb[pxb*SVP + ci]);
                ull dv1 = dup2(svb[(pxb+1)*SVP + ci]);
                acc[0][0] = ffma2(wA.x, dv0, acc[0][0]);
                acc[0][1] = ffma2(wA.x, dv1, acc[0][1]);
                acc[1][0] = ffma2(wA.y, dv0, acc[1][0]);
                acc[1][1] = ffma2(wA.y, dv1, acc[1][1]);
                acc[2][0] = ffma2(wB.x, dv0, acc[2][0]);
                acc[2][1] = ffma2(wB.x, dv1, acc[2][1]);
                acc[3][0] = ffma2(wB.y, dv0, acc[3][0]);
                acc[3][1] = ffma2(wB.y, dv1, acc[3][1]);
            }
            if (n < 8) blendst(sv0 + ((n + 1) & 1) * SVB);
            __syncthreads();
        }

        // stage outputs to smem (reuse buffer 0) then coalesced global write
        #pragma unroll
        for (int i = 0; i < 4; ++i) {
            #pragma unroll
            for (int j = 0; j < 2; ++j) {
                float lo, hi;
                unpack2(acc[i][j], lo, hi);
                sv0[(pxb + j)*SVP + cob + 2*i]     = lo;
                sv0[(pxb + j)*SVP + cob + 2*i + 1] = hi;
            }
        }
        __syncthreads();
        for (int i = t; i < 4096; i += 256) {
            int co = i >> 6, pix = i & 63;
            out[((b*CC + co)*HH + h)*WW + w0 + pix] = sv0[pix*SVP + co];
        }
        __syncthreads();
    }
}

// ---------------- launch ----------------
extern "C" void kernel_launch(void* const* d_in, const int* in_sizes, int n_in,
                              void* d_out, int out_size)
{
    const float* x    = (const float*)d_in[0];
    const float* pre  = (const float*)d_in[1];
    const float* mean = (const float*)d_in[2];
    const float* uw   = (const float*)d_in[3];
    const float* ub   = (const float*)d_in[4];
    const float* rw   = (const float*)d_in[5];
    const float* rb   = (const float*)d_in[6];
    const float* ow   = (const float*)d_in[7];
    const float* ob   = (const float*)d_in[8];
    const float* ww   = (const float*)d_in[9];
    const float* wb   = (const float*)d_in[10];
    const float* wc   = (const float*)d_in[11];

    float* out_x    = (float*)d_out;
    float* out_off  = out_x + BB*CC*HH*WW;
    float* out_mean = out_off + BB*MH*HH*WW;

    cudaFuncSetAttribute(k_updwg, cudaFuncAttributeMaxDynamicSharedMemorySize,
                         U_SMEMF * (int)sizeof(float));
    cudaFuncSetAttribute(k_rst, cudaFuncAttributeMaxDynamicSharedMemorySize,
                         R_SMEMF * (int)sizeof(float));
    cudaFuncSetAttribute(k_cand, cudaFuncAttributeMaxDynamicSharedMemorySize,
                         R_SMEMF * (int)sizeof(float));
    cudaFuncSetAttribute(k_warp, cudaFuncAttributeMaxDynamicSharedMemorySize,
                         WARP_SMEMF * (int)sizeof(float));

    k_zero<<<((int)(BB*130*130*CC*sizeof(__half)/16) + 255)/256, 256>>>();
    k_pad<<<dim3(4, 128, 4), dim3(32, 8)>>>(x);

    dim3 gg(WW/16, HH/16, BB);
    k_updwg<<<gg, 128, U_SMEMF * sizeof(float)>>>(x, pre, uw, ub, ww, wb);
    k_rst  <<<gg, 128, R_SMEMF * sizeof(float)>>>(x, pre, rw, rb);
    k_cand <<<gg, 128, R_SMEMF * sizeof(float)>>>(x, pre, mean, ow, ob,
                                                  out_off, out_mean);
    k_warp<<<148, 256, WARP_SMEMF * sizeof(float)>>>(out_off, wc, out_x);
}

// round 5
// speedup vs baseline: 1.1418x; 1.0912x over previous
#include <cuda_runtime.h>
#include <cuda_fp16.h>
#include <math.h>

#define BB 4
#define CC 64
#define MH 18
#define HH 128
#define WW 128
#define NN 9
#define HWX (HH*WW)

typedef unsigned long long ull;

// ---------------- scratch (static __device__, no allocations) ----------------
__device__ float  g_update[BB*MH*HH*WW];          // sigmoid(upd conv)
__device__ float  g_rgoff [BB*MH*HH*WW];          // pre_offset * sigmoid(rst conv)
__device__ float  g_m     [BB*NN*HH*WW];          // sigmoid(wg conv)
__device__ __half g_xTh   [BB*130*130*CC];        // padded NHWC x_t (fp16)

__device__ __forceinline__ float sigf(float x) { return 1.f/(1.f + __expf(-x)); }

// ---- f32x2 helpers (Blackwell packed fp32) ----
__device__ __forceinline__ ull ffma2(ull a, ull b, ull c) {
    ull d; asm("fma.rn.f32x2 %0,%1,%2,%3;" : "=l"(d) : "l"(a), "l"(b), "l"(c)); return d;
}
__device__ __forceinline__ ull fmul2(ull a, ull b) {
    ull d; asm("mul.rn.f32x2 %0,%1,%2;" : "=l"(d) : "l"(a), "l"(b)); return d;
}
__device__ __forceinline__ ull dup2(float v) {
    ull d; asm("mov.b64 %0,{%1,%1};" : "=l"(d) : "f"(v)); return d;
}
__device__ __forceinline__ ull pack2(float lo, float hi) {
    ull d; asm("mov.b64 %0,{%1,%2};" : "=l"(d) : "f"(lo), "f"(hi)); return d;
}
__device__ __forceinline__ void unpack2(ull p, float& lo, float& hi) {
    asm("mov.b64 {%0,%1},%2;" : "=f"(lo), "=f"(hi) : "l"(p));
}

// ---------------- kernel: zero padded NHWC fp16 buffer ----------------
__global__ void k_zero() {
    int i = blockIdx.x * blockDim.x + threadIdx.x;
    const int n = (int)(BB*130*130*CC*sizeof(__half)/16);
    if (i < n) reinterpret_cast<uint4*>(g_xTh)[i] = make_uint4(0,0,0,0);
}

// ---------------- kernel: NCHW fp32 -> padded NHWC fp16 ----------------
__global__ void k_pad(const float* __restrict__ x) {
    __shared__ float sm[64][33];
    int jb = blockIdx.x, i0 = blockIdx.y, b = blockIdx.z;
    int tx = threadIdx.x, ty = threadIdx.y;
    int jcol = jb*32 + tx;
    for (int c = ty; c < 64; c += 8)
        sm[c][tx] = x[((b*CC + c)*HH + i0)*WW + jcol];
    __syncthreads();
    for (int jj = ty; jj < 32; jj += 8) {
        int base = ((b*130 + (i0+1))*130 + (jb*32 + jj + 1))*64;
        g_xTh[base + tx]      = __float2half_rn(sm[tx][jj]);
        g_xTh[base + 32 + tx] = __float2half_rn(sm[32 + tx][jj]);
    }
}

// ====== conv geometry: 16h x 32w tile, 256 threads, 2 px/thread ======
#define IN_TILE (2*18*34)             /* 1224 */
#define NSLOT 5

// precompute staging slots: ch (0/1), plane offset (or -1 if OOB/unused)
struct Slots { int plo[NSLOT]; int ch[NSLOT]; };
__device__ __forceinline__ Slots make_slots(int t, int h0, int w0) {
    Slots s;
    #pragma unroll
    for (int k = 0; k < NSLOT; ++k) {
        int e = t + k*256;
        if (e < IN_TILE) {
            int ch = e / 612; int rr = (e % 612) / 34; int cc2 = e % 34;
            int gh = h0 - 1 + rr, gw = w0 - 1 + cc2;
            s.ch[k] = ch;
            s.plo[k] = (gh >= 0 && gh < HH && gw >= 0 && gw < WW) ? gh*WW + gw : -1;
        } else { s.ch[k] = 0; s.plo[k] = -2; }  // -2: slot unused
    }
    return s;
}

// fetch value for slot k at input channel ic (x if <64 else alt plane)
__device__ __forceinline__ float slot_fetch(
    const Slots& s, int k, int ic, int b,
    const float* __restrict__ x, const float* __restrict__ alt)
{
    int plo = s.plo[k];
    if (plo < 0) return 0.f;
    const float* base = (ic < 64) ? x + (b*CC + ic)*HWX
                                  : alt + (b*MH + (ic - 64))*HWX;
    return __ldg(base + plo);
}

// ================= K1: upd + rst convs (36 oc) =================
#define GOC 36
#define G_WF (738*GOC)                /* 26568 */
#define G_SMEMF (G_WF + 2*IN_TILE)

__global__ void __launch_bounds__(256, 1) k_gatesm(
    const float* __restrict__ x, const float* __restrict__ pre,
    const float* __restrict__ uw, const float* __restrict__ ub,
    const float* __restrict__ rw, const float* __restrict__ rb)
{
    extern __shared__ float sh[];
    float* s_w  = sh;                 // [738][36]: 0..17 upd, 18..35 rst
    float* s_in = sh + G_WF;
    int t  = threadIdx.x;
    int b  = blockIdx.z;
    int h0 = blockIdx.y * 16, w0 = blockIdx.x * 32;

    for (int i = t; i < 18*738; i += 256) {
        int oc = i / 738, k = i % 738;
        s_w[k*GOC + oc]      = uw[i];
        s_w[k*GOC + 18 + oc] = rw[i];
    }

    ull acc[18][2];
    #pragma unroll
    for (int q = 0; q < 18; ++q) { acc[q][0] = 0ULL; acc[q][1] = 0ULL; }

    int ty  = t >> 4;
    int txp = (t & 15) * 2;

    Slots sl = make_slots(t, h0, w0);

    // stage chunk 0 (channels 0,1 -> x)
    #pragma unroll
    for (int k = 0; k < NSLOT; ++k) {
        if (sl.plo[k] != -2) s_in[t + k*256] = slot_fetch(sl, k, sl.ch[k], b, x, pre);
    }
    __syncthreads();

    #pragma unroll 1
    for (int it = 0; it < 41; ++it) {
        const float* buf = s_in + (it & 1) * IN_TILE;

        float pf[NSLOT];
        if (it < 40) {
            int nc0 = it*2 + 2;
            #pragma unroll
            for (int k = 0; k < NSLOT; ++k)
                pf[k] = (sl.plo[k] != -2) ? slot_fetch(sl, k, nc0 + sl.ch[k], b, x, pre) : 0.f;
        }

        int c0 = it*2;
        #pragma unroll
        for (int ch = 0; ch < 2; ++ch) {
            #pragma unroll
            for (int ki = 0; ki < 3; ++ki) {
                int ib = ch*612 + (ty + ki)*34 + txp;
                float2 a01 = *reinterpret_cast<const float2*>(buf + ib);
                float2 a23 = *reinterpret_cast<const float2*>(buf + ib + 2);
                ull d0 = dup2(a01.x), d1 = dup2(a01.y), d2 = dup2(a23.x), d3 = dup2(a23.y);
                #pragma unroll
                for (int kj = 0; kj < 3; ++kj) {
                    ull dA = (kj == 0) ? d0 : (kj == 1) ? d1 : d2;
                    ull dB = (kj == 0) ? d1 : (kj == 1) ? d2 : d3;
                    const float* wrow = s_w + ((c0 + ch)*9 + ki*3 + kj)*GOC;
                    #pragma unroll
                    for (int q = 0; q < 9; ++q) {
                        ulonglong2 wv = *reinterpret_cast<const ulonglong2*>(wrow + q*4);
                        acc[2*q  ][0] = ffma2(wv.x, dA, acc[2*q  ][0]);
                        acc[2*q  ][1] = ffma2(wv.x, dB, acc[2*q  ][1]);
                        acc[2*q+1][0] = ffma2(wv.y, dA, acc[2*q+1][0]);
                        acc[2*q+1][1] = ffma2(wv.y, dB, acc[2*q+1][1]);
                    }
                }
            }
        }

        if (it < 40) {
            float* nbuf = s_in + ((it + 1) & 1) * IN_TILE;
            #pragma unroll
            for (int k = 0; k < NSLOT; ++k)
                if (sl.plo[k] != -2) nbuf[t + k*256] = pf[k];
        }
        __syncthreads();
    }

    int h = h0 + ty;
    int w1 = w0 + txp;
    #pragma unroll
    for (int j = 0; j < 9; ++j) {
        float l0, g0, l1, g1;
        unpack2(acc[j][0], l0, g0);    // px0: (oc0, oc1)
        unpack2(acc[j][1], l1, g1);    // px1
        int oc0 = 2*j, oc1 = 2*j + 1;
        int i0 = ((b*MH + oc0)*HH + h)*WW + w1;
        int i1 = ((b*MH + oc1)*HH + h)*WW + w1;
        *reinterpret_cast<float2*>(g_update + i0) =
            make_float2(sigf(l0 + ub[oc0]), sigf(l1 + ub[oc0]));
        *reinterpret_cast<float2*>(g_update + i1) =
            make_float2(sigf(g0 + ub[oc1]), sigf(g1 + ub[oc1]));
    }
    #pragma unroll
    for (int j = 9; j < 18; ++j) {
        float l0, g0, l1, g1;
        unpack2(acc[j][0], l0, g0);
        unpack2(acc[j][1], l1, g1);
        int oc0 = 2*j - 18, oc1 = oc0 + 1;
        int i0 = ((b*MH + oc0)*HH + h)*WW + w1;
        int i1 = ((b*MH + oc1)*HH + h)*WW + w1;
        float2 p0 = *reinterpret_cast<const float2*>(pre + i0);
        float2 p1 = *reinterpret_cast<const float2*>(pre + i1);
        *reinterpret_cast<float2*>(g_rgoff + i0) =
            make_float2(p0.x * sigf(l0 + rb[oc0]), p0.y * sigf(l1 + rb[oc0]));
        *reinterpret_cast<float2*>(g_rgoff + i1) =
            make_float2(p1.x * sigf(g0 + rb[oc1]), p1.y * sigf(g1 + rb[oc1]));
    }
}

// ================= K2: cand (18) + wg (9) convs + GRU combine =================
#define COC 28
#define C_WF (738*COC)                /* 20664 */
#define C_SMEMF (C_WF + 2*IN_TILE)

__global__ void __launch_bounds__(256, 1) k_cand(
    const float* __restrict__ x, const float* __restrict__ pre,
    const float* __restrict__ mean,
    const float* __restrict__ ow, const float* __restrict__ ob,
    const float* __restrict__ ww, const float* __restrict__ wb,
    float* __restrict__ out_off, float* __restrict__ out_mean)
{
    extern __shared__ float sh[];
    float* s_w  = sh;                 // [738][28]: 0..17 cand, 18..26 wg, 27 pad
    float* s_in = sh + C_WF;
    int t  = threadIdx.x;
    int b  = blockIdx.z;
    int h0 = blockIdx.y * 16, w0 = blockIdx.x * 32;

    for (int i = t; i < C_WF/4; i += 256)
        reinterpret_cast<float4*>(s_w)[i] = make_float4(0.f,0.f,0.f,0.f);
    __syncthreads();
    for (int i = t; i < 18*738; i += 256) {
        int oc = i / 738, k = i % 738;
        s_w[k*COC + oc] = ow[i];
    }
    for (int i = t; i < 9*576; i += 256) {
        int oc = i / 576, k = i % 576;
        s_w[k*COC + 18 + oc] = ww[i];
    }

    ull acc[14][2];
    #pragma unroll
    for (int q = 0; q < 14; ++q) { acc[q][0] = 0ULL; acc[q][1] = 0ULL; }

    int ty  = t >> 4;
    int txp = (t & 15) * 2;

    Slots sl = make_slots(t, h0, w0);

    #pragma unroll
    for (int k = 0; k < NSLOT; ++k) {
        if (sl.plo[k] != -2) s_in[t + k*256] = slot_fetch(sl, k, sl.ch[k], b, x, g_rgoff);
    }
    __syncthreads();

    #pragma unroll 1
    for (int it = 0; it < 41; ++it) {
        const float* buf = s_in + (it & 1) * IN_TILE;

        float pf[NSLOT];
        if (it < 40) {
            int nc0 = it*2 + 2;
            #pragma unroll
            for (int k = 0; k < NSLOT; ++k)
                pf[k] = (sl.plo[k] != -2) ? slot_fetch(sl, k, nc0 + sl.ch[k], b, x, g_rgoff) : 0.f;
        }

        int c0 = it*2;
        #pragma unroll
        for (int ch = 0; ch < 2; ++ch) {
            #pragma unroll
            for (int ki = 0; ki < 3; ++ki) {
                int ib = ch*612 + (ty + ki)*34 + txp;
                float2 a01 = *reinterpret_cast<const float2*>(buf + ib);
                float2 a23 = *reinterpret_cast<const float2*>(buf + ib + 2);
                ull d0 = dup2(a01.x), d1 = dup2(a01.y), d2 = dup2(a23.x), d3 = dup2(a23.y);
                #pragma unroll
                for (int kj = 0; kj < 3; ++kj) {
                    ull dA = (kj == 0) ? d0 : (kj == 1) ? d1 : d2;
                    ull dB = (kj == 0) ? d1 : (kj == 1) ? d2 : d3;
                    const float* wrow = s_w + ((c0 + ch)*9 + ki*3 + kj)*COC;
                    #pragma unroll
                    for (int q = 0; q < 7; ++q) {
                        ulonglong2 wv = *reinterpret_cast<const ulonglong2*>(wrow + q*4);
                        acc[2*q  ][0] = ffma2(wv.x, dA, acc[2*q  ][0]);
                        acc[2*q  ][1] = ffma2(wv.x, dB, acc[2*q  ][1]);
                        acc[2*q+1][0] = ffma2(wv.y, dA, acc[2*q+1][0]);
                        acc[2*q+1][1] = ffma2(wv.y, dB, acc[2*q+1][1]);
                    }
                }
            }
        }

        if (it < 40) {
            float* nbuf = s_in + ((it + 1) & 1) * IN_TILE;
            #pragma unroll
            for (int k = 0; k < NSLOT; ++k)
                if (sl.plo[k] != -2) nbuf[t + k*256] = pf[k];
        }
        __syncthreads();
    }

    int h = h0 + ty;
    int w1 = w0 + txp;
    #pragma unroll
    for (int j = 0; j < 9; ++j) {
        float l0, g0, l1, g1;
        unpack2(acc[j][0], l0, g0);
        unpack2(acc[j][1], l1, g1);
        int oc0 = 2*j, oc1 = oc0 + 1;
        #pragma unroll
        for (int s = 0; s < 2; ++s) {
            int oc = s ? oc1 : oc0;
            float cv0 = tanhf((s ? g0 : l0) + ob[oc]);
            float cv1 = tanhf((s ? g1 : l1) + ob[oc]);
            int i1 = ((b*MH + oc)*HH + h)*WW + w1;
            float2 u  = *reinterpret_cast<const float2*>(g_update + i1);
            float2 p  = *reinterpret_cast<const float2*>(pre + i1);
            float2 mn = *reinterpret_cast<const float2*>(mean + i1);
            float mn0 = 0.5f*(mn.x + p.x);
            float mn1 = 0.5f*(mn.y + p.y);
            *reinterpret_cast<float2*>(out_off + i1) =
                make_float2(p.x*(1.f - u.x) + cv0*u.x + mn0,
                            p.y*(1.f - u.y) + cv1*u.y + mn1);
            *reinterpret_cast<float2*>(out_mean + i1) = make_float2(mn0, mn1);
        }
    }
    #pragma unroll
    for (int j = 9; j < 14; ++j) {
        float l0, g0, l1, g1;
        unpack2(acc[j][0], l0, g0);
        unpack2(acc[j][1], l1, g1);
        int oc0 = 2*(j - 9), oc1 = oc0 + 1;
        int i0 = ((b*NN + oc0)*HH + h)*WW + w1;
        *reinterpret_cast<float2*>(g_m + i0) =
            make_float2(sigf(l0 + wb[oc0]), sigf(l1 + wb[oc0]));
        if (oc1 < 9) {
            int i1 = ((b*NN + oc1)*HH + h)*WW + w1;
            *reinterpret_cast<float2*>(g_m + i1) =
                make_float2(sigf(g0 + wb[oc1]), sigf(g1 + wb[oc1]));
        }
    }
}

// ================= deformable warp + regroup conv =================
#define WARP_WTF (576*64)
#define SVP 68
#define SVB (64*SVP)
#define WARP_SMEMF (WARP_WTF + 2*SVB)

__global__ void __launch_bounds__(256, 1) k_warp(
    const float* __restrict__ off, const float* __restrict__ Wc,
    float* __restrict__ out)
{
    extern __shared__ float sh[];
    float* sWT = sh;                  // [k=576][co=64]
    float* sv0 = sh + WARP_WTF;       // two [px=64][68] buffers
    int t = threadIdx.x;
    int lane = t & 31, warp = t >> 5;
    int ch4 = (lane & 15) * 4;        // 4-channel group
    int psel = lane >> 4;             // 0/1: pixel select within step

    for (int i = t; i < 64*576; i += 256) {
        int co = i / 576, k = i % 576;
        sWT[k*64 + co] = Wc[i];
    }
    __syncthreads();

    int cob = (t & 7) * 8;            // 8 consecutive co
    int pxb = (t >> 3) * 2;           // 2 consecutive px

    for (int g = blockIdx.x; g < BB*HH*2; g += gridDim.x) {
        int b = g >> 8;
        int rem = g & 255;
        int h  = rem >> 1;
        int w0 = (rem & 1) << 6;
        const __half* xh = g_xTh + b*130*130*64;

        ull acc[4][2];
        #pragma unroll
        for (int i = 0; i < 4; ++i) { acc[i][0] = 0ULL; acc[i][1] = 0ULL; }

        // gather for one n: pipelined load phase then blend phase (regs local)
        auto gatherN = [&](int n, float* svb) {
            ull cLT[4], cRB[4], cLB[4], cRT[4];
            ull wLT[4], wRB[4], wLB[4], wRT[4];
            float pnx = (float)(n/3 - 1), pny = (float)(n%3 - 1);
            #pragma unroll
            for (int st = 0; st < 4; ++st) {
                int pix = warp*8 + st*2 + psel;
                int wc  = w0 + pix;
                float ox = __ldg(off + ((b*MH + n     )*HH + h)*WW + wc);
                float oy = __ldg(off + ((b*MH + 9 + n )*HH + h)*WW + wc);
                float mm = g_m[((b*NN + n)*HH + h)*WW + wc];
                float px = (float)(h + 1) + pnx + ox;
                float py = (float)(wc + 1) + pny + oy;
                float fx = floorf(px), fy = floorf(py);
                float qxl = fminf(fmaxf(fx,       0.f), 129.f);
                float qxr = fminf(fmaxf(fx + 1.f, 0.f), 129.f);
                float qyl = fminf(fmaxf(fy,       0.f), 129.f);
                float qyr = fminf(fmaxf(fy + 1.f, 0.f), 129.f);
                float pxc = fminf(fmaxf(px, 0.f), 129.f);
                float pyc = fminf(fmaxf(py, 0.f), 129.f);
                float gx_l = 1.f + (qxl - pxc);
                float gx_r = 1.f - (qxr - pxc);
                float gy_l = 1.f + (qyl - pyc);
                float gy_r = 1.f - (qyr - pyc);
                wLT[st] = dup2(gx_l*gy_l*mm);
                wRB[st] = dup2(gx_r*gy_r*mm);
                wLB[st] = dup2(gx_l*gy_r*mm);
                wRT[st] = dup2(gx_r*gy_l*mm);
                int ixl = (int)qxl, ixr = (int)qxr, iyl = (int)qyl, iyr = (int)qyr;
                cLT[st] = *reinterpret_cast<const ull*>(xh + (ixl*130 + iyl)*64 + ch4);
                cRB[st] = *reinterpret_cast<const ull*>(xh + (ixr*130 + iyr)*64 + ch4);
                cLB[st] = *reinterpret_cast<const ull*>(xh + (ixl*130 + iyr)*64 + ch4);
                cRT[st] = *reinterpret_cast<const ull*>(xh + (ixr*130 + iyl)*64 + ch4);
            }
            #pragma unroll
            for (int st = 0; st < 4; ++st) {
                int pix = warp*8 + st*2 + psel;
                const __half2* plt = reinterpret_cast<const __half2*>(&cLT[st]);
                const __half2* prb = reinterpret_cast<const __half2*>(&cRB[st]);
                const __half2* plb = reinterpret_cast<const __half2*>(&cLB[st]);
                const __half2* prt = reinterpret_cast<const __half2*>(&cRT[st]);
                float2 flt0 = __half22float2(plt[0]), flt1 = __half22float2(plt[1]);
                float2 frb0 = __half22float2(prb[0]), frb1 = __half22float2(prb[1]);
                float2 flb0 = __half22float2(plb[0]), flb1 = __half22float2(plb[1]);
                float2 frt0 = __half22float2(prt[0]), frt1 = __half22float2(prt[1]);
                ull v0 = fmul2(wLT[st], pack2(flt0.x, flt0.y));
                ull v1 = fmul2(wLT[st], pack2(flt1.x, flt1.y));
                v0 = ffma2(wRB[st], pack2(frb0.x, frb0.y), v0);
                v1 = ffma2(wRB[st], pack2(frb1.x, frb1.y), v1);
                v0 = ffma2(wLB[st], pack2(flb0.x, flb0.y), v0);
                v1 = ffma2(wLB[st], pack2(flb1.x, flb1.y), v1);
                v0 = ffma2(wRT[st], pack2(frt0.x, frt0.y), v0);
                v1 = ffma2(wRT[st], pack2(frt1.x, frt1.y), v1);
                *reinterpret_cast<ull*>(svb + pix*SVP + ch4)     = v0;
                *reinterpret_cast<ull*>(svb + pix*SVP + ch4 + 2) = v1;
            }
        };

        gatherN(0, sv0);
        __syncthreads();

        #pragma unroll 1
        for (int n = 0; n < 9; ++n) {
            if (n < 8) gatherN(n + 1, sv0 + ((n + 1) & 1) * SVB);
            const float* svb = sv0 + (n & 1) * SVB;
            const float* sv_p0 = svb + pxb*SVP;
            const float* sv_p1 = svb + (pxb + 1)*SVP;
            #pragma unroll 2
            for (int ci4 = 0; ci4 < 16; ++ci4) {
                float4 s0 = *reinterpret_cast<const float4*>(sv_p0 + ci4*4);
                float4 s1 = *reinterpret_cast<const float4*>(sv_p1 + ci4*4);
                #pragma unroll
                for (int u = 0; u < 4; ++u) {
                    int k = (ci4*4 + u)*9 + n;
                    ulonglong2 wA = *reinterpret_cast<const ulonglong2*>(sWT + k*64 + cob);
                    ulonglong2 wB = *reinterpret_cast<const ulonglong2*>(sWT + k*64 + cob + 4);
                    float e0 = (u==0)?s0.x:(u==1)?s0.y:(u==2)?s0.z:s0.w;
                    float e1 = (u==0)?s1.x:(u==1)?s1.y:(u==2)?s1.z:s1.w;
                    ull dv0 = dup2(e0), dv1 = dup2(e1);
                    acc[0][0] = ffma2(wA.x, dv0, acc[0][0]);
                    acc[0][1] = ffma2(wA.x, dv1, acc[0][1]);
                    acc[1][0] = ffma2(wA.y, dv0, acc[1][0]);
                    acc[1][1] = ffma2(wA.y, dv1, acc[1][1]);
                    acc[2][0] = ffma2(wB.x, dv0, acc[2][0]);
                    acc[2][1] = ffma2(wB.x, dv1, acc[2][1]);
                    acc[3][0] = ffma2(wB.y, dv0, acc[3][0]);
                    acc[3][1] = ffma2(wB.y, dv1, acc[3][1]);
                }
            }
            __syncthreads();
        }

        // stage outputs to smem (reuse buffer 0) then coalesced global write
        #pragma unroll
        for (int i = 0; i < 4; ++i) {
            #pragma unroll
            for (int j = 0; j < 2; ++j) {
                float lo, hi;
                unpack2(acc[i][j], lo, hi);
                sv0[(pxb + j)*SVP + cob + 2*i]     = lo;
                sv0[(pxb + j)*SVP + cob + 2*i + 1] = hi;
            }
        }
        __syncthreads();
        for (int i = t; i < 4096; i += 256) {
            int co = i >> 6, pix = i & 63;
            out[((b*CC + co)*HH + h)*WW + w0 + pix] = sv0[pix*SVP + co];
        }
        __syncthreads();
    }
}

// ---------------- launch ----------------
extern "C" void kernel_launch(void* const* d_in, const int* in_sizes, int n_in,
                              void* d_out, int out_size)
{
    const float* x    = (const float*)d_in[0];
    const float* pre  = (const float*)d_in[1];
    const float* mean = (const float*)d_in[2];
    const float* uw   = (const float*)d_in[3];
    const float* ub   = (const float*)d_in[4];
    const float* rw   = (const float*)d_in[5];
    const float* rb   = (const float*)d_in[6];
    const float* ow   = (const float*)d_in[7];
    const float* ob   = (const float*)d_in[8];
    const float* ww   = (const float*)d_in[9];
    const float* wb   = (const float*)d_in[10];
    const float* wc   = (const float*)d_in[11];

    float* out_x    = (float*)d_out;
    float* out_off  = out_x + BB*CC*HH*WW;
    float* out_mean = out_off + BB*MH*HH*WW;

    cudaFuncSetAttribute(k_gatesm, cudaFuncAttributeMaxDynamicSharedMemorySize,
                         G_SMEMF * (int)sizeof(float));
    cudaFuncSetAttribute(k_cand, cudaFuncAttributeMaxDynamicSharedMemorySize,
                         C_SMEMF * (int)sizeof(float));
    cudaFuncSetAttribute(k_warp, cudaFuncAttributeMaxDynamicSharedMemorySize,
                         WARP_SMEMF * (int)sizeof(float));

    k_zero<<<((int)(BB*130*130*CC*sizeof(__half)/16) + 255)/256, 256>>>();
    k_pad<<<dim3(4, 128, 4), dim3(32, 8)>>>(x);

    dim3 gg(WW/32, HH/16, BB);
    k_gatesm<<<gg, 256, G_SMEMF * sizeof(float)>>>(x, pre, uw, ub, rw, rb);
    k_cand<<<gg, 256, C_SMEMF * sizeof(float)>>>(x, pre, mean, ow, ob, ww, wb,
                                                 out_off, out_mean);
    k_warp<<<148, 256, WARP_SMEMF * sizeof(float)>>>(out_off, wc, out_x);
}

// round 7
// speedup vs baseline: 2.4373x; 2.1346x over previous
#include <cuda_runtime.h>
#include <cuda_fp16.h>
#include <math.h>
#include <stdint.h>

#define BB 4
#define CC 64
#define MH 18
#define HH 128
#define WW 128
#define NN 9
#define HWX (HH*WW)

typedef unsigned long long ull;

// ---------------- scratch (static __device__, no allocations) ----------------
__device__ float  g_update[BB*MH*HH*WW];
__device__ float  g_rgoff [BB*MH*HH*WW];
__device__ float  g_m     [BB*NN*HH*WW];
__device__ __half g_xTh   [BB*130*130*CC];        // padded NHWC x_t (fp16)

__device__ __forceinline__ float sigf(float x) { return 1.f/(1.f + __expf(-x)); }

// ---- f32x2 helpers ----
__device__ __forceinline__ ull ffma2(ull a, ull b, ull c) {
    ull d; asm("fma.rn.f32x2 %0,%1,%2,%3;" : "=l"(d) : "l"(a), "l"(b), "l"(c)); return d;
}
__device__ __forceinline__ ull fmul2(ull a, ull b) {
    ull d; asm("mul.rn.f32x2 %0,%1,%2;" : "=l"(d) : "l"(a), "l"(b)); return d;
}
__device__ __forceinline__ ull dup2(float v) {
    ull d; asm("mov.b64 %0,{%1,%1};" : "=l"(d) : "f"(v)); return d;
}
__device__ __forceinline__ void unpack2(ull p, float& lo, float& hi) {
    asm("mov.b64 {%0,%1},%2;" : "=f"(lo), "=f"(hi) : "l"(p));
}

// ---------------- kernel: zero padded NHWC fp16 buffer ----------------
__global__ void k_zero() {
    int i = blockIdx.x * blockDim.x + threadIdx.x;
    const int n = (int)(BB*130*130*CC*sizeof(__half)/16);
    if (i < n) reinterpret_cast<uint4*>(g_xTh)[i] = make_uint4(0,0,0,0);
}

// ---------------- kernel: NCHW fp32 -> padded NHWC fp16 ----------------
__global__ void k_pad(const float* __restrict__ x) {
    __shared__ float sm[64][33];
    int jb = blockIdx.x, i0 = blockIdx.y, b = blockIdx.z;
    int tx = threadIdx.x, ty = threadIdx.y;
    int jcol = jb*32 + tx;
    for (int c = ty; c < 64; c += 8)
        sm[c][tx] = x[((b*CC + c)*HH + i0)*WW + jcol];
    __syncthreads();
    for (int jj = ty; jj < 32; jj += 8) {
        int base = ((b*130 + (i0+1))*130 + (jb*32 + jj + 1))*64;
        g_xTh[base + tx]      = __float2half_rn(sm[tx][jj]);
        g_xTh[base + 32 + tx] = __float2half_rn(sm[32 + tx][jj]);
    }
}

// ====== conv geometry: 16h x 32w tile, 256 threads, 2 px/thread ======
#define IN_TILE (2*18*34)
#define NSLOT 5

struct Slots { int plo[NSLOT]; int ch[NSLOT]; };
__device__ __forceinline__ Slots make_slots(int t, int h0, int w0) {
    Slots s;
    #pragma unroll
    for (int k = 0; k < NSLOT; ++k) {
        int e = t + k*256;
        if (e < IN_TILE) {
            int ch = e / 612; int rr = (e % 612) / 34; int cc2 = e % 34;
            int gh = h0 - 1 + rr, gw = w0 - 1 + cc2;
            s.ch[k] = ch;
            s.plo[k] = (gh >= 0 && gh < HH && gw >= 0 && gw < WW) ? gh*WW + gw : -1;
        } else { s.ch[k] = 0; s.plo[k] = -2; }
    }
    return s;
}

__device__ __forceinline__ float slot_fetch(
    const Slots& s, int k, int ic, int b,
    const float* __restrict__ x, const float* __restrict__ alt)
{
    int plo = s.plo[k];
    if (plo < 0) return 0.f;
    const float* base = (ic < 64) ? x + (b*CC + ic)*HWX
                                  : alt + (b*MH + (ic - 64))*HWX;
    return __ldg(base + plo);
}

// ================= K1: upd + rst convs (36 oc) =================
#define GOC 36
#define G_WF (738*GOC)
#define G_SMEMF (G_WF + 2*IN_TILE)

__global__ void __launch_bounds__(256, 1) k_gatesm(
    const float* __restrict__ x, const float* __restrict__ pre,
    const float* __restrict__ uw, const float* __restrict__ ub,
    const float* __restrict__ rw, const float* __restrict__ rb)
{
    extern __shared__ float sh[];
    float* s_w  = sh;
    float* s_in = sh + G_WF;
    int t  = threadIdx.x;
    int b  = blockIdx.z;
    int h0 = blockIdx.y * 16, w0 = blockIdx.x * 32;

    for (int i = t; i < 18*738; i += 256) {
        int oc = i / 738, k = i % 738;
        s_w[k*GOC + oc]      = uw[i];
        s_w[k*GOC + 18 + oc] = rw[i];
    }

    ull acc[18][2];
    #pragma unroll
    for (int q = 0; q < 18; ++q) { acc[q][0] = 0ULL; acc[q][1] = 0ULL; }

    int ty  = t >> 4;
    int txp = (t & 15) * 2;

    Slots sl = make_slots(t, h0, w0);

    #pragma unroll
    for (int k = 0; k < NSLOT; ++k)
        if (sl.plo[k] != -2) s_in[t + k*256] = slot_fetch(sl, k, sl.ch[k], b, x, pre);
    __syncthreads();

    #pragma unroll 1
    for (int it = 0; it < 41; ++it) {
        const float* buf = s_in + (it & 1) * IN_TILE;

        float pf[NSLOT];
        if (it < 40) {
            int nc0 = it*2 + 2;
            #pragma unroll
            for (int k = 0; k < NSLOT; ++k)
                pf[k] = (sl.plo[k] != -2) ? slot_fetch(sl, k, nc0 + sl.ch[k], b, x, pre) : 0.f;
        }

        int c0 = it*2;
        #pragma unroll
        for (int ch = 0; ch < 2; ++ch) {
            #pragma unroll
            for (int ki = 0; ki < 3; ++ki) {
                int ib = ch*612 + (ty + ki)*34 + txp;
                float2 a01 = *reinterpret_cast<const float2*>(buf + ib);
                float2 a23 = *reinterpret_cast<const float2*>(buf + ib + 2);
                ull d0 = dup2(a01.x), d1 = dup2(a01.y), d2 = dup2(a23.x), d3 = dup2(a23.y);
                #pragma unroll
                for (int kj = 0; kj < 3; ++kj) {
                    ull dA = (kj == 0) ? d0 : (kj == 1) ? d1 : d2;
                    ull dB = (kj == 0) ? d1 : (kj == 1) ? d2 : d3;
                    const float* wrow = s_w + ((c0 + ch)*9 + ki*3 + kj)*GOC;
                    #pragma unroll
                    for (int q = 0; q < 9; ++q) {
                        ulonglong2 wv = *reinterpret_cast<const ulonglong2*>(wrow + q*4);
                        acc[2*q  ][0] = ffma2(wv.x, dA, acc[2*q  ][0]);
                        acc[2*q  ][1] = ffma2(wv.x, dB, acc[2*q  ][1]);
                        acc[2*q+1][0] = ffma2(wv.y, dA, acc[2*q+1][0]);
                        acc[2*q+1][1] = ffma2(wv.y, dB, acc[2*q+1][1]);
                    }
                }
            }
        }

        if (it < 40) {
            float* nbuf = s_in + ((it + 1) & 1) * IN_TILE;
            #pragma unroll
            for (int k = 0; k < NSLOT; ++k)
                if (sl.plo[k] != -2) nbuf[t + k*256] = pf[k];
        }
        __syncthreads();
    }

    int h = h0 + ty;
    int w1 = w0 + txp;
    #pragma unroll
    for (int j = 0; j < 9; ++j) {
        float l0, g0, l1, g1;
        unpack2(acc[j][0], l0, g0);
        unpack2(acc[j][1], l1, g1);
        int oc0 = 2*j, oc1 = 2*j + 1;
        int i0 = ((b*MH + oc0)*HH + h)*WW + w1;
        int i1 = ((b*MH + oc1)*HH + h)*WW + w1;
        *reinterpret_cast<float2*>(g_update + i0) =
            make_float2(sigf(l0 + ub[oc0]), sigf(l1 + ub[oc0]));
        *reinterpret_cast<float2*>(g_update + i1) =
            make_float2(sigf(g0 + ub[oc1]), sigf(g1 + ub[oc1]));
    }
    #pragma unroll
    for (int j = 9; j < 18; ++j) {
        float l0, g0, l1, g1;
        unpack2(acc[j][0], l0, g0);
        unpack2(acc[j][1], l1, g1);
        int oc0 = 2*j - 18, oc1 = oc0 + 1;
        int i0 = ((b*MH + oc0)*HH + h)*WW + w1;
        int i1 = ((b*MH + oc1)*HH + h)*WW + w1;
        float2 p0 = *reinterpret_cast<const float2*>(pre + i0);
        float2 p1 = *reinterpret_cast<const float2*>(pre + i1);
        *reinterpret_cast<float2*>(g_rgoff + i0) =
            make_float2(p0.x * sigf(l0 + rb[oc0]), p0.y * sigf(l1 + rb[oc0]));
        *reinterpret_cast<float2*>(g_rgoff + i1) =
            make_float2(p1.x * sigf(g0 + rb[oc1]), p1.y * sigf(g1 + rb[oc1]));
    }
}

// ================= K2: cand (18) + wg (9) convs + GRU combine =================
#define COC 28
#define C_WF (738*COC)
#define C_SMEMF (C_WF + 2*IN_TILE)

__global__ void __launch_bounds__(256, 1) k_cand(
    const float* __restrict__ x, const float* __restrict__ pre,
    const float* __restrict__ mean,
    const float* __restrict__ ow, const float* __restrict__ ob,
    const float* __restrict__ ww, const float* __restrict__ wb,
    float* __restrict__ out_off, float* __restrict__ out_mean)
{
    extern __shared__ float sh[];
    float* s_w  = sh;
    float* s_in = sh + C_WF;
    int t  = threadIdx.x;
    int b  = blockIdx.z;
    int h0 = blockIdx.y * 16, w0 = blockIdx.x * 32;

    for (int i = t; i < C_WF/4; i += 256)
        reinterpret_cast<float4*>(s_w)[i] = make_float4(0.f,0.f,0.f,0.f);
    __syncthreads();
    for (int i = t; i < 18*738; i += 256) {
        int oc = i / 738, k = i % 738;
        s_w[k*COC + oc] = ow[i];
    }
    for (int i = t; i < 9*576; i += 256) {
        int oc = i / 576, k = i % 576;
        s_w[k*COC + 18 + oc] = ww[i];
    }

    ull acc[14][2];
    #pragma unroll
    for (int q = 0; q < 14; ++q) { acc[q][0] = 0ULL; acc[q][1] = 0ULL; }

    int ty  = t >> 4;
    int txp = (t & 15) * 2;

    Slots sl = make_slots(t, h0, w0);

    #pragma unroll
    for (int k = 0; k < NSLOT; ++k)
        if (sl.plo[k] != -2) s_in[t + k*256] = slot_fetch(sl, k, sl.ch[k], b, x, g_rgoff);
    __syncthreads();

    #pragma unroll 1
    for (int it = 0; it < 41; ++it) {
        const float* buf = s_in + (it & 1) * IN_TILE;

        float pf[NSLOT];
        if (it < 40) {
            int nc0 = it*2 + 2;
            #pragma unroll
            for (int k = 0; k < NSLOT; ++k)
                pf[k] = (sl.plo[k] != -2) ? slot_fetch(sl, k, nc0 + sl.ch[k], b, x, g_rgoff) : 0.f;
        }

        int c0 = it*2;
        #pragma unroll
        for (int ch = 0; ch < 2; ++ch) {
            #pragma unroll
            for (int ki = 0; ki < 3; ++ki) {
                int ib = ch*612 + (ty + ki)*34 + txp;
                float2 a01 = *reinterpret_cast<const float2*>(buf + ib);
                float2 a23 = *reinterpret_cast<const float2*>(buf + ib + 2);
                ull d0 = dup2(a01.x), d1 = dup2(a01.y), d2 = dup2(a23.x), d3 = dup2(a23.y);
                #pragma unroll
                for (int kj = 0; kj < 3; ++kj) {
                    ull dA = (kj == 0) ? d0 : (kj == 1) ? d1 : d2;
                    ull dB = (kj == 0) ? d1 : (kj == 1) ? d2 : d3;
                    const float* wrow = s_w + ((c0 + ch)*9 + ki*3 + kj)*COC;
                    #pragma unroll
                    for (int q = 0; q < 7; ++q) {
                        ulonglong2 wv = *reinterpret_cast<const ulonglong2*>(wrow + q*4);
                        acc[2*q  ][0] = ffma2(wv.x, dA, acc[2*q  ][0]);
                        acc[2*q  ][1] = ffma2(wv.x, dB, acc[2*q  ][1]);
                        acc[2*q+1][0] = ffma2(wv.y, dA, acc[2*q+1][0]);
                        acc[2*q+1][1] = ffma2(wv.y, dB, acc[2*q+1][1]);
                    }
                }
            }
        }

        if (it < 40) {
            float* nbuf = s_in + ((it + 1) & 1) * IN_TILE;
            #pragma unroll
            for (int k = 0; k < NSLOT; ++k)
                if (sl.plo[k] != -2) nbuf[t + k*256] = pf[k];
        }
        __syncthreads();
    }

    int h = h0 + ty;
    int w1 = w0 + txp;
    #pragma unroll
    for (int j = 0; j < 9; ++j) {
        float l0, g0, l1, g1;
        unpack2(acc[j][0], l0, g0);
        unpack2(acc[j][1], l1, g1);
        int oc0 = 2*j, oc1 = oc0 + 1;
        #pragma unroll
        for (int s = 0; s < 2; ++s) {
            int oc = s ? oc1 : oc0;
            float cv0 = tanhf((s ? g0 : l0) + ob[oc]);
            float cv1 = tanhf((s ? g1 : l1) + ob[oc]);
            int i1 = ((b*MH + oc)*HH + h)*WW + w1;
            float2 u  = *reinterpret_cast<const float2*>(g_update + i1);
            float2 p  = *reinterpret_cast<const float2*>(pre + i1);
            float2 mn = *reinterpret_cast<const float2*>(mean + i1);
            float mn0 = 0.5f*(mn.x + p.x);
            float mn1 = 0.5f*(mn.y + p.y);
            *reinterpret_cast<float2*>(out_off + i1) =
                make_float2(p.x*(1.f - u.x) + cv0*u.x + mn0,
                            p.y*(1.f - u.y) + cv1*u.y + mn1);
            *reinterpret_cast<float2*>(out_mean + i1) = make_float2(mn0, mn1);
        }
    }
    #pragma unroll
    for (int j = 9; j < 14; ++j) {
        float l0, g0, l1, g1;
        unpack2(acc[j][0], l0, g0);
        unpack2(acc[j][1], l1, g1);
        int oc0 = 2*(j - 9), oc1 = oc0 + 1;
        int i0 = ((b*NN + oc0)*HH + h)*WW + w1;
        *reinterpret_cast<float2*>(g_m + i0) =
            make_float2(sigf(l0 + wb[oc0]), sigf(l1 + wb[oc0]));
        if (oc1 < 9) {
            int i1 = ((b*NN + oc1)*HH + h)*WW + w1;
            *reinterpret_cast<float2*>(g_m + i1) =
                make_float2(sigf(g0 + wb[oc1]), sigf(g1 + wb[oc1]));
        }
    }
}

// ================= k_warp: deformable warp + regroup conv via HMMA =================
#define KP 584
#define W_SW_OFF 0
#define W_SV_OFF (64*KP*2)
#define W_WT_OFF (W_SV_OFF + 64*KP*2)
#define W_AD_OFF (W_WT_OFF + 576*16)
#define W_SMEMB (W_AD_OFF + 576*16)

__device__ __forceinline__ uint32_t smaddr(const void* p) {
    return (uint32_t)__cvta_generic_to_shared(p);
}

__global__ void __launch_bounds__(256, 1) k_warp(
    const float* __restrict__ off, const float* __restrict__ Wc,
    float* __restrict__ out)
{
    extern __shared__ char shb[];
    __half* sW  = reinterpret_cast<__half*>(shb + W_SW_OFF);
    __half* sv  = reinterpret_cast<__half*>(shb + W_SV_OFF);
    float4* wts = reinterpret_cast<float4*>(shb + W_WT_OFF);
    int4*   ads = reinterpret_cast<int4*>(shb + W_AD_OFF);
    float*  so  = reinterpret_cast<float*>(shb + W_WT_OFF);   // out stage [64][69]

    int t = threadIdx.x;
    int lane = t & 31, warp = t >> 5;

    // load + repack W -> fp16, k' = n*64+ci
    for (int i = t; i < 64*576; i += 256) {
        int co = i / 576, r = i % 576;
        int ci = r / 9, n = r % 9;
        sW[co*KP + n*64 + ci] = __float2half_rn(Wc[i]);
    }
    __syncthreads();

    // mma geometry
    int gid = lane >> 2, tig = lane & 3;
    int px0 = (warp >> 1) * 16;
    int co0 = (warp & 1) * 32;
    uint32_t aAddr = smaddr(sv) + (((px0 + (lane & 15))*KP + (lane >> 4)*8) << 1);
    uint32_t bAddr0 = smaddr(sW) + (((co0 + (lane & 7) + (lane >> 4)*8)*KP
                                    + ((lane >> 3) & 1)*8) << 1);
    uint32_t bAddr1 = bAddr0 + 16*KP*2;

    int g = lane >> 3;                // gather group 0..3
    int c = lane & 7;                 // ci8 group

    for (int tile = blockIdx.x; tile < BB*HH*2; tile += gridDim.x) {
        int b = tile >> 8;
        int rem = tile & 255;
        int h  = rem >> 1;
        int w0 = (rem & 1) << 6;
        const __half* xh = g_xTh + b*130*130*64;

        // ---- phase 0: per-item offsets -> corner indices + weights ----
        for (int item = t; item < 576; item += 256) {
            int n = item >> 6, px = item & 63;
            int wc = w0 + px;
            float pnx = (float)(n/3 - 1), pny = (float)(n%3 - 1);
            float ox = __ldg(off + ((b*MH + n    )*HH + h)*WW + wc);
            float oy = __ldg(off + ((b*MH + 9 + n)*HH + h)*WW + wc);
            float mm = g_m[((b*NN + n)*HH + h)*WW + wc];
            float px_ = (float)(h + 1) + pnx + ox;
            float py_ = (float)(wc + 1) + pny + oy;
            float fx = floorf(px_), fy = floorf(py_);
            float qxl = fminf(fmaxf(fx,       0.f), 129.f);
            float qxr = fminf(fmaxf(fx + 1.f, 0.f), 129.f);
            float qyl = fminf(fmaxf(fy,       0.f), 129.f);
            float qyr = fminf(fmaxf(fy + 1.f, 0.f), 129.f);
            float pxc = fminf(fmaxf(px_, 0.f), 129.f);
            float pyc = fminf(fmaxf(py_, 0.f), 129.f);
            float gx_l = 1.f + (qxl - pxc);
            float gx_r = 1.f - (qxr - pxc);
            float gy_l = 1.f + (qyl - pyc);
            float gy_r = 1.f - (qyr - pyc);
            int ixl = (int)qxl, ixr = (int)qxr, iyl = (int)qyl, iyr = (int)qyr;
            wts[item] = make_float4(gx_l*gy_l*mm, gx_r*gy_r*mm,
                                    gx_l*gy_r*mm, gx_r*gy_l*mm);
            ads[item] = make_int4(ixl*130 + iyl, ixr*130 + iyr,
                                  ixl*130 + iyr, ixr*130 + iyl);
        }
        __syncthreads();

        // ---- phase 1: gather + blend -> sv fp16 ----
        #pragma unroll 2
        for (int p = 0; p < 18; ++p) {
            int item = p*32 + warp*4 + g;
            int n = item >> 6, px = item & 63;
            float4 wt = wts[item];
            int4   ad = ads[item];
            uint4 rLT = *reinterpret_cast<const uint4*>(xh + ad.x*64 + c*8);
            uint4 rRB = *reinterpret_cast<const uint4*>(xh + ad.y*64 + c*8);
            uint4 rLB = *reinterpret_cast<const uint4*>(xh + ad.z*64 + c*8);
            uint4 rRT = *reinterpret_cast<const uint4*>(xh + ad.w*64 + c*8);
            ull dLT = dup2(wt.x), dRB = dup2(wt.y), dLB = dup2(wt.z), dRT = dup2(wt.w);
            uint32_t outh[4];
            const uint32_t* hLT = &rLT.x;
            const uint32_t* hRB = &rRB.x;
            const uint32_t* hLB = &rLB.x;
            const uint32_t* hRT = &rRT.x;
            #pragma unroll
            for (int q = 0; q < 4; ++q) {
                float2 fLT = __half22float2(*reinterpret_cast<const __half2*>(hLT + q));
                float2 fRB = __half22float2(*reinterpret_cast<const __half2*>(hRB + q));
                float2 fLB = __half22float2(*reinterpret_cast<const __half2*>(hLB + q));
                float2 fRT = __half22float2(*reinterpret_cast<const __half2*>(hRT + q));
                ull v;
                asm("mov.b64 %0,{%1,%2};" : "=l"(v) : "f"(fLT.x), "f"(fLT.y));
                v = fmul2(dLT, v);
                ull u2;
                asm("mov.b64 %0,{%1,%2};" : "=l"(u2) : "f"(fRB.x), "f"(fRB.y));
                v = ffma2(dRB, u2, v);
                asm("mov.b64 %0,{%1,%2};" : "=l"(u2) : "f"(fLB.x), "f"(fLB.y));
                v = ffma2(dLB, u2, v);
                asm("mov.b64 %0,{%1,%2};" : "=l"(u2) : "f"(fRT.x), "f"(fRT.y));
                v = ffma2(dRT, u2, v);
                float lo, hi;
                unpack2(v, lo, hi);
                __half2 hh = __floats2half2_rn(lo, hi);
                outh[q] = *reinterpret_cast<uint32_t*>(&hh);
            }
            *reinterpret_cast<uint4*>(sv + px*KP + n*64 + c*8) =
                make_uint4(outh[0], outh[1], outh[2], outh[3]);
        }
        __syncthreads();

        // ---- phase 2: HMMA GEMM out[64px][64co] ----
        float d[4][4];
        #pragma unroll
        for (int i = 0; i < 4; ++i)
            #pragma unroll
            for (int j = 0; j < 4; ++j) d[i][j] = 0.f;

        #pragma unroll 4
        for (int ks = 0; ks < 36; ++ks) {
            uint32_t a0, a1, a2, a3, b0, b1, b2, b3, b4, b5, b6, b7;
            asm volatile("ldmatrix.sync.aligned.m8n8.x4.shared.b16 {%0,%1,%2,%3},[%4];"
                : "=r"(a0), "=r"(a1), "=r"(a2), "=r"(a3) : "r"(aAddr + ks*32));
            asm volatile("ldmatrix.sync.aligned.m8n8.x4.shared.b16 {%0,%1,%2,%3},[%4];"
                : "=r"(b0), "=r"(b1), "=r"(b2), "=r"(b3) : "r"(bAddr0 + ks*32));
            asm volatile("ldmatrix.sync.aligned.m8n8.x4.shared.b16 {%0,%1,%2,%3},[%4];"
                : "=r"(b4), "=r"(b5), "=r"(b6), "=r"(b7) : "r"(bAddr1 + ks*32));
            asm volatile("mma.sync.aligned.m16n8k16.row.col.f32.f16.f16.f32 "
                "{%0,%1,%2,%3},{%4,%5,%6,%7},{%8,%9},{%0,%1,%2,%3};"
                : "+f"(d[0][0]), "+f"(d[0][1]), "+f"(d[0][2]), "+f"(d[0][3])
                : "r"(a0), "r"(a1), "r"(a2), "r"(a3), "r"(b0), "r"(b1));
            asm volatile("mma.sync.aligned.m16n8k16.row.col.f32.f16.f16.f32 "
                "{%0,%1,%2,%3},{%4,%5,%6,%7},{%8,%9},{%0,%1,%2,%3};"
                : "+f"(d[1][0]), "+f"(d[1][1]), "+f"(d[1][2]), "+f"(d[1][3])
                : "r"(a0), "r"(a1), "r"(a2), "r"(a3), "r"(b2), "r"(b3));
            asm volatile("mma.sync.aligned.m16n8k16.row.col.f32.f16.f16.f32 "
                "{%0,%1,%2,%3},{%4,%5,%6,%7},{%8,%9},{%0,%1,%2,%3};"
                : "+f"(d[2][0]), "+f"(d[2][1]), "+f"(d[2][2]), "+f"(d[2][3])
                : "r"(a0), "r"(a1), "r"(a2), "r"(a3), "r"(b4), "r"(b5));
            asm volatile("mma.sync.aligned.m16n8k16.row.col.f32.f16.f16.f32 "
                "{%0,%1,%2,%3},{%4,%5,%6,%7},{%8,%9},{%0,%1,%2,%3};"
                : "+f"(d[3][0]), "+f"(d[3][1]), "+f"(d[3][2]), "+f"(d[3][3])
                : "r"(a0), "r"(a1), "r"(a2), "r"(a3), "r"(b6), "r"(b7));
        }
        __syncthreads();

        // stage D to smem [px][69]
        #pragma unroll
        for (int nt = 0; nt < 4; ++nt) {
            int cb = co0 + nt*8 + tig*2;
            int pr = px0 + gid;
            so[pr*69 + cb]       = d[nt][0];
            so[pr*69 + cb + 1]   = d[nt][1];
            so[(pr+8)*69 + cb]     = d[nt][2];
            so[(pr+8)*69 + cb + 1] = d[nt][3];
        }
        __syncthreads();

        for (int i = t; i < 4096; i += 256) {
            int co = i >> 6, px = i & 63;
            out[((b*CC + co)*HH + h)*WW + w0 + px] = so[px*69 + co];
        }
        __syncthreads();
    }
}

// ---------------- launch ----------------
extern "C" void kernel_launch(void* const* d_in, const int* in_sizes, int n_in,
                              void* d_out, int out_size)
{
    const float* x    = (const float*)d_in[0];
    const float* pre  = (const float*)d_in[1];
    const float* mean = (const float*)d_in[2];
    const float* uw   = (const float*)d_in[3];
    const float* ub   = (const float*)d_in[4];
    const float* rw   = (const float*)d_in[5];
    const float* rb   = (const float*)d_in[6];
    const float* ow   = (const float*)d_in[7];
    const float* ob   = (const float*)d_in[8];
    const float* ww   = (const float*)d_in[9];
    const float* wb   = (const float*)d_in[10];
    const float* wc   = (const float*)d_in[11];

    float* out_x    = (float*)d_out;
    float* out_off  = out_x + BB*CC*HH*WW;
    float* out_mean = out_off + BB*MH*HH*WW;

    cudaFuncSetAttribute(k_gatesm, cudaFuncAttributeMaxDynamicSharedMemorySize,
                         G_SMEMF * (int)sizeof(float));
    cudaFuncSetAttribute(k_cand, cudaFuncAttributeMaxDynamicSharedMemorySize,
                         C_SMEMF * (int)sizeof(float));
    cudaFuncSetAttribute(k_warp, cudaFuncAttributeMaxDynamicSharedMemorySize,
                         W_SMEMB);

    k_zero<<<((int)(BB*130*130*CC*sizeof(__half)/16) + 255)/256, 256>>>();
    k_pad<<<dim3(4, 128, 4), dim3(32, 8)>>>(x);

    dim3 gg(WW/32, HH/16, BB);
    k_gatesm<<<gg, 256, G_SMEMF * sizeof(float)>>>(x, pre, uw, ub, rw, rb);
    k_cand<<<gg, 256, C_SMEMF * sizeof(float)>>>(x, pre, mean, ow, ob, ww, wb,
                                                 out_off, out_mean);
    k_warp<<<148, 256, W_SMEMB>>>(out_off, wc, out_x);
}

// round 9
// speedup vs baseline: 3.1314x; 1.2848x over previous
#include <cuda_runtime.h>
#include <cuda_fp16.h>
#include <math.h>
#include <stdint.h>

#define BB 4
#define CC 64
#define MH 18
#define HH 128
#define WW 128
#define NN 9
#define HWX (HH*WW)

typedef unsigned long long ull;

// ---------------- scratch (static __device__, no allocations) ----------------
__device__ float  g_update[BB*MH*HH*WW];
__device__ float  g_rgoff [BB*MH*HH*WW];
__device__ float  g_m     [BB*NN*HH*WW];
__device__ __half g_xTh   [BB*130*130*CC];        // padded NHWC x_t (fp16)

__device__ __forceinline__ float sigf(float x) { return 1.f/(1.f + __expf(-x)); }

// ---- f32x2 helpers ----
__device__ __forceinline__ ull ffma2(ull a, ull b, ull c) {
    ull d; asm("fma.rn.f32x2 %0,%1,%2,%3;" : "=l"(d) : "l"(a), "l"(b), "l"(c)); return d;
}
__device__ __forceinline__ ull fmul2(ull a, ull b) {
    ull d; asm("mul.rn.f32x2 %0,%1,%2;" : "=l"(d) : "l"(a), "l"(b)); return d;
}
__device__ __forceinline__ ull dup2(float v) {
    ull d; asm("mov.b64 %0,{%1,%1};" : "=l"(d) : "f"(v)); return d;
}
__device__ __forceinline__ void unpack2(ull p, float& lo, float& hi) {
    asm("mov.b64 {%0,%1},%2;" : "=f"(lo), "=f"(hi) : "l"(p));
}
__device__ __forceinline__ uint32_t smaddr(const void* p) {
    return (uint32_t)__cvta_generic_to_shared(p);
}

// ---------------- kernel: zero padded NHWC fp16 buffer ----------------
__global__ void k_zero() {
    int i = blockIdx.x * blockDim.x + threadIdx.x;
    const int n = (int)(BB*130*130*CC*sizeof(__half)/16);
    if (i < n) reinterpret_cast<uint4*>(g_xTh)[i] = make_uint4(0,0,0,0);
}

// ---------------- kernel: NCHW fp32 -> padded NHWC fp16 ----------------
__global__ void k_pad(const float* __restrict__ x) {
    __shared__ float sm[64][33];
    int jb = blockIdx.x, i0 = blockIdx.y, b = blockIdx.z;
    int tx = threadIdx.x, ty = threadIdx.y;
    int jcol = jb*32 + tx;
    for (int c = ty; c < 64; c += 8)
        sm[c][tx] = x[((b*CC + c)*HH + i0)*WW + jcol];
    __syncthreads();
    for (int jj = ty; jj < 32; jj += 8) {
        int base = ((b*130 + (i0+1))*130 + (jb*32 + jj + 1))*64;
        g_xTh[base + tx]      = __float2half_rn(sm[tx][jj]);
        g_xTh[base + 32 + tx] = __float2half_rn(sm[32 + tx][jj]);
    }
}

// ====== shared HMMA conv geometry ======
// tile = (b, h, half-row): 64 px. Input halo 3 rows x 66 cols x 96 K (82 used).
#define PIN 104                       /* sIn pitch in halves (conflict-free)   */
#define SIN_ROWS 198                  /* 3*66                                  */
#define SIN_B (SIN_ROWS*PIN*2)        /* 41184 bytes                           */
#define WPP 872                       /* weight pitch in halves (conflict-free)*/
#define SO_PITCH 68
#define SO_B (64*SO_PITCH*4)          /* 17408 bytes */

// ================= K1: upd + rst + wg convs via HMMA =================
#define W1_OC 64                      /* 45 used (18 upd, 18 rst, 9 wg) */
#define K1_SO_OFF (SIN_B + W1_OC*WPP*2)
#define K1_SMEM (K1_SO_OFF + SO_B)    /* 41184 + 111616 + 17408 = 170208 */

__global__ void __launch_bounds__(256, 1) k1_gates(
    const float* __restrict__ pre,
    const float* __restrict__ uw, const float* __restrict__ ub,
    const float* __restrict__ rw, const float* __restrict__ rb,
    const float* __restrict__ ww, const float* __restrict__ wb)
{
    extern __shared__ char shb[];
    __half* sIn = reinterpret_cast<__half*>(shb);
    __half* Wp  = reinterpret_cast<__half*>(shb + SIN_B);
    float*  so  = reinterpret_cast<float*>(shb + K1_SO_OFF);   // dedicated

    int t = threadIdx.x;
    int lane = t & 31, warp = t >> 5;

    // zero sIn (K-pad cols stay zero forever) and Wp
    for (int i = t; i < SIN_ROWS*PIN/8; i += 256)
        reinterpret_cast<uint4*>(sIn)[i] = make_uint4(0,0,0,0);
    for (int i = t; i < W1_OC*WPP/8; i += 256)
        reinterpret_cast<uint4*>(Wp)[i] = make_uint4(0,0,0,0);
    __syncthreads();
    // repack weights -> Wp[oc][pos][ic]
    for (int i = t; i < 18*738; i += 256) {
        int oc = i / 738, r = i % 738, ic = r / 9, pos = r % 9;
        Wp[oc*WPP + pos*96 + ic]        = __float2half_rn(uw[i]);
        Wp[(18 + oc)*WPP + pos*96 + ic] = __float2half_rn(rw[i]);
    }
    for (int i = t; i < 9*576; i += 256) {
        int oc = i / 576, r = i % 576, ic = r / 9, pos = r % 9;
        Wp[(36 + oc)*WPP + pos*96 + ic] = __float2half_rn(ww[i]);
    }
    __syncthreads();

    int wp = warp & 3, wo = warp >> 2;
    int px0 = wp * 16, oc0 = wo * 32;
    uint32_t aBase = smaddr(sIn) + (((px0 + (lane & 15))*PIN) + (lane >> 4)*8)*2;
    uint32_t bBase = smaddr(Wp) + ((oc0 + (lane & 7) + ((lane >> 4) & 1)*8)*WPP)*2
                     + ((lane >> 3) & 1)*16;
    int gid = lane >> 2, tig = lane & 3;

    for (int tile = blockIdx.x; tile < BB*HH*2; tile += gridDim.x) {
        int b = tile >> 8;
        int rem = tile & 255;
        int h  = rem >> 1;
        int w0 = (rem & 1) << 6;

        // ---- stage x channels (0..63) from padded NHWC fp16 ----
        for (int i = t; i < 1584; i += 256) {
            int r = i >> 3, q = i & 7;
            int crow = r / 66, col = r % 66;
            const uint4* src = reinterpret_cast<const uint4*>(
                g_xTh + ((b*130 + h + crow)*130 + (w0 + col))*64) + q;
            reinterpret_cast<uint4*>(sIn + r*PIN)[q] = *src;
        }
        // ---- stage pre channels (64..81), fp32 -> fp16, bounds-checked ----
        for (int i = t; i < 3564; i += 256) {
            int ch = i / 198, r = i % 198;
            int crow = r / 66, col = r % 66;
            int gh = h - 1 + crow, gw = w0 - 1 + col;
            float v = 0.f;
            if (gh >= 0 && gh < HH && gw >= 0 && gw < WW)
                v = pre[(b*MH + ch)*HWX + gh*WW + gw];
            sIn[r*PIN + 64 + ch] = __float2half_rn(v);
        }
        __syncthreads();

        // ---- 9-position shifted GEMM, K=96 each ----
        float d[4][4];
        #pragma unroll
        for (int i = 0; i < 4; ++i)
            #pragma unroll
            for (int j = 0; j < 4; ++j) d[i][j] = 0.f;

        #pragma unroll 1
        for (int pos = 0; pos < 9; ++pos) {
            int ki = pos / 3, kj = pos % 3;
            uint32_t aPos = aBase + (ki*66 + kj)*PIN*2;
            uint32_t bPos = bBase + pos*96*2;
            #pragma unroll
            for (int kk = 0; kk < 6; ++kk) {
                uint32_t a0,a1,a2,a3, b0,b1,b2,b3, b4,b5,b6,b7;
                asm volatile("ldmatrix.sync.aligned.m8n8.x4.shared.b16 {%0,%1,%2,%3},[%4];"
                    : "=r"(a0),"=r"(a1),"=r"(a2),"=r"(a3) : "r"(aPos + kk*32));
                asm volatile("ldmatrix.sync.aligned.m8n8.x4.shared.b16 {%0,%1,%2,%3},[%4];"
                    : "=r"(b0),"=r"(b1),"=r"(b2),"=r"(b3) : "r"(bPos + kk*32));
                asm volatile("ldmatrix.sync.aligned.m8n8.x4.shared.b16 {%0,%1,%2,%3},[%4];"
                    : "=r"(b4),"=r"(b5),"=r"(b6),"=r"(b7) : "r"(bPos + 16*WPP*2 + kk*32));
                asm volatile("mma.sync.aligned.m16n8k16.row.col.f32.f16.f16.f32 "
                    "{%0,%1,%2,%3},{%4,%5,%6,%7},{%8,%9},{%0,%1,%2,%3};"
                    : "+f"(d[0][0]),"+f"(d[0][1]),"+f"(d[0][2]),"+f"(d[0][3])
                    : "r"(a0),"r"(a1),"r"(a2),"r"(a3),"r"(b0),"r"(b1));
                asm volatile("mma.sync.aligned.m16n8k16.row.col.f32.f16.f16.f32 "
                    "{%0,%1,%2,%3},{%4,%5,%6,%7},{%8,%9},{%0,%1,%2,%3};"
                    : "+f"(d[1][0]),"+f"(d[1][1]),"+f"(d[1][2]),"+f"(d[1][3])
                    : "r"(a0),"r"(a1),"r"(a2),"r"(a3),"r"(b2),"r"(b3));
                asm volatile("mma.sync.aligned.m16n8k16.row.col.f32.f16.f16.f32 "
                    "{%0,%1,%2,%3},{%4,%5,%6,%7},{%8,%9},{%0,%1,%2,%3};"
                    : "+f"(d[2][0]),"+f"(d[2][1]),"+f"(d[2][2]),"+f"(d[2][3])
                    : "r"(a0),"r"(a1),"r"(a2),"r"(a3),"r"(b4),"r"(b5));
                asm volatile("mma.sync.aligned.m16n8k16.row.col.f32.f16.f16.f32 "
                    "{%0,%1,%2,%3},{%4,%5,%6,%7},{%8,%9},{%0,%1,%2,%3};"
                    : "+f"(d[3][0]),"+f"(d[3][1]),"+f"(d[3][2]),"+f"(d[3][3])
                    : "r"(a0),"r"(a1),"r"(a2),"r"(a3),"r"(b6),"r"(b7));
            }
        }

        // ---- stage D (dedicated so region; no clobber of sIn) ----
        #pragma unroll
        for (int nt = 0; nt < 4; ++nt) {
            int oc = oc0 + nt*8 + tig*2;
            int pr = px0 + gid;
            so[pr*SO_PITCH + oc]         = d[nt][0];
            so[pr*SO_PITCH + oc + 1]     = d[nt][1];
            so[(pr+8)*SO_PITCH + oc]     = d[nt][2];
            so[(pr+8)*SO_PITCH + oc + 1] = d[nt][3];
        }
        __syncthreads();

        for (int i = t; i < 45*64; i += 256) {
            int oc = i >> 6, px = i & 63;
            float a = so[px*SO_PITCH + oc];
            if (oc < 18) {
                g_update[((b*MH + oc)*HH + h)*WW + w0 + px] = sigf(a + ub[oc]);
            } else if (oc < 36) {
                int o = oc - 18;
                int idx = ((b*MH + o)*HH + h)*WW + w0 + px;
                g_rgoff[idx] = pre[idx] * sigf(a + rb[o]);
            } else {
                int o = oc - 36;
                g_m[((b*NN + o)*HH + h)*WW + w0 + px] = sigf(a + wb[o]);
            }
        }
        __syncthreads();
    }
}

// ================= K2: cand conv via HMMA + GRU combine =================
#define W2_OC 32                      /* 18 used */
#define K2_SO_OFF (SIN_B + W2_OC*WPP*2)
#define K2_SMEM (K2_SO_OFF + SO_B)    /* 41184 + 55808 + 17408 = 114400 */

__global__ void __launch_bounds__(256, 1) k2_cand(
    const float* __restrict__ pre, const float* __restrict__ mean,
    const float* __restrict__ ow, const float* __restrict__ ob,
    float* __restrict__ out_off, float* __restrict__ out_mean)
{
    extern __shared__ char shb[];
    __half* sIn = reinterpret_cast<__half*>(shb);
    __half* Wp  = reinterpret_cast<__half*>(shb + SIN_B);
    float*  so  = reinterpret_cast<float*>(shb + K2_SO_OFF);   // dedicated

    int t = threadIdx.x;
    int lane = t & 31, warp = t >> 5;

    for (int i = t; i < SIN_ROWS*PIN/8; i += 256)
        reinterpret_cast<uint4*>(sIn)[i] = make_uint4(0,0,0,0);
    for (int i = t; i < W2_OC*WPP/8; i += 256)
        reinterpret_cast<uint4*>(Wp)[i] = make_uint4(0,0,0,0);
    __syncthreads();
    for (int i = t; i < 18*738; i += 256) {
        int oc = i / 738, r = i % 738, ic = r / 9, pos = r % 9;
        Wp[oc*WPP + pos*96 + ic] = __float2half_rn(ow[i]);
    }
    __syncthreads();

    int wp = warp & 3, wo = warp >> 2;
    int px0 = wp * 16, oc0 = wo * 16;
    uint32_t aBase = smaddr(sIn) + (((px0 + (lane & 15))*PIN) + (lane >> 4)*8)*2;
    uint32_t bBase = smaddr(Wp) + ((oc0 + (lane & 7) + ((lane >> 4) & 1)*8)*WPP)*2
                     + ((lane >> 3) & 1)*16;
    int gid = lane >> 2, tig = lane & 3;

    for (int tile = blockIdx.x; tile < BB*HH*2; tile += gridDim.x) {
        int b = tile >> 8;
        int rem = tile & 255;
        int h  = rem >> 1;
        int w0 = (rem & 1) << 6;

        for (int i = t; i < 1584; i += 256) {
            int r = i >> 3, q = i & 7;
            int crow = r / 66, col = r % 66;
            const uint4* src = reinterpret_cast<const uint4*>(
                g_xTh + ((b*130 + h + crow)*130 + (w0 + col))*64) + q;
            reinterpret_cast<uint4*>(sIn + r*PIN)[q] = *src;
        }
        for (int i = t; i < 3564; i += 256) {
            int ch = i / 198, r = i % 198;
            int crow = r / 66, col = r % 66;
            int gh = h - 1 + crow, gw = w0 - 1 + col;
            float v = 0.f;
            if (gh >= 0 && gh < HH && gw >= 0 && gw < WW)
                v = g_rgoff[(b*MH + ch)*HWX + gh*WW + gw];
            sIn[r*PIN + 64 + ch] = __float2half_rn(v);
        }
        __syncthreads();

        float d[2][4];
        #pragma unroll
        for (int i = 0; i < 2; ++i)
            #pragma unroll
            for (int j = 0; j < 4; ++j) d[i][j] = 0.f;

        #pragma unroll 1
        for (int pos = 0; pos < 9; ++pos) {
            int ki = pos / 3, kj = pos % 3;
            uint32_t aPos = aBase + (ki*66 + kj)*PIN*2;
            uint32_t bPos = bBase + pos*96*2;
            #pragma unroll
            for (int kk = 0; kk < 6; ++kk) {
                uint32_t a0,a1,a2,a3, b0,b1,b2,b3;
                asm volatile("ldmatrix.sync.aligned.m8n8.x4.shared.b16 {%0,%1,%2,%3},[%4];"
                    : "=r"(a0),"=r"(a1),"=r"(a2),"=r"(a3) : "r"(aPos + kk*32));
                asm volatile("ldmatrix.sync.aligned.m8n8.x4.shared.b16 {%0,%1,%2,%3},[%4];"
                    : "=r"(b0),"=r"(b1),"=r"(b2),"=r"(b3) : "r"(bPos + kk*32));
                asm volatile("mma.sync.aligned.m16n8k16.row.col.f32.f16.f16.f32 "
                    "{%0,%1,%2,%3},{%4,%5,%6,%7},{%8,%9},{%0,%1,%2,%3};"
                    : "+f"(d[0][0]),"+f"(d[0][1]),"+f"(d[0][2]),"+f"(d[0][3])
                    : "r"(a0),"r"(a1),"r"(a2),"r"(a3),"r"(b0),"r"(b1));
                asm volatile("mma.sync.aligned.m16n8k16.row.col.f32.f16.f16.f32 "
                    "{%0,%1,%2,%3},{%4,%5,%6,%7},{%8,%9},{%0,%1,%2,%3};"
                    : "+f"(d[1][0]),"+f"(d[1][1]),"+f"(d[1][2]),"+f"(d[1][3])
                    : "r"(a0),"r"(a1),"r"(a2),"r"(a3),"r"(b2),"r"(b3));
            }
        }

        #pragma unroll
        for (int nt = 0; nt < 2; ++nt) {
            int oc = oc0 + nt*8 + tig*2;
            int pr = px0 + gid;
            so[pr*SO_PITCH + oc]         = d[nt][0];
            so[pr*SO_PITCH + oc + 1]     = d[nt][1];
            so[(pr+8)*SO_PITCH + oc]     = d[nt][2];
            so[(pr+8)*SO_PITCH + oc + 1] = d[nt][3];
        }
        __syncthreads();

        for (int i = t; i < 18*64; i += 256) {
            int oc = i >> 6, px = i & 63;
            float cv = tanhf(so[px*SO_PITCH + oc] + ob[oc]);
            int idx = ((b*MH + oc)*HH + h)*WW + w0 + px;
            float u  = g_update[idx];
            float p  = pre[idx];
            float mn = 0.5f*(mean[idx] + p);
            out_off[idx]  = p*(1.f - u) + cv*u + mn;
            out_mean[idx] = mn;
        }
        __syncthreads();
    }
}

// ================= k_warp: deformable warp + regroup conv via HMMA =================
#define KP 584
#define W_SW_OFF 0
#define W_SV_OFF (64*KP*2)
#define W_WT_OFF (W_SV_OFF + 64*KP*2)
#define W_AD_OFF (W_WT_OFF + 576*16)
#define W_SMEMB (W_AD_OFF + 576*16)

__global__ void __launch_bounds__(256, 1) k_warp(
    const float* __restrict__ off, const float* __restrict__ Wc,
    float* __restrict__ out)
{
    extern __shared__ char shb[];
    __half* sW  = reinterpret_cast<__half*>(shb + W_SW_OFF);
    __half* sv  = reinterpret_cast<__half*>(shb + W_SV_OFF);
    float4* wts = reinterpret_cast<float4*>(shb + W_WT_OFF);
    int4*   ads = reinterpret_cast<int4*>(shb + W_AD_OFF);
    float*  so  = reinterpret_cast<float*>(shb + W_WT_OFF);

    int t = threadIdx.x;
    int lane = t & 31, warp = t >> 5;

    for (int i = t; i < 64*576; i += 256) {
        int co = i / 576, r = i % 576;
        int ci = r / 9, n = r % 9;
        sW[co*KP + n*64 + ci] = __float2half_rn(Wc[i]);
    }
    __syncthreads();

    int gid = lane >> 2, tig = lane & 3;
    int px0 = (warp >> 1) * 16;
    int co0 = (warp & 1) * 32;
    uint32_t aAddr = smaddr(sv) + (((px0 + (lane & 15))*KP + (lane >> 4)*8) << 1);
    uint32_t bAddr0 = smaddr(sW) + (((co0 + (lane & 7) + (lane >> 4)*8)*KP
                                    + ((lane >> 3) & 1)*8) << 1);
    uint32_t bAddr1 = bAddr0 + 16*KP*2;

    int g = lane >> 3;
    int c = lane & 7;

    for (int tile = blockIdx.x; tile < BB*HH*2; tile += gridDim.x) {
        int b = tile >> 8;
        int rem = tile & 255;
        int h  = rem >> 1;
        int w0 = (rem & 1) << 6;
        const __half* xh = g_xTh + b*130*130*64;

        for (int item = t; item < 576; item += 256) {
            int n = item >> 6, px = item & 63;
            int wc = w0 + px;
            float pnx = (float)(n/3 - 1), pny = (float)(n%3 - 1);
            float ox = __ldg(off + ((b*MH + n    )*HH + h)*WW + wc);
            float oy = __ldg(off + ((b*MH + 9 + n)*HH + h)*WW + wc);
            float mm = g_m[((b*NN + n)*HH + h)*WW + wc];
            float px_ = (float)(h + 1) + pnx + ox;
            float py_ = (float)(wc + 1) + pny + oy;
            float fx = floorf(px_), fy = floorf(py_);
            float qxl = fminf(fmaxf(fx,       0.f), 129.f);
            float qxr = fminf(fmaxf(fx + 1.f, 0.f), 129.f);
            float qyl = fminf(fmaxf(fy,       0.f), 129.f);
            float qyr = fminf(fmaxf(fy + 1.f, 0.f), 129.f);
            float pxc = fminf(fmaxf(px_, 0.f), 129.f);
            float pyc = fminf(fmaxf(py_, 0.f), 129.f);
            float gx_l = 1.f + (qxl - pxc);
            float gx_r = 1.f - (qxr - pxc);
            float gy_l = 1.f + (qyl - pyc);
            float gy_r = 1.f - (qyr - pyc);
            int ixl = (int)qxl, ixr = (int)qxr, iyl = (int)qyl, iyr = (int)qyr;
            wts[item] = make_float4(gx_l*gy_l*mm, gx_r*gy_r*mm,
                                    gx_l*gy_r*mm, gx_r*gy_l*mm);
            ads[item] = make_int4(ixl*130 + iyl, ixr*130 + iyr,
                                  ixl*130 + iyr, ixr*130 + iyl);
        }
        __syncthreads();

        #pragma unroll 2
        for (int p = 0; p < 18; ++p) {
            int item = p*32 + warp*4 + g;
            int n = item >> 6, px = item & 63;
            float4 wt = wts[item];
            int4   ad = ads[item];
            uint4 rLT = *reinterpret_cast<const uint4*>(xh + ad.x*64 + c*8);
            uint4 rRB = *reinterpret_cast<const uint4*>(xh + ad.y*64 + c*8);
            uint4 rLB = *reinterpret_cast<const uint4*>(xh + ad.z*64 + c*8);
            uint4 rRT = *reinterpret_cast<const uint4*>(xh + ad.w*64 + c*8);
            ull dLT = dup2(wt.x), dRB = dup2(wt.y), dLB = dup2(wt.z), dRT = dup2(wt.w);
            uint32_t outh[4];
            const uint32_t* hLT = &rLT.x;
            const uint32_t* hRB = &rRB.x;
            const uint32_t* hLB = &rLB.x;
            const uint32_t* hRT = &rRT.x;
            #pragma unroll
            for (int q = 0; q < 4; ++q) {
                float2 fLT = __half22float2(*reinterpret_cast<const __half2*>(hLT + q));
                float2 fRB = __half22float2(*reinterpret_cast<const __half2*>(hRB + q));
                float2 fLB = __half22float2(*reinterpret_cast<const __half2*>(hLB + q));
                float2 fRT = __half22float2(*reinterpret_cast<const __half2*>(hRT + q));
                ull v;
                asm("mov.b64 %0,{%1,%2};" : "=l"(v) : "f"(fLT.x), "f"(fLT.y));
                v = fmul2(dLT, v);
                ull u2;
                asm("mov.b64 %0,{%1,%2};" : "=l"(u2) : "f"(fRB.x), "f"(fRB.y));
                v = ffma2(dRB, u2, v);
                asm("mov.b64 %0,{%1,%2};" : "=l"(u2) : "f"(fLB.x), "f"(fLB.y));
                v = ffma2(dLB, u2, v);
                asm("mov.b64 %0,{%1,%2};" : "=l"(u2) : "f"(fRT.x), "f"(fRT.y));
                v = ffma2(dRT, u2, v);
                float lo, hi;
                unpack2(v, lo, hi);
                __half2 hh = __floats2half2_rn(lo, hi);
                outh[q] = *reinterpret_cast<uint32_t*>(&hh);
            }
            *reinterpret_cast<uint4*>(sv + px*KP + n*64 + c*8) =
                make_uint4(outh[0], outh[1], outh[2], outh[3]);
        }
        __syncthreads();

        float d[4][4];
        #pragma unroll
        for (int i = 0; i < 4; ++i)
            #pragma unroll
            for (int j = 0; j < 4; ++j) d[i][j] = 0.f;

        #pragma unroll 4
        for (int ks = 0; ks < 36; ++ks) {
            uint32_t a0, a1, a2, a3, b0, b1, b2, b3, b4, b5, b6, b7;
            asm volatile("ldmatrix.sync.aligned.m8n8.x4.shared.b16 {%0,%1,%2,%3},[%4];"
                : "=r"(a0), "=r"(a1), "=r"(a2), "=r"(a3) : "r"(aAddr + ks*32));
            asm volatile("ldmatrix.sync.aligned.m8n8.x4.shared.b16 {%0,%1,%2,%3},[%4];"
                : "=r"(b0), "=r"(b1), "=r"(b2), "=r"(b3) : "r"(bAddr0 + ks*32));
            asm volatile("ldmatrix.sync.aligned.m8n8.x4.shared.b16 {%0,%1,%2,%3},[%4];"
                : "=r"(b4), "=r"(b5), "=r"(b6), "=r"(b7) : "r"(bAddr1 + ks*32));
            asm volatile("mma.sync.aligned.m16n8k16.row.col.f32.f16.f16.f32 "
                "{%0,%1,%2,%3},{%4,%5,%6,%7},{%8,%9},{%0,%1,%2,%3};"
                : "+f"(d[0][0]), "+f"(d[0][1]), "+f"(d[0][2]), "+f"(d[0][3])
                : "r"(a0), "r"(a1), "r"(a2), "r"(a3), "r"(b0), "r"(b1));
            asm volatile("mma.sync.aligned.m16n8k16.row.col.f32.f16.f16.f32 "
                "{%0,%1,%2,%3},{%4,%5,%6,%7},{%8,%9},{%0,%1,%2,%3};"
                : "+f"(d[1][0]), "+f"(d[1][1]), "+f"(d[1][2]), "+f"(d[1][3])
                : "r"(a0), "r"(a1), "r"(a2), "r"(a3), "r"(b2), "r"(b3));
            asm volatile("mma.sync.aligned.m16n8k16.row.col.f32.f16.f16.f32 "
                "{%0,%1,%2,%3},{%4,%5,%6,%7},{%8,%9},{%0,%1,%2,%3};"
                : "+f"(d[2][0]), "+f"(d[2][1]), "+f"(d[2][2]), "+f"(d[2][3])
                : "r"(a0), "r"(a1), "r"(a2), "r"(a3), "r"(b4), "r"(b5));
            asm volatile("mma.sync.aligned.m16n8k16.row.col.f32.f16.f16.f32 "
                "{%0,%1,%2,%3},{%4,%5,%6,%7},{%8,%9},{%0,%1,%2,%3};"
                : "+f"(d[3][0]), "+f"(d[3][1]), "+f"(d[3][2]), "+f"(d[3][3])
                : "r"(a0), "r"(a1), "r"(a2), "r"(a3), "r"(b6), "r"(b7));
        }
        __syncthreads();

        #pragma unroll
        for (int nt = 0; nt < 4; ++nt) {
            int cb = co0 + nt*8 + tig*2;
            int pr = px0 + gid;
            so[pr*69 + cb]         = d[nt][0];
            so[pr*69 + cb + 1]     = d[nt][1];
            so[(pr+8)*69 + cb]     = d[nt][2];
            so[(pr+8)*69 + cb + 1] = d[nt][3];
        }
        __syncthreads();

        for (int i = t; i < 4096; i += 256) {
            int co = i >> 6, px = i & 63;
            out[((b*CC + co)*HH + h)*WW + w0 + px] = so[px*69 + co];
        }
        __syncthreads();
    }
}

// ---------------- launch ----------------
extern "C" void kernel_launch(void* const* d_in, const int* in_sizes, int n_in,
                              void* d_out, int out_size)
{
    const float* x    = (const float*)d_in[0];
    const float* pre  = (const float*)d_in[1];
    const float* mean = (const float*)d_in[2];
    const float* uw   = (const float*)d_in[3];
    const float* ub   = (const float*)d_in[4];
    const float* rw   = (const float*)d_in[5];
    const float* rb   = (const float*)d_in[6];
    const float* ow   = (const float*)d_in[7];
    const float* ob   = (const float*)d_in[8];
    const float* ww   = (const float*)d_in[9];
    const float* wb   = (const float*)d_in[10];
    const float* wc   = (const float*)d_in[11];

    float* out_x    = (float*)d_out;
    float* out_off  = out_x + BB*CC*HH*WW;
    float* out_mean = out_off + BB*MH*HH*WW;

    cudaFuncSetAttribute(k1_gates, cudaFuncAttributeMaxDynamicSharedMemorySize, K1_SMEM);
    cudaFuncSetAttribute(k2_cand,  cudaFuncAttributeMaxDynamicSharedMemorySize, K2_SMEM);
    cudaFuncSetAttribute(k_warp,   cudaFuncAttributeMaxDynamicSharedMemorySize, W_SMEMB);

    k_zero<<<((int)(BB*130*130*CC*sizeof(__half)/16) + 255)/256, 256>>>();
    k_pad<<<dim3(4, 128, 4), dim3(32, 8)>>>(x);

    k1_gates<<<148, 256, K1_SMEM>>>(pre, uw, ub, rw, rb, ww, wb);
    k2_cand <<<148, 256, K2_SMEM>>>(pre, mean, ow, ob, out_off, out_mean);
    k_warp  <<<148, 256, W_SMEMB>>>(out_off, wc, out_x);
}

// round 10
// speedup vs baseline: 3.3900x; 1.0826x over previous
#include <cuda_runtime.h>
#include <cuda_fp16.h>
#include <math.h>
#include <stdint.h>

#define BB 4
#define CC 64
#define MH 18
#define HH 128
#define WW 128
#define NN 9
#define HWX (HH*WW)

typedef unsigned long long ull;

// ---------------- scratch (static __device__, no allocations) ----------------
__device__ float  g_update[BB*MH*HH*WW];
__device__ float  g_rgoff [BB*MH*HH*WW];
__device__ float  g_m     [BB*NN*HH*WW];
__device__ float  g_candx [BB*MH*HH*WW];          // conv_x part of cand (raw)
__device__ __half g_xTh   [BB*130*130*CC];        // padded NHWC x_t (fp16)

__device__ __forceinline__ float sigf(float x) { return 1.f/(1.f + __expf(-x)); }

// ---- f32x2 helpers ----
__device__ __forceinline__ ull ffma2(ull a, ull b, ull c) {
    ull d; asm("fma.rn.f32x2 %0,%1,%2,%3;" : "=l"(d) : "l"(a), "l"(b), "l"(c)); return d;
}
__device__ __forceinline__ ull fmul2(ull a, ull b) {
    ull d; asm("mul.rn.f32x2 %0,%1,%2;" : "=l"(d) : "l"(a), "l"(b)); return d;
}
__device__ __forceinline__ ull dup2(float v) {
    ull d; asm("mov.b64 %0,{%1,%1};" : "=l"(d) : "f"(v)); return d;
}
__device__ __forceinline__ void unpack2(ull p, float& lo, float& hi) {
    asm("mov.b64 {%0,%1},%2;" : "=f"(lo), "=f"(hi) : "l"(p));
}
__device__ __forceinline__ uint32_t smaddr(const void* p) {
    return (uint32_t)__cvta_generic_to_shared(p);
}

// ---------------- kernel: zero padded NHWC fp16 buffer ----------------
__global__ void k_zero() {
    int i = blockIdx.x * blockDim.x + threadIdx.x;
    const int n = (int)(BB*130*130*CC*sizeof(__half)/16);
    if (i < n) reinterpret_cast<uint4*>(g_xTh)[i] = make_uint4(0,0,0,0);
}

// ---------------- kernel: NCHW fp32 -> padded NHWC fp16 ----------------
__global__ void k_pad(const float* __restrict__ x) {
    __shared__ float sm[64][33];
    int jb = blockIdx.x, i0 = blockIdx.y, b = blockIdx.z;
    int tx = threadIdx.x, ty = threadIdx.y;
    int jcol = jb*32 + tx;
    for (int c = ty; c < 64; c += 8)
        sm[c][tx] = x[((b*CC + c)*HH + i0)*WW + jcol];
    __syncthreads();
    for (int jj = ty; jj < 32; jj += 8) {
        int base = ((b*130 + (i0+1))*130 + (jb*32 + jj + 1))*64;
        g_xTh[base + tx]      = __float2half_rn(sm[tx][jj]);
        g_xTh[base + 32 + tx] = __float2half_rn(sm[32 + tx][jj]);
    }
}

// ====== shared HMMA conv geometry ======
#define PIN 104
#define SIN_ROWS 198
#define SIN_B (SIN_ROWS*PIN*2)
#define WPP 872
#define SO_PITCH 68
#define SO_B (64*SO_PITCH*4)

// ================= K1: upd + rst + wg + cand_x convs via HMMA =================
#define W1_OC 64                      /* 63 used: 18 upd, 18 rst, 9 wg, 18 candx */
#define K1_SO_OFF (SIN_B + W1_OC*WPP*2)
#define K1_SMEM (K1_SO_OFF + SO_B)

__global__ void __launch_bounds__(256, 1) k1_gates(
    const float* __restrict__ pre,
    const float* __restrict__ uw, const float* __restrict__ ub,
    const float* __restrict__ rw, const float* __restrict__ rb,
    const float* __restrict__ ww, const float* __restrict__ wb,
    const float* __restrict__ ow)
{
    extern __shared__ char shb[];
    __half* sIn = reinterpret_cast<__half*>(shb);
    __half* Wp  = reinterpret_cast<__half*>(shb + SIN_B);
    float*  so  = reinterpret_cast<float*>(shb + K1_SO_OFF);

    int t = threadIdx.x;
    int lane = t & 31, warp = t >> 5;

    for (int i = t; i < SIN_ROWS*PIN/8; i += 256)
        reinterpret_cast<uint4*>(sIn)[i] = make_uint4(0,0,0,0);
    for (int i = t; i < W1_OC*WPP/8; i += 256)
        reinterpret_cast<uint4*>(Wp)[i] = make_uint4(0,0,0,0);
    __syncthreads();
    // repack weights -> Wp[oc][pos][ic]
    for (int i = t; i < 18*738; i += 256) {
        int oc = i / 738, r = i % 738, ic = r / 9, pos = r % 9;
        Wp[oc*WPP + pos*96 + ic]        = __float2half_rn(uw[i]);
        Wp[(18 + oc)*WPP + pos*96 + ic] = __float2half_rn(rw[i]);
    }
    for (int i = t; i < 9*576; i += 256) {
        int oc = i / 576, r = i % 576, ic = r / 9, pos = r % 9;
        Wp[(36 + oc)*WPP + pos*96 + ic] = __float2half_rn(ww[i]);
    }
    // cand conv, x channels only (ic < 64) -> oc 45..62
    for (int i = t; i < 18*576; i += 256) {
        int oc = i / 576, r = i % 576, ic = r / 9, pos = r % 9;
        Wp[(45 + oc)*WPP + pos*96 + ic] = __float2half_rn(ow[oc*738 + ic*9 + pos]);
    }
    __syncthreads();

    int wp = warp & 3, wo = warp >> 2;
    int px0 = wp * 16, oc0 = wo * 32;
    uint32_t aBase = smaddr(sIn) + (((px0 + (lane & 15))*PIN) + (lane >> 4)*8)*2;
    uint32_t bBase = smaddr(Wp) + ((oc0 + (lane & 7) + ((lane >> 4) & 1)*8)*WPP)*2
                     + ((lane >> 3) & 1)*16;
    int gid = lane >> 2, tig = lane & 3;

    for (int tile = blockIdx.x; tile < BB*HH*2; tile += gridDim.x) {
        int b = tile >> 8;
        int rem = tile & 255;
        int h  = rem >> 1;
        int w0 = (rem & 1) << 6;

        for (int i = t; i < 1584; i += 256) {
            int r = i >> 3, q = i & 7;
            int crow = r / 66, col = r % 66;
            const uint4* src = reinterpret_cast<const uint4*>(
                g_xTh + ((b*130 + h + crow)*130 + (w0 + col))*64) + q;
            reinterpret_cast<uint4*>(sIn + r*PIN)[q] = *src;
        }
        for (int i = t; i < 3564; i += 256) {
            int ch = i / 198, r = i % 198;
            int crow = r / 66, col = r % 66;
            int gh = h - 1 + crow, gw = w0 - 1 + col;
            float v = 0.f;
            if (gh >= 0 && gh < HH && gw >= 0 && gw < WW)
                v = pre[(b*MH + ch)*HWX + gh*WW + gw];
            sIn[r*PIN + 64 + ch] = __float2half_rn(v);
        }
        __syncthreads();

        float d[4][4];
        #pragma unroll
        for (int i = 0; i < 4; ++i)
            #pragma unroll
            for (int j = 0; j < 4; ++j) d[i][j] = 0.f;

        #pragma unroll 1
        for (int pos = 0; pos < 9; ++pos) {
            int ki = pos / 3, kj = pos % 3;
            uint32_t aPos = aBase + (ki*66 + kj)*PIN*2;
            uint32_t bPos = bBase + pos*96*2;
            #pragma unroll
            for (int kk = 0; kk < 6; ++kk) {
                uint32_t a0,a1,a2,a3, b0,b1,b2,b3, b4,b5,b6,b7;
                asm volatile("ldmatrix.sync.aligned.m8n8.x4.shared.b16 {%0,%1,%2,%3},[%4];"
                    : "=r"(a0),"=r"(a1),"=r"(a2),"=r"(a3) : "r"(aPos + kk*32));
                asm volatile("ldmatrix.sync.aligned.m8n8.x4.shared.b16 {%0,%1,%2,%3},[%4];"
                    : "=r"(b0),"=r"(b1),"=r"(b2),"=r"(b3) : "r"(bPos + kk*32));
                asm volatile("ldmatrix.sync.aligned.m8n8.x4.shared.b16 {%0,%1,%2,%3},[%4];"
                    : "=r"(b4),"=r"(b5),"=r"(b6),"=r"(b7) : "r"(bPos + 16*WPP*2 + kk*32));
                asm volatile("mma.sync.aligned.m16n8k16.row.col.f32.f16.f16.f32 "
                    "{%0,%1,%2,%3},{%4,%5,%6,%7},{%8,%9},{%0,%1,%2,%3};"
                    : "+f"(d[0][0]),"+f"(d[0][1]),"+f"(d[0][2]),"+f"(d[0][3])
                    : "r"(a0),"r"(a1),"r"(a2),"r"(a3),"r"(b0),"r"(b1));
                asm volatile("mma.sync.aligned.m16n8k16.row.col.f32.f16.f16.f32 "
                    "{%0,%1,%2,%3},{%4,%5,%6,%7},{%8,%9},{%0,%1,%2,%3};"
                    : "+f"(d[1][0]),"+f"(d[1][1]),"+f"(d[1][2]),"+f"(d[1][3])
                    : "r"(a0),"r"(a1),"r"(a2),"r"(a3),"r"(b2),"r"(b3));
                asm volatile("mma.sync.aligned.m16n8k16.row.col.f32.f16.f16.f32 "
                    "{%0,%1,%2,%3},{%4,%5,%6,%7},{%8,%9},{%0,%1,%2,%3};"
                    : "+f"(d[2][0]),"+f"(d[2][1]),"+f"(d[2][2]),"+f"(d[2][3])
                    : "r"(a0),"r"(a1),"r"(a2),"r"(a3),"r"(b4),"r"(b5));
                asm volatile("mma.sync.aligned.m16n8k16.row.col.f32.f16.f16.f32 "
                    "{%0,%1,%2,%3},{%4,%5,%6,%7},{%8,%9},{%0,%1,%2,%3};"
                    : "+f"(d[3][0]),"+f"(d[3][1]),"+f"(d[3][2]),"+f"(d[3][3])
                    : "r"(a0),"r"(a1),"r"(a2),"r"(a3),"r"(b6),"r"(b7));
            }
        }

        #pragma unroll
        for (int nt = 0; nt < 4; ++nt) {
            int oc = oc0 + nt*8 + tig*2;
            int pr = px0 + gid;
            so[pr*SO_PITCH + oc]         = d[nt][0];
            so[pr*SO_PITCH + oc + 1]     = d[nt][1];
            so[(pr+8)*SO_PITCH + oc]     = d[nt][2];
            so[(pr+8)*SO_PITCH + oc + 1] = d[nt][3];
        }
        __syncthreads();

        for (int i = t; i < 63*64; i += 256) {
            int oc = i >> 6, px = i & 63;
            float a = so[px*SO_PITCH + oc];
            if (oc < 18) {
                g_update[((b*MH + oc)*HH + h)*WW + w0 + px] = sigf(a + ub[oc]);
            } else if (oc < 36) {
                int o = oc - 18;
                int idx = ((b*MH + o)*HH + h)*WW + w0 + px;
                g_rgoff[idx] = pre[idx] * sigf(a + rb[o]);
            } else if (oc < 45) {
                int o = oc - 36;
                g_m[((b*NN + o)*HH + h)*WW + w0 + px] = sigf(a + wb[o]);
            } else {
                int o = oc - 45;
                g_candx[((b*MH + o)*HH + h)*WW + w0 + px] = a;
            }
        }
        __syncthreads();
    }
}

// ================= K2: cand_p conv (K=18->32) + GRU combine =================
#define PIN2 40
#define SIN2_B (SIN_ROWS*PIN2*2)      /* 15840 */
#define WPP2 296
#define W2_OC 32                      /* 18 used */
#define K2_SO_OFF (SIN2_B + W2_OC*WPP2*2)   /* 15840+18944=34784 */
#define K2_SMEM (K2_SO_OFF + SO_B)          /* 52192 */

__global__ void __launch_bounds__(256, 2) k2_cand(
    const float* __restrict__ pre, const float* __restrict__ mean,
    const float* __restrict__ ow, const float* __restrict__ ob,
    float* __restrict__ out_off, float* __restrict__ out_mean)
{
    extern __shared__ char shb[];
    __half* sIn = reinterpret_cast<__half*>(shb);
    __half* Wp  = reinterpret_cast<__half*>(shb + SIN2_B);
    float*  so  = reinterpret_cast<float*>(shb + K2_SO_OFF);

    int t = threadIdx.x;
    int lane = t & 31, warp = t >> 5;

    for (int i = t; i < SIN_ROWS*PIN2/8; i += 256)
        reinterpret_cast<uint4*>(sIn)[i] = make_uint4(0,0,0,0);
    for (int i = t; i < W2_OC*WPP2/8; i += 256)
        reinterpret_cast<uint4*>(Wp)[i] = make_uint4(0,0,0,0);
    __syncthreads();
    // cand conv, pre channels (ic 64..81) -> K' = ic-64
    for (int i = t; i < 18*162; i += 256) {
        int oc = i / 162, r = i % 162, icp = r / 9, pos = r % 9;
        Wp[oc*WPP2 + pos*32 + icp] = __float2half_rn(ow[oc*738 + (64 + icp)*9 + pos]);
    }
    __syncthreads();

    int wp = warp & 3, wo = warp >> 2;
    int px0 = wp * 16, oc0 = wo * 16;
    uint32_t aBase = smaddr(sIn) + (((px0 + (lane & 15))*PIN2) + (lane >> 4)*8)*2;
    uint32_t bBase = smaddr(Wp) + ((oc0 + (lane & 7) + ((lane >> 4) & 1)*8)*WPP2)*2
                     + ((lane >> 3) & 1)*16;
    int gid = lane >> 2, tig = lane & 3;

    for (int tile = blockIdx.x; tile < BB*HH*2; tile += gridDim.x) {
        int b = tile >> 8;
        int rem = tile & 255;
        int h  = rem >> 1;
        int w0 = (rem & 1) << 6;

        // stage rgoff channels (18), bounds-checked
        for (int i = t; i < 3564; i += 256) {
            int ch = i / 198, r = i % 198;
            int crow = r / 66, col = r % 66;
            int gh = h - 1 + crow, gw = w0 - 1 + col;
            float v = 0.f;
            if (gh >= 0 && gh < HH && gw >= 0 && gw < WW)
                v = g_rgoff[(b*MH + ch)*HWX + gh*WW + gw];
            sIn[r*PIN2 + ch] = __float2half_rn(v);
        }
        __syncthreads();

        float d[2][4];
        #pragma unroll
        for (int i = 0; i < 2; ++i)
            #pragma unroll
            for (int j = 0; j < 4; ++j) d[i][j] = 0.f;

        #pragma unroll 1
        for (int pos = 0; pos < 9; ++pos) {
            int ki = pos / 3, kj = pos % 3;
            uint32_t aPos = aBase + (ki*66 + kj)*PIN2*2;
            uint32_t bPos = bBase + pos*32*2;
            #pragma unroll
            for (int kk = 0; kk < 2; ++kk) {
                uint32_t a0,a1,a2,a3, b0,b1,b2,b3;
                asm volatile("ldmatrix.sync.aligned.m8n8.x4.shared.b16 {%0,%1,%2,%3},[%4];"
                    : "=r"(a0),"=r"(a1),"=r"(a2),"=r"(a3) : "r"(aPos + kk*32));
                asm volatile("ldmatrix.sync.aligned.m8n8.x4.shared.b16 {%0,%1,%2,%3},[%4];"
                    : "=r"(b0),"=r"(b1),"=r"(b2),"=r"(b3) : "r"(bPos + kk*32));
                asm volatile("mma.sync.aligned.m16n8k16.row.col.f32.f16.f16.f32 "
                    "{%0,%1,%2,%3},{%4,%5,%6,%7},{%8,%9},{%0,%1,%2,%3};"
                    : "+f"(d[0][0]),"+f"(d[0][1]),"+f"(d[0][2]),"+f"(d[0][3])
                    : "r"(a0),"r"(a1),"r"(a2),"r"(a3),"r"(b0),"r"(b1));
                asm volatile("mma.sync.aligned.m16n8k16.row.col.f32.f16.f16.f32 "
                    "{%0,%1,%2,%3},{%4,%5,%6,%7},{%8,%9},{%0,%1,%2,%3};"
                    : "+f"(d[1][0]),"+f"(d[1][1]),"+f"(d[1][2]),"+f"(d[1][3])
                    : "r"(a0),"r"(a1),"r"(a2),"r"(a3),"r"(b2),"r"(b3));
            }
        }

        #pragma unroll
        for (int nt = 0; nt < 2; ++nt) {
            int oc = oc0 + nt*8 + tig*2;
            int pr = px0 + gid;
            so[pr*SO_PITCH + oc]         = d[nt][0];
            so[pr*SO_PITCH + oc + 1]     = d[nt][1];
            so[(pr+8)*SO_PITCH + oc]     = d[nt][2];
            so[(pr+8)*SO_PITCH + oc + 1] = d[nt][3];
        }
        __syncthreads();

        for (int i = t; i < 18*64; i += 256) {
            int oc = i >> 6, px = i & 63;
            int idx = ((b*MH + oc)*HH + h)*WW + w0 + px;
            float cv = tanhf(so[px*SO_PITCH + oc] + g_candx[idx] + ob[oc]);
            float u  = g_update[idx];
            float p  = pre[idx];
            float mn = 0.5f*(mean[idx] + p);
            out_off[idx]  = p*(1.f - u) + cv*u + mn;
            out_mean[idx] = mn;
        }
        __syncthreads();
    }
}

// ================= k_warp: deformable warp + regroup conv via HMMA =================
#define KP 584
#define W_SW_OFF 0
#define W_SV_OFF (64*KP*2)
#define W_WT_OFF (W_SV_OFF + 64*KP*2)
#define W_AD_OFF (W_WT_OFF + 576*16)
#define W_SMEMB (W_AD_OFF + 576*16)

__global__ void __launch_bounds__(256, 1) k_warp(
    const float* __restrict__ off, const float* __restrict__ Wc,
    float* __restrict__ out)
{
    extern __shared__ char shb[];
    __half* sW  = reinterpret_cast<__half*>(shb + W_SW_OFF);
    __half* sv  = reinterpret_cast<__half*>(shb + W_SV_OFF);
    float4* wts = reinterpret_cast<float4*>(shb + W_WT_OFF);
    int4*   ads = reinterpret_cast<int4*>(shb + W_AD_OFF);
    float*  so  = reinterpret_cast<float*>(shb + W_WT_OFF);

    int t = threadIdx.x;
    int lane = t & 31, warp = t >> 5;

    for (int i = t; i < 64*576; i += 256) {
        int co = i / 576, r = i % 576;
        int ci = r / 9, n = r % 9;
        sW[co*KP + n*64 + ci] = __float2half_rn(Wc[i]);
    }
    __syncthreads();

    int gid = lane >> 2, tig = lane & 3;
    int px0 = (warp >> 1) * 16;
    int co0 = (warp & 1) * 32;
    uint32_t aAddr = smaddr(sv) + (((px0 + (lane & 15))*KP + (lane >> 4)*8) << 1);
    uint32_t bAddr0 = smaddr(sW) + (((co0 + (lane & 7) + (lane >> 4)*8)*KP
                                    + ((lane >> 3) & 1)*8) << 1);
    uint32_t bAddr1 = bAddr0 + 16*KP*2;

    int g = lane >> 3;
    int c = lane & 7;

    for (int tile = blockIdx.x; tile < BB*HH*2; tile += gridDim.x) {
        int b = tile >> 8;
        int rem = tile & 255;
        int h  = rem >> 1;
        int w0 = (rem & 1) << 6;
        const __half* xh = g_xTh + b*130*130*64;

        for (int item = t; item < 576; item += 256) {
            int n = item >> 6, px = item & 63;
            int wc = w0 + px;
            float pnx = (float)(n/3 - 1), pny = (float)(n%3 - 1);
            float ox = __ldg(off + ((b*MH + n    )*HH + h)*WW + wc);
            float oy = __ldg(off + ((b*MH + 9 + n)*HH + h)*WW + wc);
            float mm = g_m[((b*NN + n)*HH + h)*WW + wc];
            float px_ = (float)(h + 1) + pnx + ox;
            float py_ = (float)(wc + 1) + pny + oy;
            float fx = floorf(px_), fy = floorf(py_);
            float qxl = fminf(fmaxf(fx,       0.f), 129.f);
            float qxr = fminf(fmaxf(fx + 1.f, 0.f), 129.f);
            float qyl = fminf(fmaxf(fy,       0.f), 129.f);
            float qyr = fminf(fmaxf(fy + 1.f, 0.f), 129.f);
            float pxc = fminf(fmaxf(px_, 0.f), 129.f);
            float pyc = fminf(fmaxf(py_, 0.f), 129.f);
            float gx_l = 1.f + (qxl - pxc);
            float gx_r = 1.f - (qxr - pxc);
            float gy_l = 1.f + (qyl - pyc);
            float gy_r = 1.f - (qyr - pyc);
            int ixl = (int)qxl, ixr = (int)qxr, iyl = (int)qyl, iyr = (int)qyr;
            wts[item] = make_float4(gx_l*gy_l*mm, gx_r*gy_r*mm,
                                    gx_l*gy_r*mm, gx_r*gy_l*mm);
            ads[item] = make_int4(ixl*130 + iyl, ixr*130 + iyr,
                                  ixl*130 + iyr, ixr*130 + iyl);
        }
        __syncthreads();

        #pragma unroll 2
        for (int p = 0; p < 18; ++p) {
            int item = p*32 + warp*4 + g;
            int n = item >> 6, px = item & 63;
            float4 wt = wts[item];
            int4   ad = ads[item];
            uint4 rLT = *reinterpret_cast<const uint4*>(xh + ad.x*64 + c*8);
            uint4 rRB = *reinterpret_cast<const uint4*>(xh + ad.y*64 + c*8);
            uint4 rLB = *reinterpret_cast<const uint4*>(xh + ad.z*64 + c*8);
            uint4 rRT = *reinterpret_cast<const uint4*>(xh + ad.w*64 + c*8);
            ull dLT = dup2(wt.x), dRB = dup2(wt.y), dLB = dup2(wt.z), dRT = dup2(wt.w);
            uint32_t outh[4];
            const uint32_t* hLT = &rLT.x;
            const uint32_t* hRB = &rRB.x;
            const uint32_t* hLB = &rLB.x;
            const uint32_t* hRT = &rRT.x;
            #pragma unroll
            for (int q = 0; q < 4; ++q) {
                float2 fLT = __half22float2(*reinterpret_cast<const __half2*>(hLT + q));
                float2 fRB = __half22float2(*reinterpret_cast<const __half2*>(hRB + q));
                float2 fLB = __half22float2(*reinterpret_cast<const __half2*>(hLB + q));
                float2 fRT = __half22float2(*reinterpret_cast<const __half2*>(hRT + q));
                ull v;
                asm("mov.b64 %0,{%1,%2};" : "=l"(v) : "f"(fLT.x), "f"(fLT.y));
                v = fmul2(dLT, v);
                ull u2;
                asm("mov.b64 %0,{%1,%2};" : "=l"(u2) : "f"(fRB.x), "f"(fRB.y));
                v = ffma2(dRB, u2, v);
                asm("mov.b64 %0,{%1,%2};" : "=l"(u2) : "f"(fLB.x), "f"(fLB.y));
                v = ffma2(dLB, u2, v);
                asm("mov.b64 %0,{%1,%2};" : "=l"(u2) : "f"(fRT.x), "f"(fRT.y));
                v = ffma2(dRT, u2, v);
                float lo, hi;
                unpack2(v, lo, hi);
                __half2 hh = __floats2half2_rn(lo, hi);
                outh[q] = *reinterpret_cast<uint32_t*>(&hh);
            }
            *reinterpret_cast<uint4*>(sv + px*KP + n*64 + c*8) =
                make_uint4(outh[0], outh[1], outh[2], outh[3]);
        }
        __syncthreads();

        float d[4][4];
        #pragma unroll
        for (int i = 0; i < 4; ++i)
            #pragma unroll
            for (int j = 0; j < 4; ++j) d[i][j] = 0.f;

        #pragma unroll 4
        for (int ks = 0; ks < 36; ++ks) {
            uint32_t a0, a1, a2, a3, b0, b1, b2, b3, b4, b5, b6, b7;
            asm volatile("ldmatrix.sync.aligned.m8n8.x4.shared.b16 {%0,%1,%2,%3},[%4];"
                : "=r"(a0), "=r"(a1), "=r"(a2), "=r"(a3) : "r"(aAddr + ks*32));
            asm volatile("ldmatrix.sync.aligned.m8n8.x4.shared.b16 {%0,%1,%2,%3},[%4];"
                : "=r"(b0), "=r"(b1), "=r"(b2), "=r"(b3) : "r"(bAddr0 + ks*32));
            asm volatile("ldmatrix.sync.aligned.m8n8.x4.shared.b16 {%0,%1,%2,%3},[%4];"
                : "=r"(b4), "=r"(b5), "=r"(b6), "=r"(b7) : "r"(bAddr1 + ks*32));
            asm volatile("mma.sync.aligned.m16n8k16.row.col.f32.f16.f16.f32 "
                "{%0,%1,%2,%3},{%4,%5,%6,%7},{%8,%9},{%0,%1,%2,%3};"
                : "+f"(d[0][0]), "+f"(d[0][1]), "+f"(d[0][2]), "+f"(d[0][3])
                : "r"(a0), "r"(a1), "r"(a2), "r"(a3), "r"(b0), "r"(b1));
            asm volatile("mma.sync.aligned.m16n8k16.row.col.f32.f16.f16.f32 "
                "{%0,%1,%2,%3},{%4,%5,%6,%7},{%8,%9},{%0,%1,%2,%3};"
                : "+f"(d[1][0]), "+f"(d[1][1]), "+f"(d[1][2]), "+f"(d[1][3])
                : "r"(a0), "r"(a1), "r"(a2), "r"(a3), "r"(b2), "r"(b3));
            asm volatile("mma.sync.aligned.m16n8k16.row.col.f32.f16.f16.f32 "
                "{%0,%1,%2,%3},{%4,%5,%6,%7},{%8,%9},{%0,%1,%2,%3};"
                : "+f"(d[2][0]), "+f"(d[2][1]), "+f"(d[2][2]), "+f"(d[2][3])
                : "r"(a0), "r"(a1), "r"(a2), "r"(a3), "r"(b4), "r"(b5));
            asm volatile("mma.sync.aligned.m16n8k16.row.col.f32.f16.f16.f32 "
                "{%0,%1,%2,%3},{%4,%5,%6,%7},{%8,%9},{%0,%1,%2,%3};"
                : "+f"(d[3][0]), "+f"(d[3][1]), "+f"(d[3][2]), "+f"(d[3][3])
                : "r"(a0), "r"(a1), "r"(a2), "r"(a3), "r"(b6), "r"(b7));
        }
        __syncthreads();

        #pragma unroll
        for (int nt = 0; nt < 4; ++nt) {
            int cb = co0 + nt*8 + tig*2;
            int pr = px0 + gid;
            so[pr*69 + cb]         = d[nt][0];
            so[pr*69 + cb + 1]     = d[nt][1];
            so[(pr+8)*69 + cb]     = d[nt][2];
            so[(pr+8)*69 + cb + 1] = d[nt][3];
        }
        __syncthreads();

        for (int i = t; i < 4096; i += 256) {
            int co = i >> 6, px = i & 63;
            out[((b*CC + co)*HH + h)*WW + w0 + px] = so[px*69 + co];
        }
        __syncthreads();
    }
}

// ---------------- launch ----------------
extern "C" void kernel_launch(void* const* d_in, const int* in_sizes, int n_in,
                              void* d_out, int out_size)
{
    const float* x    = (const float*)d_in[0];
    const float* pre  = (const float*)d_in[1];
    const float* mean = (const float*)d_in[2];
    const float* uw   = (const float*)d_in[3];
    const float* ub   = (const float*)d_in[4];
    const float* rw   = (const float*)d_in[5];
    const float* rb   = (const float*)d_in[6];
    const float* ow   = (const float*)d_in[7];
    const float* ob   = (const float*)d_in[8];
    const float* ww   = (const float*)d_in[9];
    const float* wb   = (const float*)d_in[10];
    const float* wc   = (const float*)d_in[11];

    float* out_x    = (float*)d_out;
    float* out_off  = out_x + BB*CC*HH*WW;
    float* out_mean = out_off + BB*MH*HH*WW;

    cudaFuncSetAttribute(k1_gates, cudaFuncAttributeMaxDynamicSharedMemorySize, K1_SMEM);
    cudaFuncSetAttribute(k2_cand,  cudaFuncAttributeMaxDynamicSharedMemorySize, K2_SMEM);
    cudaFuncSetAttribute(k_warp,   cudaFuncAttributeMaxDynamicSharedMemorySize, W_SMEMB);

    k_zero<<<((int)(BB*130*130*CC*sizeof(__half)/16) + 255)/256, 256>>>();
    k_pad<<<dim3(4, 128, 4), dim3(32, 8)>>>(x);

    k1_gates<<<148, 256, K1_SMEM>>>(pre, uw, ub, rw, rb, ww, wb, ow);
    k2_cand <<<296, 256, K2_SMEM>>>(pre, mean, ow, ob, out_off, out_mean);
    k_warp  <<<148, 256, W_SMEMB>>>(out_off, wc, out_x);
}

// round 11
// speedup vs baseline: 3.7518x; 1.1067x over previous
#include <cuda_runtime.h>
#include <cuda_fp16.h>
#include <math.h>
#include <stdint.h>

#define BB 4
#define CC 64
#define MH 18
#define HH 128
#define WW 128
#define NN 9
#define HWX (HH*WW)

typedef unsigned long long ull;

// ---------------- scratch (static __device__, no allocations) ----------------
__device__ float  g_update[BB*MH*HH*WW];
__device__ float  g_rgoff [BB*MH*HH*WW];
__device__ float  g_m     [BB*NN*HH*WW];
__device__ float  g_candx [BB*MH*HH*WW];          // conv_x part of cand (raw)
__device__ __half g_xTh   [BB*130*130*CC];        // padded NHWC x_t (fp16)

__device__ __forceinline__ float sigf(float x) { return 1.f/(1.f + __expf(-x)); }

// ---- f32x2 helpers ----
__device__ __forceinline__ ull ffma2(ull a, ull b, ull c) {
    ull d; asm("fma.rn.f32x2 %0,%1,%2,%3;" : "=l"(d) : "l"(a), "l"(b), "l"(c)); return d;
}
__device__ __forceinline__ ull fmul2(ull a, ull b) {
    ull d; asm("mul.rn.f32x2 %0,%1,%2;" : "=l"(d) : "l"(a), "l"(b)); return d;
}
__device__ __forceinline__ ull dup2(float v) {
    ull d; asm("mov.b64 %0,{%1,%1};" : "=l"(d) : "f"(v)); return d;
}
__device__ __forceinline__ void unpack2(ull p, float& lo, float& hi) {
    asm("mov.b64 {%0,%1},%2;" : "=f"(lo), "=f"(hi) : "l"(p));
}
__device__ __forceinline__ uint32_t smaddr(const void* p) {
    return (uint32_t)__cvta_generic_to_shared(p);
}

// ---------------- kernel: zero ONLY the pad border of g_xTh ----------------
// per batch: row0 (1040 uint4) + row129 (1040) + col0 rows1-128 (1024) + col129 (1024) = 4128
__global__ void k_border() {
    int i = blockIdx.x * blockDim.x + threadIdx.x;
    if (i >= BB*4128) return;
    int b = i / 4128, r = i % 4128;
    uint4* base = reinterpret_cast<uint4*>(g_xTh + (size_t)b*130*130*64);
    uint4 z = make_uint4(0,0,0,0);
    if (r < 1040) {
        base[r] = z;                               // row 0
    } else if (r < 2080) {
        base[129*1040 + (r - 1040)] = z;           // row 129
    } else if (r < 3104) {
        int rr = r - 2080;                         // col 0, rows 1..128
        base[(1 + (rr >> 3))*1040 + (rr & 7)] = z;
    } else {
        int rr = r - 3104;                         // col 129, rows 1..128
        base[(1 + (rr >> 3))*1040 + 129*8 + (rr & 7)] = z;
    }
}

// ---------------- kernel: NCHW fp32 -> padded NHWC fp16 (interior) ----------------
__global__ void k_pad(const float* __restrict__ x) {
    __shared__ float sm[64][33];
    int jb = blockIdx.x, i0 = blockIdx.y, b = blockIdx.z;
    int tx = threadIdx.x, ty = threadIdx.y;
    int jcol = jb*32 + tx;
    for (int c = ty; c < 64; c += 8)
        sm[c][tx] = x[((b*CC + c)*HH + i0)*WW + jcol];
    __syncthreads();
    for (int jj = ty; jj < 32; jj += 8) {
        int base = ((b*130 + (i0+1))*130 + (jb*32 + jj + 1))*64;
        g_xTh[base + tx]      = __float2half_rn(sm[tx][jj]);
        g_xTh[base + 32 + tx] = __float2half_rn(sm[32 + tx][jj]);
    }
}

// ====== shared HMMA conv geometry ======
#define PIN 104
#define SIN_ROWS 198
#define SIN_B (SIN_ROWS*PIN*2)
#define WPP 872
#define SO_PITCH 68
#define SO_B (64*SO_PITCH*4)

// ================= K1: upd + rst + wg + cand_x convs via HMMA =================
#define W1_OC 64                      /* 63 used */
#define K1_SO_OFF (SIN_B + W1_OC*WPP*2)
#define K1_SMEM (K1_SO_OFF + SO_B)

__global__ void __launch_bounds__(256, 1) k1_gates(
    const float* __restrict__ pre,
    const float* __restrict__ uw, const float* __restrict__ ub,
    const float* __restrict__ rw, const float* __restrict__ rb,
    const float* __restrict__ ww, const float* __restrict__ wb,
    const float* __restrict__ ow)
{
    extern __shared__ char shb[];
    __half* sIn = reinterpret_cast<__half*>(shb);
    __half* Wp  = reinterpret_cast<__half*>(shb + SIN_B);
    float*  so  = reinterpret_cast<float*>(shb + K1_SO_OFF);

    int t = threadIdx.x;
    int lane = t & 31, warp = t >> 5;

    for (int i = t; i < SIN_ROWS*PIN/8; i += 256)
        reinterpret_cast<uint4*>(sIn)[i] = make_uint4(0,0,0,0);
    for (int i = t; i < W1_OC*WPP/8; i += 256)
        reinterpret_cast<uint4*>(Wp)[i] = make_uint4(0,0,0,0);
    __syncthreads();
    for (int i = t; i < 18*738; i += 256) {
        int oc = i / 738, r = i % 738, ic = r / 9, pos = r % 9;
        Wp[oc*WPP + pos*96 + ic]        = __float2half_rn(uw[i]);
        Wp[(18 + oc)*WPP + pos*96 + ic] = __float2half_rn(rw[i]);
    }
    for (int i = t; i < 9*576; i += 256) {
        int oc = i / 576, r = i % 576, ic = r / 9, pos = r % 9;
        Wp[(36 + oc)*WPP + pos*96 + ic] = __float2half_rn(ww[i]);
    }
    for (int i = t; i < 18*576; i += 256) {
        int oc = i / 576, r = i % 576, ic = r / 9, pos = r % 9;
        Wp[(45 + oc)*WPP + pos*96 + ic] = __float2half_rn(ow[oc*738 + ic*9 + pos]);
    }
    __syncthreads();

    // ---- precompute staging slot descriptors (tile-invariant) ----
    int xsrc[7], xdst[7];
    #pragma unroll
    for (int s = 0; s < 7; ++s) {
        int e = t + s*256;
        if (e < 1584) {
            int r = e >> 3, q = e & 7;
            int crow = r / 66, col = r % 66;
            xsrc[s] = (crow*130 + col)*64 + q*8;
            xdst[s] = r*PIN + q*8;
        } else { xsrc[s] = -1; xdst[s] = 0; }
    }
    int pofs[14], pcrow[14], pcol[14], pdst[14];
    #pragma unroll
    for (int s = 0; s < 14; ++s) {
        int e = t + s*256;
        if (e < 3564) {
            int ch = e / 198, r = e % 198;
            int crow = r / 66, col = r % 66;
            pofs[s]  = ch*HWX + crow*WW + col;
            pcrow[s] = crow; pcol[s] = col;
            pdst[s]  = r*PIN + 64 + ch;
        } else { pofs[s] = -1; pcrow[s] = 0; pcol[s] = 0; pdst[s] = 0; }
    }

    int wp = warp & 3, wo = warp >> 2;
    int px0 = wp * 16, oc0 = wo * 32;
    uint32_t aBase = smaddr(sIn) + (((px0 + (lane & 15))*PIN) + (lane >> 4)*8)*2;
    uint32_t bBase = smaddr(Wp) + ((oc0 + (lane & 7) + ((lane >> 4) & 1)*8)*WPP)*2
                     + ((lane >> 3) & 1)*16;
    int gid = lane >> 2, tig = lane & 3;

    for (int tile = blockIdx.x; tile < BB*HH*2; tile += gridDim.x) {
        int b = tile >> 8;
        int rem = tile & 255;
        int h  = rem >> 1;
        int w0 = (rem & 1) << 6;

        const __half* xbase = g_xTh + (size_t)(((b*130 + h)*130) + w0)*64;
        #pragma unroll
        for (int s = 0; s < 7; ++s)
            if (xsrc[s] >= 0)
                *reinterpret_cast<uint4*>(sIn + xdst[s]) =
                    *reinterpret_cast<const uint4*>(xbase + xsrc[s]);
        const float* pbase = pre + (size_t)b*MH*HWX + (h-1)*WW + (w0-1);
        #pragma unroll
        for (int s = 0; s < 14; ++s) {
            if (pofs[s] >= 0) {
                int gh = h - 1 + pcrow[s], gw = w0 - 1 + pcol[s];
                float v = 0.f;
                if ((unsigned)gh < HH && (unsigned)gw < WW)
                    v = __ldg(pbase + pofs[s]);
                sIn[pdst[s]] = __float2half_rn(v);
            }
        }
        __syncthreads();

        float d[4][4];
        #pragma unroll
        for (int i = 0; i < 4; ++i)
            #pragma unroll
            for (int j = 0; j < 4; ++j) d[i][j] = 0.f;

        #pragma unroll 1
        for (int pos = 0; pos < 9; ++pos) {
            int ki = pos / 3, kj = pos % 3;
            uint32_t aPos = aBase + (ki*66 + kj)*PIN*2;
            uint32_t bPos = bBase + pos*96*2;
            #pragma unroll
            for (int kk = 0; kk < 6; ++kk) {
                uint32_t a0,a1,a2,a3, b0,b1,b2,b3, b4,b5,b6,b7;
                asm volatile("ldmatrix.sync.aligned.m8n8.x4.shared.b16 {%0,%1,%2,%3},[%4];"
                    : "=r"(a0),"=r"(a1),"=r"(a2),"=r"(a3) : "r"(aPos + kk*32));
                asm volatile("ldmatrix.sync.aligned.m8n8.x4.shared.b16 {%0,%1,%2,%3},[%4];"
                    : "=r"(b0),"=r"(b1),"=r"(b2),"=r"(b3) : "r"(bPos + kk*32));
                asm volatile("ldmatrix.sync.aligned.m8n8.x4.shared.b16 {%0,%1,%2,%3},[%4];"
                    : "=r"(b4),"=r"(b5),"=r"(b6),"=r"(b7) : "r"(bPos + 16*WPP*2 + kk*32));
                asm volatile("mma.sync.aligned.m16n8k16.row.col.f32.f16.f16.f32 "
                    "{%0,%1,%2,%3},{%4,%5,%6,%7},{%8,%9},{%0,%1,%2,%3};"
                    : "+f"(d[0][0]),"+f"(d[0][1]),"+f"(d[0][2]),"+f"(d[0][3])
                    : "r"(a0),"r"(a1),"r"(a2),"r"(a3),"r"(b0),"r"(b1));
                asm volatile("mma.sync.aligned.m16n8k16.row.col.f32.f16.f16.f32 "
                    "{%0,%1,%2,%3},{%4,%5,%6,%7},{%8,%9},{%0,%1,%2,%3};"
                    : "+f"(d[1][0]),"+f"(d[1][1]),"+f"(d[1][2]),"+f"(d[1][3])
                    : "r"(a0),"r"(a1),"r"(a2),"r"(a3),"r"(b2),"r"(b3));
                asm volatile("mma.sync.aligned.m16n8k16.row.col.f32.f16.f16.f32 "
                    "{%0,%1,%2,%3},{%4,%5,%6,%7},{%8,%9},{%0,%1,%2,%3};"
                    : "+f"(d[2][0]),"+f"(d[2][1]),"+f"(d[2][2]),"+f"(d[2][3])
                    : "r"(a0),"r"(a1),"r"(a2),"r"(a3),"r"(b4),"r"(b5));
                asm volatile("mma.sync.aligned.m16n8k16.row.col.f32.f16.f16.f32 "
                    "{%0,%1,%2,%3},{%4,%5,%6,%7},{%8,%9},{%0,%1,%2,%3};"
                    : "+f"(d[3][0]),"+f"(d[3][1]),"+f"(d[3][2]),"+f"(d[3][3])
                    : "r"(a0),"r"(a1),"r"(a2),"r"(a3),"r"(b6),"r"(b7));
            }
        }

        #pragma unroll
        for (int nt = 0; nt < 4; ++nt) {
            int oc = oc0 + nt*8 + tig*2;
            int pr = px0 + gid;
            so[pr*SO_PITCH + oc]         = d[nt][0];
            so[pr*SO_PITCH + oc + 1]     = d[nt][1];
            so[(pr+8)*SO_PITCH + oc]     = d[nt][2];
            so[(pr+8)*SO_PITCH + oc + 1] = d[nt][3];
        }
        __syncthreads();

        for (int i = t; i < 63*64; i += 256) {
            int oc = i >> 6, px = i & 63;
            float a = so[px*SO_PITCH + oc];
            if (oc < 18) {
                g_update[((b*MH + oc)*HH + h)*WW + w0 + px] = sigf(a + ub[oc]);
            } else if (oc < 36) {
                int o = oc - 18;
                int idx = ((b*MH + o)*HH + h)*WW + w0 + px;
                g_rgoff[idx] = pre[idx] * sigf(a + rb[o]);
            } else if (oc < 45) {
                int o = oc - 36;
                g_m[((b*NN + o)*HH + h)*WW + w0 + px] = sigf(a + wb[o]);
            } else {
                int o = oc - 45;
                g_candx[((b*MH + o)*HH + h)*WW + w0 + px] = a;
            }
        }
        __syncthreads();
    }
}

// ================= K2: cand_p conv (K=18->32) + GRU combine =================
#define PIN2 40
#define SIN2_B (SIN_ROWS*PIN2*2)
#define WPP2 296
#define W2_OC 32
#define K2_SO_OFF (SIN2_B + W2_OC*WPP2*2)
#define K2_SMEM (K2_SO_OFF + SO_B)

__global__ void __launch_bounds__(256, 2) k2_cand(
    const float* __restrict__ pre, const float* __restrict__ mean,
    const float* __restrict__ ow, const float* __restrict__ ob,
    float* __restrict__ out_off, float* __restrict__ out_mean)
{
    extern __shared__ char shb[];
    __half* sIn = reinterpret_cast<__half*>(shb);
    __half* Wp  = reinterpret_cast<__half*>(shb + SIN2_B);
    float*  so  = reinterpret_cast<float*>(shb + K2_SO_OFF);

    int t = threadIdx.x;
    int lane = t & 31, warp = t >> 5;

    for (int i = t; i < SIN_ROWS*PIN2/8; i += 256)
        reinterpret_cast<uint4*>(sIn)[i] = make_uint4(0,0,0,0);
    for (int i = t; i < W2_OC*WPP2/8; i += 256)
        reinterpret_cast<uint4*>(Wp)[i] = make_uint4(0,0,0,0);
    __syncthreads();
    for (int i = t; i < 18*162; i += 256) {
        int oc = i / 162, r = i % 162, icp = r / 9, pos = r % 9;
        Wp[oc*WPP2 + pos*32 + icp] = __float2half_rn(ow[oc*738 + (64 + icp)*9 + pos]);
    }
    __syncthreads();

    // precompute staging slot descriptors (3564 items, 14 slots)
    int pofs[14], pcrow[14], pcol[14], pdst[14];
    #pragma unroll
    for (int s = 0; s < 14; ++s) {
        int e = t + s*256;
        if (e < 3564) {
            int ch = e / 198, r = e % 198;
            int crow = r / 66, col = r % 66;
            pofs[s]  = ch*HWX + crow*WW + col;
            pcrow[s] = crow; pcol[s] = col;
            pdst[s]  = r*PIN2 + ch;
        } else { pofs[s] = -1; pcrow[s] = 0; pcol[s] = 0; pdst[s] = 0; }
    }

    int wp = warp & 3, wo = warp >> 2;
    int px0 = wp * 16, oc0 = wo * 16;
    uint32_t aBase = smaddr(sIn) + (((px0 + (lane & 15))*PIN2) + (lane >> 4)*8)*2;
    uint32_t bBase = smaddr(Wp) + ((oc0 + (lane & 7) + ((lane >> 4) & 1)*8)*WPP2)*2
                     + ((lane >> 3) & 1)*16;
    int gid = lane >> 2, tig = lane & 3;

    for (int tile = blockIdx.x; tile < BB*HH*2; tile += gridDim.x) {
        int b = tile >> 8;
        int rem = tile & 255;
        int h  = rem >> 1;
        int w0 = (rem & 1) << 6;

        const float* pbase = g_rgoff + (size_t)b*MH*HWX + (h-1)*WW + (w0-1);
        #pragma unroll
        for (int s = 0; s < 14; ++s) {
            if (pofs[s] >= 0) {
                int gh = h - 1 + pcrow[s], gw = w0 - 1 + pcol[s];
                float v = 0.f;
                if ((unsigned)gh < HH && (unsigned)gw < WW)
                    v = __ldg(pbase + pofs[s]);
                sIn[pdst[s]] = __float2half_rn(v);
            }
        }
        __syncthreads();

        float d[2][4];
        #pragma unroll
        for (int i = 0; i < 2; ++i)
            #pragma unroll
            for (int j = 0; j < 4; ++j) d[i][j] = 0.f;

        #pragma unroll 1
        for (int pos = 0; pos < 9; ++pos) {
            int ki = pos / 3, kj = pos % 3;
            uint32_t aPos = aBase + (ki*66 + kj)*PIN2*2;
            uint32_t bPos = bBase + pos*32*2;
            #pragma unroll
            for (int kk = 0; kk < 2; ++kk) {
                uint32_t a0,a1,a2,a3, b0,b1,b2,b3;
                asm volatile("ldmatrix.sync.aligned.m8n8.x4.shared.b16 {%0,%1,%2,%3},[%4];"
                    : "=r"(a0),"=r"(a1),"=r"(a2),"=r"(a3) : "r"(aPos + kk*32));
                asm volatile("ldmatrix.sync.aligned.m8n8.x4.shared.b16 {%0,%1,%2,%3},[%4];"
                    : "=r"(b0),"=r"(b1),"=r"(b2),"=r"(b3) : "r"(bPos + kk*32));
                asm volatile("mma.sync.aligned.m16n8k16.row.col.f32.f16.f16.f32 "
                    "{%0,%1,%2,%3},{%4,%5,%6,%7},{%8,%9},{%0,%1,%2,%3};"
                    : "+f"(d[0][0]),"+f"(d[0][1]),"+f"(d[0][2]),"+f"(d[0][3])
                    : "r"(a0),"r"(a1),"r"(a2),"r"(a3),"r"(b0),"r"(b1));
                asm volatile("mma.sync.aligned.m16n8k16.row.col.f32.f16.f16.f32 "
                    "{%0,%1,%2,%3},{%4,%5,%6,%7},{%8,%9},{%0,%1,%2,%3};"
                    : "+f"(d[1][0]),"+f"(d[1][1]),"+f"(d[1][2]),"+f"(d[1][3])
                    : "r"(a0),"r"(a1),"r"(a2),"r"(a3),"r"(b2),"r"(b3));
            }
        }

        #pragma unroll
        for (int nt = 0; nt < 2; ++nt) {
            int oc = oc0 + nt*8 + tig*2;
            int pr = px0 + gid;
            so[pr*SO_PITCH + oc]         = d[nt][0];
            so[pr*SO_PITCH + oc + 1]     = d[nt][1];
            so[(pr+8)*SO_PITCH + oc]     = d[nt][2];
            so[(pr+8)*SO_PITCH + oc + 1] = d[nt][3];
        }
        __syncthreads();

        for (int i = t; i < 18*64; i += 256) {
            int oc = i >> 6, px = i & 63;
            int idx = ((b*MH + oc)*HH + h)*WW + w0 + px;
            float cv = tanhf(so[px*SO_PITCH + oc] + g_candx[idx] + ob[oc]);
            float u  = g_update[idx];
            float p  = pre[idx];
            float mn = 0.5f*(mean[idx] + p);
            out_off[idx]  = p*(1.f - u) + cv*u + mn;
            out_mean[idx] = mn;
        }
        __syncthreads();
    }
}

// ================= k_warp: deformable warp + regroup conv via HMMA =================
#define KP 584
#define W_SW_OFF 0
#define W_SV_OFF (64*KP*2)
#define W_WT_OFF (W_SV_OFF + 64*KP*2)
#define W_AD_OFF (W_WT_OFF + 576*16)
#define W_SMEMB (W_AD_OFF + 576*16)

__global__ void __launch_bounds__(256, 1) k_warp(
    const float* __restrict__ off, const float* __restrict__ Wc,
    float* __restrict__ out)
{
    extern __shared__ char shb[];
    __half* sW  = reinterpret_cast<__half*>(shb + W_SW_OFF);
    __half* sv  = reinterpret_cast<__half*>(shb + W_SV_OFF);
    float4* wts = reinterpret_cast<float4*>(shb + W_WT_OFF);
    int4*   ads = reinterpret_cast<int4*>(shb + W_AD_OFF);
    float*  so  = reinterpret_cast<float*>(shb + W_WT_OFF);

    int t = threadIdx.x;
    int lane = t & 31, warp = t >> 5;

    for (int i = t; i < 64*576; i += 256) {
        int co = i / 576, r = i % 576;
        int ci = r / 9, n = r % 9;
        sW[co*KP + n*64 + ci] = __float2half_rn(Wc[i]);
    }
    __syncthreads();

    int gid = lane >> 2, tig = lane & 3;
    int px0 = (warp >> 1) * 16;
    int co0 = (warp & 1) * 32;
    uint32_t aAddr = smaddr(sv) + (((px0 + (lane & 15))*KP + (lane >> 4)*8) << 1);
    uint32_t bAddr0 = smaddr(sW) + (((co0 + (lane & 7) + (lane >> 4)*8)*KP
                                    + ((lane >> 3) & 1)*8) << 1);
    uint32_t bAddr1 = bAddr0 + 16*KP*2;

    int g = lane >> 3;
    int c = lane & 7;

    for (int tile = blockIdx.x; tile < BB*HH*2; tile += gridDim.x) {
        int b = tile >> 8;
        int rem = tile & 255;
        int h  = rem >> 1;
        int w0 = (rem & 1) << 6;
        const __half* xh = g_xTh + (size_t)b*130*130*64;

        for (int item = t; item < 576; item += 256) {
            int n = item >> 6, px = item & 63;
            int wc = w0 + px;
            float pnx = (float)(n/3 - 1), pny = (float)(n%3 - 1);
            float ox = __ldg(off + ((b*MH + n    )*HH + h)*WW + wc);
            float oy = __ldg(off + ((b*MH + 9 + n)*HH + h)*WW + wc);
            float mm = g_m[((b*NN + n)*HH + h)*WW + wc];
            float px_ = (float)(h + 1) + pnx + ox;
            float py_ = (float)(wc + 1) + pny + oy;
            float fx = floorf(px_), fy = floorf(py_);
            float qxl = fminf(fmaxf(fx,       0.f), 129.f);
            float qxr = fminf(fmaxf(fx + 1.f, 0.f), 129.f);
            float qyl = fminf(fmaxf(fy,       0.f), 129.f);
            float qyr = fminf(fmaxf(fy + 1.f, 0.f), 129.f);
            float pxc = fminf(fmaxf(px_, 0.f), 129.f);
            float pyc = fminf(fmaxf(py_, 0.f), 129.f);
            float gx_l = 1.f + (qxl - pxc);
            float gx_r = 1.f - (qxr - pxc);
            float gy_l = 1.f + (qyl - pyc);
            float gy_r = 1.f - (qyr - pyc);
            int ixl = (int)qxl, ixr = (int)qxr, iyl = (int)qyl, iyr = (int)qyr;
            wts[item] = make_float4(gx_l*gy_l*mm, gx_r*gy_r*mm,
                                    gx_l*gy_r*mm, gx_r*gy_l*mm);
            ads[item] = make_int4(ixl*130 + iyl, ixr*130 + iyr,
                                  ixl*130 + iyr, ixr*130 + iyl);
        }
        __syncthreads();

        #pragma unroll 2
        for (int p = 0; p < 18; ++p) {
            int item = p*32 + warp*4 + g;
            int n = item >> 6, px = item & 63;
            float4 wt = wts[item];
            int4   ad = ads[item];
            uint4 rLT = *reinterpret_cast<const uint4*>(xh + ad.x*64 + c*8);
            uint4 rRB = *reinterpret_cast<const uint4*>(xh + ad.y*64 + c*8);
            uint4 rLB = *reinterpret_cast<const uint4*>(xh + ad.z*64 + c*8);
            uint4 rRT = *reinterpret_cast<const uint4*>(xh + ad.w*64 + c*8);
            ull dLT = dup2(wt.x), dRB = dup2(wt.y), dLB = dup2(wt.z), dRT = dup2(wt.w);
            uint32_t outh[4];
            const uint32_t* hLT = &rLT.x;
            const uint32_t* hRB = &rRB.x;
            const uint32_t* hLB = &rLB.x;
            const uint32_t* hRT = &rRT.x;
            #pragma unroll
            for (int q = 0; q < 4; ++q) {
                float2 fLT = __half22float2(*reinterpret_cast<const __half2*>(hLT + q));
                float2 fRB = __half22float2(*reinterpret_cast<const __half2*>(hRB + q));
                float2 fLB = __half22float2(*reinterpret_cast<const __half2*>(hLB + q));
                float2 fRT = __half22float2(*reinterpret_cast<const __half2*>(hRT + q));
                ull v;
                asm("mov.b64 %0,{%1,%2};" : "=l"(v) : "f"(fLT.x), "f"(fLT.y));
                v = fmul2(dLT, v);
                ull u2;
                asm("mov.b64 %0,{%1,%2};" : "=l"(u2) : "f"(fRB.x), "f"(fRB.y));
                v = ffma2(dRB, u2, v);
                asm("mov.b64 %0,{%1,%2};" : "=l"(u2) : "f"(fLB.x), "f"(fLB.y));
                v = ffma2(dLB, u2, v);
                asm("mov.b64 %0,{%1,%2};" : "=l"(u2) : "f"(fRT.x), "f"(fRT.y));
                v = ffma2(dRT, u2, v);
                float lo, hi;
                unpack2(v, lo, hi);
                __half2 hh = __floats2half2_rn(lo, hi);
                outh[q] = *reinterpret_cast<uint32_t*>(&hh);
            }
            *reinterpret_cast<uint4*>(sv + px*KP + n*64 + c*8) =
                make_uint4(outh[0], outh[1], outh[2], outh[3]);
        }
        __syncthreads();

        float d[4][4];
        #pragma unroll
        for (int i = 0; i < 4; ++i)
            #pragma unroll
            for (int j = 0; j < 4; ++j) d[i][j] = 0.f;

        #pragma unroll 4
        for (int ks = 0; ks < 36; ++ks) {
            uint32_t a0, a1, a2, a3, b0, b1, b2, b3, b4, b5, b6, b7;
            asm volatile("ldmatrix.sync.aligned.m8n8.x4.shared.b16 {%0,%1,%2,%3},[%4];"
                : "=r"(a0), "=r"(a1), "=r"(a2), "=r"(a3) : "r"(aAddr + ks*32));
            asm volatile("ldmatrix.sync.aligned.m8n8.x4.shared.b16 {%0,%1,%2,%3},[%4];"
                : "=r"(b0), "=r"(b1), "=r"(b2), "=r"(b3) : "r"(bAddr0 + ks*32));
            asm volatile("ldmatrix.sync.aligned.m8n8.x4.shared.b16 {%0,%1,%2,%3},[%4];"
                : "=r"(b4), "=r"(b5), "=r"(b6), "=r"(b7) : "r"(bAddr1 + ks*32));
            asm volatile("mma.sync.aligned.m16n8k16.row.col.f32.f16.f16.f32 "
                "{%0,%1,%2,%3},{%4,%5,%6,%7},{%8,%9},{%0,%1,%2,%3};"
                : "+f"(d[0][0]), "+f"(d[0][1]), "+f"(d[0][2]), "+f"(d[0][3])
                : "r"(a0), "r"(a1), "r"(a2), "r"(a3), "r"(b0), "r"(b1));
            asm volatile("mma.sync.aligned.m16n8k16.row.col.f32.f16.f16.f32 "
                "{%0,%1,%2,%3},{%4,%5,%6,%7},{%8,%9},{%0,%1,%2,%3};"
                : "+f"(d[1][0]), "+f"(d[1][1]), "+f"(d[1][2]), "+f"(d[1][3])
                : "r"(a0), "r"(a1), "r"(a2), "r"(a3), "r"(b2), "r"(b3));
            asm volatile("mma.sync.aligned.m16n8k16.row.col.f32.f16.f16.f32 "
                "{%0,%1,%2,%3},{%4,%5,%6,%7},{%8,%9},{%0,%1,%2,%3};"
                : "+f"(d[2][0]), "+f"(d[2][1]), "+f"(d[2][2]), "+f"(d[2][3])
                : "r"(a0), "r"(a1), "r"(a2), "r"(a3), "r"(b4), "r"(b5));
            asm volatile("mma.sync.aligned.m16n8k16.row.col.f32.f16.f16.f32 "
                "{%0,%1,%2,%3},{%4,%5,%6,%7},{%8,%9},{%0,%1,%2,%3};"
                : "+f"(d[3][0]), "+f"(d[3][1]), "+f"(d[3][2]), "+f"(d[3][3])
                : "r"(a0), "r"(a1), "r"(a2), "r"(a3), "r"(b6), "r"(b7));
        }
        __syncthreads();

        #pragma unroll
        for (int nt = 0; nt < 4; ++nt) {
            int cb = co0 + nt*8 + tig*2;
            int pr = px0 + gid;
            so[pr*69 + cb]         = d[nt][0];
            so[pr*69 + cb + 1]     = d[nt][1];
            so[(pr+8)*69 + cb]     = d[nt][2];
            so[(pr+8)*69 + cb + 1] = d[nt][3];
        }
        __syncthreads();

        for (int i = t; i < 4096; i += 256) {
            int co = i >> 6, px = i & 63;
            out[((b*CC + co)*HH + h)*WW + w0 + px] = so[px*69 + co];
        }
        __syncthreads();
    }
}

// ---------------- launch ----------------
extern "C" void kernel_launch(void* const* d_in, const int* in_sizes, int n_in,
                              void* d_out, int out_size)
{
    const float* x    = (const float*)d_in[0];
    const float* pre  = (const float*)d_in[1];
    const float* mean = (const float*)d_in[2];
    const float* uw   = (const float*)d_in[3];
    const float* ub   = (const float*)d_in[4];
    const float* rw   = (const float*)d_in[5];
    const float* rb   = (const float*)d_in[6];
    const float* ow   = (const float*)d_in[7];
    const float* ob   = (const float*)d_in[8];
    const float* ww   = (const float*)d_in[9];
    const float* wb   = (const float*)d_in[10];
    const float* wc   = (const float*)d_in[11];

    float* out_x    = (float*)d_out;
    float* out_off  = out_x + BB*CC*HH*WW;
    float* out_mean = out_off + BB*MH*HH*WW;

    cudaFuncSetAttribute(k1_gates, cudaFuncAttributeMaxDynamicSharedMemorySize, K1_SMEM);
    cudaFuncSetAttribute(k2_cand,  cudaFuncAttributeMaxDynamicSharedMemorySize, K2_SMEM);
    cudaFuncSetAttribute(k_warp,   cudaFuncAttributeMaxDynamicSharedMemorySize, W_SMEMB);

    k_border<<<(BB*4128 + 255)/256, 256>>>();
    k_pad<<<dim3(4, 128, 4), dim3(32, 8)>>>(x);

    k1_gates<<<148, 256, K1_SMEM>>>(pre, uw, ub, rw, rb, ww, wb, ow);
    k2_cand <<<296, 256, K2_SMEM>>>(pre, mean, ow, ob, out_off, out_mean);
    k_warp  <<<148, 256, W_SMEMB>>>(out_off, wc, out_x);
}

// round 12
// speedup vs baseline: 3.8125x; 1.0162x over previous
#include <cuda_runtime.h>
#include <cuda_fp16.h>
#include <math.h>
#include <stdint.h>

#define BB 4
#define CC 64
#define MH 18
#define HH 128
#define WW 128
#define NN 9
#define HWX (HH*WW)

typedef unsigned long long ull;

// ---------------- scratch (static __device__, no allocations) ----------------
__device__ float  g_update[BB*MH*HH*WW];
__device__ float  g_rgoff [BB*MH*HH*WW];
__device__ float  g_m     [BB*NN*HH*WW];
__device__ float  g_candx [BB*MH*HH*WW];          // conv_x part of cand (raw)
__device__ __half g_xTh   [BB*130*130*CC];        // padded NHWC x_t (fp16)

__device__ __forceinline__ float sigf(float x) { return 1.f/(1.f + __expf(-x)); }

// ---- f32x2 helpers ----
__device__ __forceinline__ ull ffma2(ull a, ull b, ull c) {
    ull d; asm("fma.rn.f32x2 %0,%1,%2,%3;" : "=l"(d) : "l"(a), "l"(b), "l"(c)); return d;
}
__device__ __forceinline__ ull fmul2(ull a, ull b) {
    ull d; asm("mul.rn.f32x2 %0,%1,%2;" : "=l"(d) : "l"(a), "l"(b)); return d;
}
__device__ __forceinline__ ull dup2(float v) {
    ull d; asm("mov.b64 %0,{%1,%1};" : "=l"(d) : "f"(v)); return d;
}
__device__ __forceinline__ void unpack2(ull p, float& lo, float& hi) {
    asm("mov.b64 {%0,%1},%2;" : "=f"(lo), "=f"(hi) : "l"(p));
}
__device__ __forceinline__ uint32_t smaddr(const void* p) {
    return (uint32_t)__cvta_generic_to_shared(p);
}

// ---------------- kernel: zero ONLY the pad border of g_xTh ----------------
__global__ void k_border() {
    int i = blockIdx.x * blockDim.x + threadIdx.x;
    if (i >= BB*4128) return;
    int b = i / 4128, r = i % 4128;
    uint4* base = reinterpret_cast<uint4*>(g_xTh + (size_t)b*130*130*64);
    uint4 z = make_uint4(0,0,0,0);
    if (r < 1040) {
        base[r] = z;
    } else if (r < 2080) {
        base[129*1040 + (r - 1040)] = z;
    } else if (r < 3104) {
        int rr = r - 2080;
        base[(1 + (rr >> 3))*1040 + (rr & 7)] = z;
    } else {
        int rr = r - 3104;
        base[(1 + (rr >> 3))*1040 + 129*8 + (rr & 7)] = z;
    }
}

// ---------------- kernel: NCHW fp32 -> padded NHWC fp16 (interior) ----------------
__global__ void k_pad(const float* __restrict__ x) {
    __shared__ float sm[64][33];
    int jb = blockIdx.x, i0 = blockIdx.y, b = blockIdx.z;
    int tx = threadIdx.x, ty = threadIdx.y;
    int jcol = jb*32 + tx;
    for (int c = ty; c < 64; c += 8)
        sm[c][tx] = x[((b*CC + c)*HH + i0)*WW + jcol];
    __syncthreads();
    for (int jj = ty; jj < 32; jj += 8) {
        int base = ((b*130 + (i0+1))*130 + (jb*32 + jj + 1))*64;
        g_xTh[base + tx]      = __float2half_rn(sm[tx][jj]);
        g_xTh[base + 32 + tx] = __float2half_rn(sm[32 + tx][jj]);
    }
}

// ====== shared HMMA conv geometry ======
#define PIN 104
#define SIN_ROWS 198
#define SIN_B (SIN_ROWS*PIN*2)
#define WPP 872
#define SO_PITCH 68
#define SO_B (64*SO_PITCH*4)
#define NTILES (BB*HH*2)

// ================= K1: upd + rst + wg + cand_x convs via HMMA =================
#define W1_OC 64
#define K1_SO_OFF (SIN_B + W1_OC*WPP*2)
#define K1_SMEM (K1_SO_OFF + SO_B)

__global__ void __launch_bounds__(256, 1) k1_gates(
    const float* __restrict__ pre,
    const float* __restrict__ uw, const float* __restrict__ ub,
    const float* __restrict__ rw, const float* __restrict__ rb,
    const float* __restrict__ ww, const float* __restrict__ wb,
    const float* __restrict__ ow)
{
    extern __shared__ char shb[];
    __half* sIn = reinterpret_cast<__half*>(shb);
    __half* Wp  = reinterpret_cast<__half*>(shb + SIN_B);
    float*  so  = reinterpret_cast<float*>(shb + K1_SO_OFF);

    int t = threadIdx.x;
    int lane = t & 31, warp = t >> 5;

    for (int i = t; i < SIN_ROWS*PIN/8; i += 256)
        reinterpret_cast<uint4*>(sIn)[i] = make_uint4(0,0,0,0);
    for (int i = t; i < W1_OC*WPP/8; i += 256)
        reinterpret_cast<uint4*>(Wp)[i] = make_uint4(0,0,0,0);
    __syncthreads();
    for (int i = t; i < 18*738; i += 256) {
        int oc = i / 738, r = i % 738, ic = r / 9, pos = r % 9;
        Wp[oc*WPP + pos*96 + ic]        = __float2half_rn(uw[i]);
        Wp[(18 + oc)*WPP + pos*96 + ic] = __float2half_rn(rw[i]);
    }
    for (int i = t; i < 9*576; i += 256) {
        int oc = i / 576, r = i % 576, ic = r / 9, pos = r % 9;
        Wp[(36 + oc)*WPP + pos*96 + ic] = __float2half_rn(ww[i]);
    }
    for (int i = t; i < 18*576; i += 256) {
        int oc = i / 576, r = i % 576, ic = r / 9, pos = r % 9;
        Wp[(45 + oc)*WPP + pos*96 + ic] = __float2half_rn(ow[oc*738 + ic*9 + pos]);
    }
    __syncthreads();

    // staging slot descriptors (tile-invariant)
    int xsrc[7], xdst[7];
    #pragma unroll
    for (int s = 0; s < 7; ++s) {
        int e = t + s*256;
        if (e < 1584) {
            int r = e >> 3, q = e & 7;
            int crow = r / 66, col = r % 66;
            xsrc[s] = (crow*130 + col)*64 + q*8;
            xdst[s] = r*PIN + q*8;
        } else { xsrc[s] = -1; xdst[s] = 0; }
    }
    int pofs[14], pcrow[14], pcol[14], pdst[14];
    #pragma unroll
    for (int s = 0; s < 14; ++s) {
        int e = t + s*256;
        if (e < 3564) {
            int ch = e / 198, r = e % 198;
            int crow = r / 66, col = r % 66;
            pofs[s]  = ch*HWX + crow*WW + col;
            pcrow[s] = crow; pcol[s] = col;
            pdst[s]  = r*PIN + 64 + ch;
        } else { pofs[s] = -1; pcrow[s] = 0; pcol[s] = 0; pdst[s] = 0; }
    }

    // ---- stage first tile directly into smem ----
    {
        int tile = blockIdx.x;
        int b = tile >> 8, rem = tile & 255;
        int h = rem >> 1, w0 = (rem & 1) << 6;
        const __half* xbase = g_xTh + (size_t)(((b*130 + h)*130) + w0)*64;
        #pragma unroll
        for (int s = 0; s < 7; ++s)
            if (xsrc[s] >= 0)
                *reinterpret_cast<uint4*>(sIn + xdst[s]) =
                    *reinterpret_cast<const uint4*>(xbase + xsrc[s]);
        const float* pbase = pre + (size_t)b*MH*HWX + (h-1)*WW + (w0-1);
        #pragma unroll
        for (int s = 0; s < 14; ++s) {
            if (pofs[s] >= 0) {
                int gh = h - 1 + pcrow[s], gw = w0 - 1 + pcol[s];
                float v = 0.f;
                if ((unsigned)gh < HH && (unsigned)gw < WW)
                    v = __ldg(pbase + pofs[s]);
                sIn[pdst[s]] = __float2half_rn(v);
            }
        }
    }
    __syncthreads();

    int wp = warp & 3, wo = warp >> 2;
    int px0 = wp * 16, oc0 = wo * 32;
    uint32_t aBase = smaddr(sIn) + (((px0 + (lane & 15))*PIN) + (lane >> 4)*8)*2;
    uint32_t bBase = smaddr(Wp) + ((oc0 + (lane & 7) + ((lane >> 4) & 1)*8)*WPP)*2
                     + ((lane >> 3) & 1)*16;
    int gid = lane >> 2, tig = lane & 3;

    for (int tile = blockIdx.x; tile < NTILES; tile += gridDim.x) {
        int b = tile >> 8;
        int rem = tile & 255;
        int h  = rem >> 1;
        int w0 = (rem & 1) << 6;

        // ---- issue next tile's staging loads into registers ----
        int nxt = tile + gridDim.x;
        bool hasNext = nxt < NTILES;
        uint4 xpf[7];
        float ppf[14];
        if (hasNext) {
            int b2 = nxt >> 8, rem2 = nxt & 255;
            int h2 = rem2 >> 1, w02 = (rem2 & 1) << 6;
            const __half* xbase2 = g_xTh + (size_t)(((b2*130 + h2)*130) + w02)*64;
            #pragma unroll
            for (int s = 0; s < 7; ++s)
                if (xsrc[s] >= 0)
                    xpf[s] = *reinterpret_cast<const uint4*>(xbase2 + xsrc[s]);
            const float* pbase2 = pre + (size_t)b2*MH*HWX + (h2-1)*WW + (w02-1);
            #pragma unroll
            for (int s = 0; s < 14; ++s) {
                float v = 0.f;
                if (pofs[s] >= 0) {
                    int gh = h2 - 1 + pcrow[s], gw = w02 - 1 + pcol[s];
                    if ((unsigned)gh < HH && (unsigned)gw < WW)
                        v = __ldg(pbase2 + pofs[s]);
                }
                ppf[s] = v;
            }
        }

        float d[4][4];
        #pragma unroll
        for (int i = 0; i < 4; ++i)
            #pragma unroll
            for (int j = 0; j < 4; ++j) d[i][j] = 0.f;

        #pragma unroll 1
        for (int pos = 0; pos < 9; ++pos) {
            int ki = pos / 3, kj = pos % 3;
            uint32_t aPos = aBase + (ki*66 + kj)*PIN*2;
            uint32_t bPos = bBase + pos*96*2;
            #pragma unroll
            for (int kk = 0; kk < 6; ++kk) {
                uint32_t a0,a1,a2,a3, b0,b1,b2,b3, b4,b5,b6,b7;
                asm volatile("ldmatrix.sync.aligned.m8n8.x4.shared.b16 {%0,%1,%2,%3},[%4];"
                    : "=r"(a0),"=r"(a1),"=r"(a2),"=r"(a3) : "r"(aPos + kk*32));
                asm volatile("ldmatrix.sync.aligned.m8n8.x4.shared.b16 {%0,%1,%2,%3},[%4];"
                    : "=r"(b0),"=r"(b1),"=r"(b2),"=r"(b3) : "r"(bPos + kk*32));
                asm volatile("ldmatrix.sync.aligned.m8n8.x4.shared.b16 {%0,%1,%2,%3},[%4];"
                    : "=r"(b4),"=r"(b5),"=r"(b6),"=r"(b7) : "r"(bPos + 16*WPP*2 + kk*32));
                asm volatile("mma.sync.aligned.m16n8k16.row.col.f32.f16.f16.f32 "
                    "{%0,%1,%2,%3},{%4,%5,%6,%7},{%8,%9},{%0,%1,%2,%3};"
                    : "+f"(d[0][0]),"+f"(d[0][1]),"+f"(d[0][2]),"+f"(d[0][3])
                    : "r"(a0),"r"(a1),"r"(a2),"r"(a3),"r"(b0),"r"(b1));
                asm volatile("mma.sync.aligned.m16n8k16.row.col.f32.f16.f16.f32 "
                    "{%0,%1,%2,%3},{%4,%5,%6,%7},{%8,%9},{%0,%1,%2,%3};"
                    : "+f"(d[1][0]),"+f"(d[1][1]),"+f"(d[1][2]),"+f"(d[1][3])
                    : "r"(a0),"r"(a1),"r"(a2),"r"(a3),"r"(b2),"r"(b3));
                asm volatile("mma.sync.aligned.m16n8k16.row.col.f32.f16.f16.f32 "
                    "{%0,%1,%2,%3},{%4,%5,%6,%7},{%8,%9},{%0,%1,%2,%3};"
                    : "+f"(d[2][0]),"+f"(d[2][1]),"+f"(d[2][2]),"+f"(d[2][3])
                    : "r"(a0),"r"(a1),"r"(a2),"r"(a3),"r"(b4),"r"(b5));
                asm volatile("mma.sync.aligned.m16n8k16.row.col.f32.f16.f16.f32 "
                    "{%0,%1,%2,%3},{%4,%5,%6,%7},{%8,%9},{%0,%1,%2,%3};"
                    : "+f"(d[3][0]),"+f"(d[3][1]),"+f"(d[3][2]),"+f"(d[3][3])
                    : "r"(a0),"r"(a1),"r"(a2),"r"(a3),"r"(b6),"r"(b7));
            }
        }

        #pragma unroll
        for (int nt = 0; nt < 4; ++nt) {
            int oc = oc0 + nt*8 + tig*2;
            int pr = px0 + gid;
            so[pr*SO_PITCH + oc]         = d[nt][0];
            so[pr*SO_PITCH + oc + 1]     = d[nt][1];
            so[(pr+8)*SO_PITCH + oc]     = d[nt][2];
            so[(pr+8)*SO_PITCH + oc + 1] = d[nt][3];
        }
        __syncthreads();   // GEMM's sIn reads done; so writes visible

        // ---- commit prefetched staging into sIn (overlaps epilogue) ----
        if (hasNext) {
            #pragma unroll
            for (int s = 0; s < 7; ++s)
                if (xsrc[s] >= 0)
                    *reinterpret_cast<uint4*>(sIn + xdst[s]) = xpf[s];
            #pragma unroll
            for (int s = 0; s < 14; ++s)
                if (pofs[s] >= 0)
                    sIn[pdst[s]] = __float2half_rn(ppf[s]);
        }

        for (int i = t; i < 63*64; i += 256) {
            int oc = i >> 6, px = i & 63;
            float a = so[px*SO_PITCH + oc];
            if (oc < 18) {
                g_update[((b*MH + oc)*HH + h)*WW + w0 + px] = sigf(a + ub[oc]);
            } else if (oc < 36) {
                int o = oc - 18;
                int idx = ((b*MH + o)*HH + h)*WW + w0 + px;
                g_rgoff[idx] = pre[idx] * sigf(a + rb[o]);
            } else if (oc < 45) {
                int o = oc - 36;
                g_m[((b*NN + o)*HH + h)*WW + w0 + px] = sigf(a + wb[o]);
            } else {
                int o = oc - 45;
                g_candx[((b*MH + o)*HH + h)*WW + w0 + px] = a;
            }
        }
        __syncthreads();
    }
}

// ================= K2: cand_p conv (K=18->32) + GRU combine =================
#define PIN2 40
#define SIN2_B (SIN_ROWS*PIN2*2)
#define WPP2 296
#define W2_OC 32
#define K2_SO_OFF (SIN2_B + W2_OC*WPP2*2)
#define K2_SMEM (K2_SO_OFF + SO_B)

__global__ void __launch_bounds__(256, 2) k2_cand(
    const float* __restrict__ pre, const float* __restrict__ mean,
    const float* __restrict__ ow, const float* __restrict__ ob,
    float* __restrict__ out_off, float* __restrict__ out_mean)
{
    extern __shared__ char shb[];
    __half* sIn = reinterpret_cast<__half*>(shb);
    __half* Wp  = reinterpret_cast<__half*>(shb + SIN2_B);
    float*  so  = reinterpret_cast<float*>(shb + K2_SO_OFF);

    int t = threadIdx.x;
    int lane = t & 31, warp = t >> 5;

    for (int i = t; i < SIN_ROWS*PIN2/8; i += 256)
        reinterpret_cast<uint4*>(sIn)[i] = make_uint4(0,0,0,0);
    for (int i = t; i < W2_OC*WPP2/8; i += 256)
        reinterpret_cast<uint4*>(Wp)[i] = make_uint4(0,0,0,0);
    __syncthreads();
    for (int i = t; i < 18*162; i += 256) {
        int oc = i / 162, r = i % 162, icp = r / 9, pos = r % 9;
        Wp[oc*WPP2 + pos*32 + icp] = __float2half_rn(ow[oc*738 + (64 + icp)*9 + pos]);
    }
    __syncthreads();

    int pofs[14], pcrow[14], pcol[14], pdst[14];
    #pragma unroll
    for (int s = 0; s < 14; ++s) {
        int e = t + s*256;
        if (e < 3564) {
            int ch = e / 198, r = e % 198;
            int crow = r / 66, col = r % 66;
            pofs[s]  = ch*HWX + crow*WW + col;
            pcrow[s] = crow; pcol[s] = col;
            pdst[s]  = r*PIN2 + ch;
        } else { pofs[s] = -1; pcrow[s] = 0; pcol[s] = 0; pdst[s] = 0; }
    }

    // stage first tile
    {
        int tile = blockIdx.x;
        if (tile < NTILES) {
            int b = tile >> 8, rem = tile & 255;
            int h = rem >> 1, w0 = (rem & 1) << 6;
            const float* pbase = g_rgoff + (size_t)b*MH*HWX + (h-1)*WW + (w0-1);
            #pragma unroll
            for (int s = 0; s < 14; ++s) {
                if (pofs[s] >= 0) {
                    int gh = h - 1 + pcrow[s], gw = w0 - 1 + pcol[s];
                    float v = 0.f;
                    if ((unsigned)gh < HH && (unsigned)gw < WW)
                        v = __ldg(pbase + pofs[s]);
                    sIn[pdst[s]] = __float2half_rn(v);
                }
            }
        }
    }
    __syncthreads();

    int wp = warp & 3, wo = warp >> 2;
    int px0 = wp * 16, oc0 = wo * 16;
    uint32_t aBase = smaddr(sIn) + (((px0 + (lane & 15))*PIN2) + (lane >> 4)*8)*2;
    uint32_t bBase = smaddr(Wp) + ((oc0 + (lane & 7) + ((lane >> 4) & 1)*8)*WPP2)*2
                     + ((lane >> 3) & 1)*16;
    int gid = lane >> 2, tig = lane & 3;

    for (int tile = blockIdx.x; tile < NTILES; tile += gridDim.x) {
        int b = tile >> 8;
        int rem = tile & 255;
        int h  = rem >> 1;
        int w0 = (rem & 1) << 6;

        int nxt = tile + gridDim.x;
        bool hasNext = nxt < NTILES;
        float ppf[14];
        if (hasNext) {
            int b2 = nxt >> 8, rem2 = nxt & 255;
            int h2 = rem2 >> 1, w02 = (rem2 & 1) << 6;
            const float* pbase2 = g_rgoff + (size_t)b2*MH*HWX + (h2-1)*WW + (w02-1);
            #pragma unroll
            for (int s = 0; s < 14; ++s) {
                float v = 0.f;
                if (pofs[s] >= 0) {
                    int gh = h2 - 1 + pcrow[s], gw = w02 - 1 + pcol[s];
                    if ((unsigned)gh < HH && (unsigned)gw < WW)
                        v = __ldg(pbase2 + pofs[s]);
                }
                ppf[s] = v;
            }
        }

        float d[2][4];
        #pragma unroll
        for (int i = 0; i < 2; ++i)
            #pragma unroll
            for (int j = 0; j < 4; ++j) d[i][j] = 0.f;

        #pragma unroll 1
        for (int pos = 0; pos < 9; ++pos) {
            int ki = pos / 3, kj = pos % 3;
            uint32_t aPos = aBase + (ki*66 + kj)*PIN2*2;
            uint32_t bPos = bBase + pos*32*2;
            #pragma unroll
            for (int kk = 0; kk < 2; ++kk) {
                uint32_t a0,a1,a2,a3, b0,b1,b2,b3;
                asm volatile("ldmatrix.sync.aligned.m8n8.x4.shared.b16 {%0,%1,%2,%3},[%4];"
                    : "=r"(a0),"=r"(a1),"=r"(a2),"=r"(a3) : "r"(aPos + kk*32));
                asm volatile("ldmatrix.sync.aligned.m8n8.x4.shared.b16 {%0,%1,%2,%3},[%4];"
                    : "=r"(b0),"=r"(b1),"=r"(b2),"=r"(b3) : "r"(bPos + kk*32));
                asm volatile("mma.sync.aligned.m16n8k16.row.col.f32.f16.f16.f32 "
                    "{%0,%1,%2,%3},{%4,%5,%6,%7},{%8,%9},{%0,%1,%2,%3};"
                    : "+f"(d[0][0]),"+f"(d[0][1]),"+f"(d[0][2]),"+f"(d[0][3])
                    : "r"(a0),"r"(a1),"r"(a2),"r"(a3),"r"(b0),"r"(b1));
                asm volatile("mma.sync.aligned.m16n8k16.row.col.f32.f16.f16.f32 "
                    "{%0,%1,%2,%3},{%4,%5,%6,%7},{%8,%9},{%0,%1,%2,%3};"
                    : "+f"(d[1][0]),"+f"(d[1][1]),"+f"(d[1][2]),"+f"(d[1][3])
                    : "r"(a0),"r"(a1),"r"(a2),"r"(a3),"r"(b2),"r"(b3));
            }
        }

        #pragma unroll
        for (int nt = 0; nt < 2; ++nt) {
            int oc = oc0 + nt*8 + tig*2;
            int pr = px0 + gid;
            so[pr*SO_PITCH + oc]         = d[nt][0];
            so[pr*SO_PITCH + oc + 1]     = d[nt][1];
            so[(pr+8)*SO_PITCH + oc]     = d[nt][2];
            so[(pr+8)*SO_PITCH + oc + 1] = d[nt][3];
        }
        __syncthreads();

        if (hasNext) {
            #pragma unroll
            for (int s = 0; s < 14; ++s)
                if (pofs[s] >= 0)
                    sIn[pdst[s]] = __float2half_rn(ppf[s]);
        }

        for (int i = t; i < 18*64; i += 256) {
            int oc = i >> 6, px = i & 63;
            int idx = ((b*MH + oc)*HH + h)*WW + w0 + px;
            float cv = tanhf(so[px*SO_PITCH + oc] + g_candx[idx] + ob[oc]);
            float u  = g_update[idx];
            float p  = pre[idx];
            float mn = 0.5f*(mean[idx] + p);
            out_off[idx]  = p*(1.f - u) + cv*u + mn;
            out_mean[idx] = mn;
        }
        __syncthreads();
    }
}

// ================= k_warp: deformable warp + regroup conv via HMMA =================
#define KP 584
#define W_SW_OFF 0
#define W_SV_OFF (64*KP*2)
#define W_WT_OFF (W_SV_OFF + 64*KP*2)
#define W_AD_OFF (W_WT_OFF + 576*16)
#define W_SMEMB (W_AD_OFF + 576*16)

__global__ void __launch_bounds__(256, 1) k_warp(
    const float* __restrict__ off, const float* __restrict__ Wc,
    float* __restrict__ out)
{
    extern __shared__ char shb[];
    __half* sW  = reinterpret_cast<__half*>(shb + W_SW_OFF);
    __half* sv  = reinterpret_cast<__half*>(shb + W_SV_OFF);
    float4* wts = reinterpret_cast<float4*>(shb + W_WT_OFF);
    int4*   ads = reinterpret_cast<int4*>(shb + W_AD_OFF);
    float*  so  = reinterpret_cast<float*>(shb + W_WT_OFF);

    int t = threadIdx.x;
    int lane = t & 31, warp = t >> 5;

    for (int i = t; i < 64*576; i += 256) {
        int co = i / 576, r = i % 576;
        int ci = r / 9, n = r % 9;
        sW[co*KP + n*64 + ci] = __float2half_rn(Wc[i]);
    }
    __syncthreads();

    int gid = lane >> 2, tig = lane & 3;
    int px0 = (warp >> 1) * 16;
    int co0 = (warp & 1) * 32;
    uint32_t aAddr = smaddr(sv) + (((px0 + (lane & 15))*KP + (lane >> 4)*8) << 1);
    uint32_t bAddr0 = smaddr(sW) + (((co0 + (lane & 7) + (lane >> 4)*8)*KP
                                    + ((lane >> 3) & 1)*8) << 1);
    uint32_t bAddr1 = bAddr0 + 16*KP*2;

    int g = lane >> 3;
    int c = lane & 7;

    for (int tile = blockIdx.x; tile < NTILES; tile += gridDim.x) {
        int b = tile >> 8;
        int rem = tile & 255;
        int h  = rem >> 1;
        int w0 = (rem & 1) << 6;
        const __half* xh = g_xTh + (size_t)b*130*130*64;

        for (int item = t; item < 576; item += 256) {
            int n = item >> 6, px = item & 63;
            int wc = w0 + px;
            float pnx = (float)(n/3 - 1), pny = (float)(n%3 - 1);
            float ox = __ldg(off + ((b*MH + n    )*HH + h)*WW + wc);
            float oy = __ldg(off + ((b*MH + 9 + n)*HH + h)*WW + wc);
            float mm = g_m[((b*NN + n)*HH + h)*WW + wc];
            float px_ = (float)(h + 1) + pnx + ox;
            float py_ = (float)(wc + 1) + pny + oy;
            float fx = floorf(px_), fy = floorf(py_);
            float qxl = fminf(fmaxf(fx,       0.f), 129.f);
            float qxr = fminf(fmaxf(fx + 1.f, 0.f), 129.f);
            float qyl = fminf(fmaxf(fy,       0.f), 129.f);
            float qyr = fminf(fmaxf(fy + 1.f, 0.f), 129.f);
            float pxc = fminf(fmaxf(px_, 0.f), 129.f);
            float pyc = fminf(fmaxf(py_, 0.f), 129.f);
            float gx_l = 1.f + (qxl - pxc);
            float gx_r = 1.f - (qxr - pxc);
            float gy_l = 1.f + (qyl - pyc);
            float gy_r = 1.f - (qyr - pyc);
            int ixl = (int)qxl, ixr = (int)qxr, iyl = (int)qyl, iyr = (int)qyr;
            wts[item] = make_float4(gx_l*gy_l*mm, gx_r*gy_r*mm,
                                    gx_l*gy_r*mm, gx_r*gy_l*mm);
            ads[item] = make_int4(ixl*130 + iyl, ixr*130 + iyr,
                                  ixl*130 + iyr, ixr*130 + iyl);
        }
        __syncthreads();

        #pragma unroll 2
        for (int p = 0; p < 18; ++p) {
            int item = p*32 + warp*4 + g;
            int n = item >> 6, px = item & 63;
            float4 wt = wts[item];
            int4   ad = ads[item];
            uint4 rLT = *reinterpret_cast<const uint4*>(xh + ad.x*64 + c*8);
            uint4 rRB = *reinterpret_cast<const uint4*>(xh + ad.y*64 + c*8);
            uint4 rLB = *reinterpret_cast<const uint4*>(xh + ad.z*64 + c*8);
            uint4 rRT = *reinterpret_cast<const uint4*>(xh + ad.w*64 + c*8);
            ull dLT = dup2(wt.x), dRB = dup2(wt.y), dLB = dup2(wt.z), dRT = dup2(wt.w);
            uint32_t outh[4];
            const uint32_t* hLT = &rLT.x;
            const uint32_t* hRB = &rRB.x;
            const uint32_t* hLB = &rLB.x;
            const uint32_t* hRT = &rRT.x;
            #pragma unroll
            for (int q = 0; q < 4; ++q) {
                float2 fLT = __half22float2(*reinterpret_cast<const __half2*>(hLT + q));
                float2 fRB = __half22float2(*reinterpret_cast<const __half2*>(hRB + q));
                float2 fLB = __half22float2(*reinterpret_cast<const __half2*>(hLB + q));
                float2 fRT = __half22float2(*reinterpret_cast<const __half2*>(hRT + q));
                ull v;
                asm("mov.b64 %0,{%1,%2};" : "=l"(v) : "f"(fLT.x), "f"(fLT.y));
                v = fmul2(dLT, v);
                ull u2;
                asm("mov.b64 %0,{%1,%2};" : "=l"(u2) : "f"(fRB.x), "f"(fRB.y));
                v = ffma2(dRB, u2, v);
                asm("mov.b64 %0,{%1,%2};" : "=l"(u2) : "f"(fLB.x), "f"(fLB.y));
                v = ffma2(dLB, u2, v);
                asm("mov.b64 %0,{%1,%2};" : "=l"(u2) : "f"(fRT.x), "f"(fRT.y));
                v = ffma2(dRT, u2, v);
                float lo, hi;
                unpack2(v, lo, hi);
                __half2 hh = __floats2half2_rn(lo, hi);
                outh[q] = *reinterpret_cast<uint32_t*>(&hh);
            }
            *reinterpret_cast<uint4*>(sv + px*KP + n*64 + c*8) =
                make_uint4(outh[0], outh[1], outh[2], outh[3]);
        }
        __syncthreads();

        float d[4][4];
        #pragma unroll
        for (int i = 0; i < 4; ++i)
            #pragma unroll
            for (int j = 0; j < 4; ++j) d[i][j] = 0.f;

        #pragma unroll 4
        for (int ks = 0; ks < 36; ++ks) {
            uint32_t a0, a1, a2, a3, b0, b1, b2, b3, b4, b5, b6, b7;
            asm volatile("ldmatrix.sync.aligned.m8n8.x4.shared.b16 {%0,%1,%2,%3},[%4];"
                : "=r"(a0), "=r"(a1), "=r"(a2), "=r"(a3) : "r"(aAddr + ks*32));
            asm volatile("ldmatrix.sync.aligned.m8n8.x4.shared.b16 {%0,%1,%2,%3},[%4];"
                : "=r"(b0), "=r"(b1), "=r"(b2), "=r"(b3) : "r"(bAddr0 + ks*32));
            asm volatile("ldmatrix.sync.aligned.m8n8.x4.shared.b16 {%0,%1,%2,%3},[%4];"
                : "=r"(b4), "=r"(b5), "=r"(b6), "=r"(b7) : "r"(bAddr1 + ks*32));
            asm volatile("mma.sync.aligned.m16n8k16.row.col.f32.f16.f16.f32 "
                "{%0,%1,%2,%3},{%4,%5,%6,%7},{%8,%9},{%0,%1,%2,%3};"
                : "+f"(d[0][0]), "+f"(d[0][1]), "+f"(d[0][2]), "+f"(d[0][3])
                : "r"(a0), "r"(a1), "r"(a2), "r"(a3), "r"(b0), "r"(b1));
            asm volatile("mma.sync.aligned.m16n8k16.row.col.f32.f16.f16.f32 "
                "{%0,%1,%2,%3},{%4,%5,%6,%7},{%8,%9},{%0,%1,%2,%3};"
                : "+f"(d[1][0]), "+f"(d[1][1]), "+f"(d[1][2]), "+f"(d[1][3])
                : "r"(a0), "r"(a1), "r"(a2), "r"(a3), "r"(b2), "r"(b3));
            asm volatile("mma.sync.aligned.m16n8k16.row.col.f32.f16.f16.f32 "
                "{%0,%1,%2,%3},{%4,%5,%6,%7},{%8,%9},{%0,%1,%2,%3};"
                : "+f"(d[2][0]), "+f"(d[2][1]), "+f"(d[2][2]), "+f"(d[2][3])
                : "r"(a0), "r"(a1), "r"(a2), "r"(a3), "r"(b4), "r"(b5));
            asm volatile("mma.sync.aligned.m16n8k16.row.col.f32.f16.f16.f32 "
                "{%0,%1,%2,%3},{%4,%5,%6,%7},{%8,%9},{%0,%1,%2,%3};"
                : "+f"(d[3][0]), "+f"(d[3][1]), "+f"(d[3][2]), "+f"(d[3][3])
                : "r"(a0), "r"(a1), "r"(a2), "r"(a3), "r"(b6), "r"(b7));
        }
        __syncthreads();

        #pragma unroll
        for (int nt = 0; nt < 4; ++nt) {
            int cb = co0 + nt*8 + tig*2;
            int pr = px0 + gid;
            so[pr*69 + cb]         = d[nt][0];
            so[pr*69 + cb + 1]     = d[nt][1];
            so[(pr+8)*69 + cb]     = d[nt][2];
            so[(pr+8)*69 + cb + 1] = d[nt][3];
        }
        __syncthreads();

        for (int i = t; i < 4096; i += 256) {
            int co = i >> 6, px = i & 63;
            out[((b*CC + co)*HH + h)*WW + w0 + px] = so[px*69 + co];
        }
        __syncthreads();
    }
}

// ---------------- launch ----------------
extern "C" void kernel_launch(void* const* d_in, const int* in_sizes, int n_in,
                              void* d_out, int out_size)
{
    const float* x    = (const float*)d_in[0];
    const float* pre  = (const float*)d_in[1];
    const float* mean = (const float*)d_in[2];
    const float* uw   = (const float*)d_in[3];
    const float* ub   = (const float*)d_in[4];
    const float* rw   = (const float*)d_in[5];
    const float* rb   = (const float*)d_in[6];
    const float* ow   = (const float*)d_in[7];
    const float* ob   = (const float*)d_in[8];
    const float* ww   = (const float*)d_in[9];
    const float* wb   = (const float*)d_in[10];
    const float* wc   = (const float*)d_in[11];

    float* out_x    = (float*)d_out;
    float* out_off  = out_x + BB*CC*HH*WW;
    float* out_mean = out_off + BB*MH*HH*WW;

    cudaFuncSetAttribute(k1_gates, cudaFuncAttributeMaxDynamicSharedMemorySize, K1_SMEM);
    cudaFuncSetAttribute(k2_cand,  cudaFuncAttributeMaxDynamicSharedMemorySize, K2_SMEM);
    cudaFuncSetAttribute(k_warp,   cudaFuncAttributeMaxDynamicSharedMemorySize, W_SMEMB);

    k_border<<<(BB*4128 + 255)/256, 256>>>();
    k_pad<<<dim3(4, 128, 4), dim3(32, 8)>>>(x);

    k1_gates<<<148, 256, K1_SMEM>>>(pre, uw, ub, rw, rb, ww, wb, ow);
    k2_cand <<<296, 256, K2_SMEM>>>(pre, mean, ow, ob, out_off, out_mean);
    k_warp  <<<148, 256, W_SMEMB>>>(out_off, wc, out_x);
}